// round 11
// baseline (speedup 1.0000x reference)
#include <cuda_runtime.h>
#include <cuda_fp16.h>
#include <math.h>
#include <stdint.h>

#define BSZ   8
#define SEQ   4096
#define NTOK  3000
#define DIN   128
#define DM    512
#define DFF   2048
#define DOUT  64
#define DH    128
#define MTOT  (BSZ*SEQ)
#define MTPB  24                     // M-tiles per batch: ceil(3000/128)
#define SCALE 0.08838834764831845f   // 1/sqrt(128)
#define GEMM_SMEM (3*32768)          // 3 stages x (2 subchunks x 2 arrays x 8KB)
#define LA_SMEM   57344              // tile 32KB + qs 16KB + scores 8KB + pad

typedef __half fp16;

// ---------------- scratch (static device globals: no allocation) -------------
__device__ float g_h[MTOT*DM];
__device__ float g_q[MTOT*DM];
__device__ float g_k[MTOT*DM];
__device__ float g_v[MTOT*DM];
__device__ float g_kmax[BSZ*3*DH];
__device__ float g_lsep[BSZ*3*8*DH];
__device__ float g_ctxp[BSZ*3*8*DH*DH];
__device__ float g_ctx[BSZ*3*DH*DH];
__device__ float g_lnpad[DM];
__device__ float g_kpad[DM];
__device__ float g_vpad[DM];
// fp16 activation buffers
__device__ fp16 g_sh[MTOT*DM];
__device__ fp16 g_s2h[MTOT*DFF];
// transposed weights [N][K], fp16
__device__ fp16 g_w1h[DM*DIN];
__device__ fp16 g_wqkv[3*DM*DM];     // rows 0-511: Wq^T, 512-1023: Wk^T, 1024-1535: Wv^T
__device__ fp16 g_woh[DM*DM];
__device__ fp16 g_wf1h[DFF*DM];
__device__ fp16 g_wf2h[DM*DFF];
__device__ fp16 g_w2h[DOUT*DM];

// ---------------- helpers ----------------
__device__ __forceinline__ uint32_t smem_u32(const void* p) {
    uint32_t a;
    asm("{ .reg .u64 t; cvta.to.shared.u64 t, %1; cvt.u32.u64 %0, t; }" : "=r"(a) : "l"(p));
    return a;
}
__device__ __forceinline__ uint32_t pack2h(float x, float y) {
    __half2 h = __floats2half2_rn(x, y);
    return *reinterpret_cast<uint32_t*>(&h);
}
// fast exp for x <= 0 on the FMA pipe (no MUFU). rel err ~1e-7.
__device__ __forceinline__ float fexp(float x) {
    x = fmaxf(x, -87.0f);
    float t = x * 1.4426950408889634f;      // log2(e)
    float fn = rintf(t);
    float r = t - fn;                       // r in [-0.5, 0.5]
    float p =            1.5403530394e-4f;  // 2^r Taylor (ln2^k / k!)
    p = fmaf(p, r, 1.3333558146e-3f);
    p = fmaf(p, r, 9.6181291076e-3f);
    p = fmaf(p, r, 5.5504108665e-2f);
    p = fmaf(p, r, 2.4022650696e-1f);
    p = fmaf(p, r, 6.9314718056e-1f);
    p = fmaf(p, r, 1.0f);
    return __int_as_float(__float_as_int(p) + (((int)fn) << 23));
}
#define EXPF(x) fexp(x)

#define LDSM_X4(r0,r1,r2,r3,addr) \
    asm volatile("ldmatrix.sync.aligned.m8n8.x4.shared.b16 {%0,%1,%2,%3}, [%4];" \
        : "=r"(r0),"=r"(r1),"=r"(r2),"=r"(r3) : "r"(addr))
#define MMA16816(d, a0,a1,a2,a3, b0,b1) \
    asm volatile("mma.sync.aligned.m16n8k16.row.col.f32.f16.f16.f32 " \
        "{%0,%1,%2,%3},{%4,%5,%6,%7},{%8,%9},{%0,%1,%2,%3};" \
        : "+f"((d)[0]),"+f"((d)[1]),"+f"((d)[2]),"+f"((d)[3]) \
        : "r"(a0),"r"(a1),"r"(a2),"r"(a3),"r"(b0),"r"(b1))
#define CP_ASYNC16(dst, src, sz) \
    asm volatile("cp.async.cg.shared.global [%0], [%1], 16, %2;" :: "r"(dst), "l"(src), "r"(sz))
#define CP_COMMIT()  asm volatile("cp.async.commit_group;" ::: "memory")
#define CP_WAIT0()   asm volatile("cp.async.wait_group 0;" ::: "memory")
#define CP_WAIT1()   asm volatile("cp.async.wait_group 1;" ::: "memory")

// ---------------- weight transpose + fp16: T[n][k] = h(W[k][n]) --------------
__global__ void transpose_h_kernel(const float* __restrict__ W,
                                   fp16* __restrict__ Th, int K, int N) {
    __shared__ float t[32][33];
    int bx = blockIdx.x * 32, by = blockIdx.y * 32;
    int x = bx + threadIdx.x;
    #pragma unroll
    for (int i = 0; i < 32; i += 8) {
        int y = by + threadIdx.y + i;
        if (x < N && y < K) t[threadIdx.y + i][threadIdx.x] = W[(size_t)y * N + x];
    }
    __syncthreads();
    int xk = by + threadIdx.x;
    #pragma unroll
    for (int i = 0; i < 32; i += 8) {
        int yn = bx + threadIdx.y + i;
        if (xk < K && yn < N)
            Th[(size_t)yn * K + xk] = __float2half_rn(t[threadIdx.x][threadIdx.y + i]);
    }
}

// ---------------- x (real rows only) -> g_sh fp16 ----------------------------
__global__ void pad_split_kernel(const float* __restrict__ x) {
    int idx = blockIdx.x*256 + threadIdx.x;
    const int total = BSZ*NTOK*(DIN/4);
    if (idx >= total) return;
    int rr = idx >> 5;
    int c4 = idx & 31;
    int b = rr / NTOK, t = rr - b*NTOK;
    float4 val = reinterpret_cast<const float4*>(x)[(size_t)rr*32 + c4];
    uint2 hv;
    hv.x = pack2h(val.x, val.y);
    hv.y = pack2h(val.z, val.w);
    *reinterpret_cast<uint2*>(g_sh + (size_t)(b*SEQ + t)*DIN + c4*4) = hv;
}

// ---------------- pad-row LN: lnpad = LN(tanh(b1)) ---------------------------
__global__ void pad_ln_kernel(const float* __restrict__ b1, const float* __restrict__ gam,
                              const float* __restrict__ bet) {
    __shared__ float ss[16], ss2[16], stat[2];
    int t = threadIdx.x;
    float h = tanhf(b1[t]);
    float s = h, s2 = h*h;
    #pragma unroll
    for (int o=16;o;o>>=1) { s += __shfl_xor_sync(~0u,s,o); s2 += __shfl_xor_sync(~0u,s2,o); }
    if ((t & 31) == 0) { ss[t>>5] = s; ss2[t>>5] = s2; }
    __syncthreads();
    if (t == 0) {
        float S=0.f, S2=0.f;
        #pragma unroll
        for (int i=0;i<16;i++) { S += ss[i]; S2 += ss2[i]; }
        float mu = S*(1.f/512.f);
        float var = S2*(1.f/512.f) - mu*mu;
        stat[0] = mu; stat[1] = rsqrtf(var + 1e-5f);
    }
    __syncthreads();
    g_lnpad[t] = (h - stat[0])*stat[1]*gam[t] + bet[t];
}

// ---------------- pad-row k/v ------------------------------------------------
__global__ void pad_kv_kernel(const float* __restrict__ Wk, const float* __restrict__ Wv) {
    int d = blockIdx.x*256 + threadIdx.x;
    if (d >= 2*DM) return;
    const float* W = (d < DM) ? Wk : Wv;
    int dd = d & (DM-1);
    float s = 0.f;
    for (int kk = 0; kk < DM; kk++) s += g_lnpad[kk] * W[(size_t)kk*DM + dd];
    if (d < DM) g_kpad[dd] = s; else g_vpad[dd] = s;
}

// ---------------- broadcast pad k/v rows -------------------------------------
__global__ void padfill_kernel() {
    int idx = blockIdx.x*256 + threadIdx.x;
    const int per = (SEQ-NTOK)*(DM/4);
    if (idx >= BSZ*per) return;
    int b = idx / per, r = idx - b*per;
    int t = NTOK + r/(DM/4), c4 = r % (DM/4);
    size_t off = (size_t)(b*SEQ + t)*DM + c4*4;
    *reinterpret_cast<float4*>(g_k + off) = *reinterpret_cast<const float4*>(g_kpad + c4*4);
    *reinterpret_cast<float4*>(g_v + off) = *reinterpret_cast<const float4*>(g_vpad + c4*4);
}

// ---------------- fp16 tensor-core GEMM, K-chunk 64 (real rows) --------------
// If Ck != null: fused QKV routing — cols [0,512)->C, [512,1024)->Ck, [1024,1536)->Cv,
// all with row stride 512.
__global__ __launch_bounds__(256, 2) void tc_gemm_kernel(
    const fp16* __restrict__ A, const fp16* __restrict__ B,
    const float* __restrict__ bias, const float* __restrict__ res,
    float* __restrict__ C, float* __restrict__ Ck, float* __restrict__ Cv,
    fp16* __restrict__ Ch,
    int N, int K, int act, int omul)
{
    extern __shared__ __align__(1024) char smc[];
    uint32_t sbase = smem_u32(smc);
    int tid = threadIdx.x;
    int mtile = blockIdx.y;
    int bb = mtile / MTPB, t0 = (mtile - bb*MTPB) << 7;
    int bm = bb*SEQ + t0;
    int alim = NTOK - t0;
    int rowlim = bm + alim;
    int odelta = bb*(omul - SEQ);
    int bn = blockIdx.x << 7;
    int lane = tid & 31, w = tid >> 5;
    int wm = w & 1, wn = w >> 1;
    int grp = lane >> 2, qp = lane & 3;

    uint32_t swz = (lane >> 1) & 3;
    uint32_t a_base = (uint32_t)(wm*64 + (lane & 15))*64 + (((uint32_t)(lane >> 4) ^ swz) << 4);
    uint32_t b_base = (uint32_t)(wn*32 + ((lane >> 4) & 1)*8 + (lane & 7))*64
                    + ((((uint32_t)(lane >> 3) & 1) ^ swz) << 4);

    float acc[4][4][4];
    #pragma unroll
    for (int i=0;i<4;i++)
        #pragma unroll
        for (int j=0;j<4;j++)
            #pragma unroll
            for (int r=0;r<4;r++) acc[i][j][r] = 0.f;

    const int NC = K >> 6;   // 64-wide K chunks

    #define STAGE_LOAD(c_, buf_) do { \
        uint32_t sb = sbase + (uint32_t)(buf_)*32768u; \
        _Pragma("unroll") \
        for (int i_ = 0; i_ < 8; i_++) { \
            const int sub_ = i_ >> 2; \
            const int arr_ = (i_ >> 1) & 1; \
            int j_ = ((i_ & 1) << 8) + tid; \
            int r_ = j_ >> 2, cc_ = j_ & 3; \
            int k0 = ((c_) << 6) + sub_*32; \
            uint32_t dst_ = sb + (uint32_t)sub_*16384u + (uint32_t)arr_*8192u \
                          + (uint32_t)r_*64u + ((uint32_t)(cc_ ^ ((r_ >> 1) & 3)) << 4); \
            const fp16* g_; int sz_ = 16; \
            if (arr_ == 0) { \
                if (r_ < alim) g_ = A + (size_t)(bm + r_)*K + k0 + cc_*8; \
                else { g_ = A; sz_ = 0; } \
            } else { \
                int rowv_ = bn + r_; \
                if (rowv_ < N) g_ = B + (size_t)rowv_*K + k0 + cc_*8; \
                else { g_ = B; sz_ = 0; } \
            } \
            CP_ASYNC16(dst_, g_, sz_); \
        } \
        CP_COMMIT(); \
    } while (0)

    STAGE_LOAD(0, 0);
    if (NC > 1) STAGE_LOAD(1, 1);

    int buf = 0, bufn = 2;
    for (int c = 0; c < NC; c++) {
        if (c + 1 < NC) CP_WAIT1(); else CP_WAIT0();
        __syncthreads();
        if (c + 2 < NC) {
            STAGE_LOAD(c + 2, bufn);
            bufn = (bufn == 2) ? 0 : bufn + 1;
        }
        uint32_t stg = sbase + (uint32_t)buf*32768u;
        buf = (buf == 2) ? 0 : buf + 1;

        #pragma unroll
        for (int sub = 0; sub < 2; sub++) {
            uint32_t sA = stg + (uint32_t)sub*16384u;
            uint32_t sB = sA + 8192u;
            #pragma unroll
            for (int ks = 0; ks < 2; ks++) {
                uint32_t kx = ks ? 32u : 0u;
                uint32_t bh[4][2], a[4][4];
                #pragma unroll
                for (int p = 0; p < 2; p++)
                    LDSM_X4(bh[2*p][0], bh[2*p][1], bh[2*p+1][0], bh[2*p+1][1],
                            sB + ((b_base + p*1024u) ^ kx));
                #pragma unroll
                for (int mt = 0; mt < 4; mt++)
                    LDSM_X4(a[mt][0], a[mt][1], a[mt][2], a[mt][3],
                            sA + ((a_base + mt*1024u) ^ kx));
                #pragma unroll
                for (int mt = 0; mt < 4; mt++)
                    #pragma unroll
                    for (int nt = 0; nt < 4; nt++)
                        MMA16816(acc[mt][nt], a[mt][0],a[mt][1],a[mt][2],a[mt][3],
                                 bh[nt][0],bh[nt][1]);
            }
        }
    }
    #undef STAGE_LOAD

    // ---- epilogue (valid rows only) ----
    #pragma unroll
    for (int mt = 0; mt < 4; mt++) {
        #pragma unroll
        for (int nt = 0; nt < 4; nt++) {
            int c0 = bn + wn*32 + nt*8 + qp*2;
            if (c0 >= N) continue;
            int rbase = bm + wm*64 + mt*16 + grp;
            float bs0 = 0.f, bs1 = 0.f;
            if (bias) { bs0 = bias[c0]; bs1 = bias[c0 + 1]; }
            #pragma unroll
            for (int half = 0; half < 2; half++) {
                int r = rbase + half*8;
                if (r >= rowlim) continue;
                float v0 = acc[mt][nt][half*2 + 0] + bs0;
                float v1 = acc[mt][nt][half*2 + 1] + bs1;
                if (act == 1) { v0 = tanhf(v0); v1 = tanhf(v1); }
                else if (act == 2) {
                    v0 = 0.5f*v0*(1.f + erff(v0*0.7071067811865476f));
                    v1 = 0.5f*v1*(1.f + erff(v1*0.7071067811865476f));
                }
                if (res) {
                    v0 += res[(size_t)r*N + c0];
                    v1 += res[(size_t)r*N + c0 + 1];
                }
                size_t orow = (size_t)(r + odelta);
                if (Ck) {
                    float* dst; int cc;
                    if (c0 < 512)       { dst = C;  cc = c0; }
                    else if (c0 < 1024) { dst = Ck; cc = c0 - 512; }
                    else                { dst = Cv; cc = c0 - 1024; }
                    float2 o; o.x = v0; o.y = v1;
                    *reinterpret_cast<float2*>(dst + orow*512 + cc) = o;
                } else if (Ch) {
                    *reinterpret_cast<uint32_t*>(Ch + orow*N + c0) = pack2h(v0, v1);
                } else {
                    float2 o; o.x = v0; o.y = v1;
                    *reinterpret_cast<float2*>(C + orow*N + c0) = o;
                }
            }
        }
    }
}

// ---------------- LayerNorm (real rows) -> fp16 ------------------------------
__global__ void ln_kernel(const float* __restrict__ in, const float* __restrict__ gam,
                          const float* __restrict__ bet) {
    int gw = (blockIdx.x*blockDim.x + threadIdx.x) >> 5;
    int lane = threadIdx.x & 31;
    if (gw >= BSZ*NTOK) return;
    int b = gw / NTOK, t = gw - b*NTOK;
    size_t row = (size_t)(b*SEQ + t);
    const float4* rp = reinterpret_cast<const float4*>(in + row*DM);
    float4 v[4];
    float s=0.f, s2=0.f;
    #pragma unroll
    for (int i=0;i<4;i++) {
        v[i] = rp[lane + 32*i];
        s  += v[i].x+v[i].y+v[i].z+v[i].w;
        s2 += v[i].x*v[i].x + v[i].y*v[i].y + v[i].z*v[i].z + v[i].w*v[i].w;
    }
    #pragma unroll
    for (int o=16;o;o>>=1) { s += __shfl_xor_sync(~0u,s,o); s2 += __shfl_xor_sync(~0u,s2,o); }
    float mu  = s*(1.f/512.f);
    float var = s2*(1.f/512.f) - mu*mu;
    float r = rsqrtf(var + 1e-5f);
    #pragma unroll
    for (int i=0;i<4;i++) {
        int c = (lane + 32*i)*4;
        float4 g4 = *reinterpret_cast<const float4*>(gam + c);
        float4 b4 = *reinterpret_cast<const float4*>(bet + c);
        uint2 hv;
        hv.x = pack2h((v[i].x-mu)*r*g4.x + b4.x, (v[i].y-mu)*r*g4.y + b4.y);
        hv.y = pack2h((v[i].z-mu)*r*g4.z + b4.z, (v[i].w-mu)*r*g4.w + b4.w);
        *reinterpret_cast<uint2*>(g_sh + row*DM + c) = hv;
    }
}

// ---------------- local attention, head 0 (shuffle-free scores, poly exp) ----
__global__ __launch_bounds__(1024) void local_attn_kernel() {
    extern __shared__ float dyn[];
    float* tile   = dyn;            // [64][128]
    float* qs     = dyn + 8192;     // [32][128]
    float* scores = dyn + 12288;    // [32][64]
    int b   = blockIdx.x / 94;
    int blk = blockIdx.x - b*94;
    int win = blk >> 2;
    int qc  = blk & 3;
    int warp = threadIdx.x >> 5, lane = threadIdx.x & 31;
    int qt = win*128 + qc*32 + warp;
    size_t qoff = (size_t)(b*SEQ + qt)*DM;
    {
        float4 q4 = *reinterpret_cast<const float4*>(g_q + qoff + lane*4);
        *reinterpret_cast<float4*>(qs + warp*128 + lane*4) = q4;
    }
    __syncwarp();
    float m = -1e30f, l = 0.f;
    float4 acc = make_float4(0.f,0.f,0.f,0.f);
    int kbase = win*128 - 128;
    for (int ch=0; ch<6; ch++) {
        int t0 = kbase + ch*64;
        __syncthreads();
        #pragma unroll
        for (int it=0; it<2; it++) {
            int idx = it*1024 + threadIdx.x;
            int r = idx >> 5, c4 = idx & 31;
            int t = t0 + r;
            float4 kv = make_float4(0.f,0.f,0.f,0.f);
            if (t >= 0 && t < SEQ)
                kv = *reinterpret_cast<const float4*>(g_k + (size_t)(b*SEQ+t)*DM + c4*4);
            *reinterpret_cast<float4*>(tile + r*128 + c4*4) = kv;
        }
        __syncthreads();
        float s0 = 0.f, s1 = 0.f;
        const float* qrow = qs + warp*128;
        #pragma unroll
        for (int it=0; it<32; it++) {
            int d4 = ((it + lane) & 31)*4;
            float4 qv = *reinterpret_cast<const float4*>(qrow + d4);
            float4 k0 = *reinterpret_cast<const float4*>(tile + lane*128 + d4);
            float4 k1 = *reinterpret_cast<const float4*>(tile + (lane+32)*128 + d4);
            s0 = fmaf(qv.x,k0.x, fmaf(qv.y,k0.y, fmaf(qv.z,k0.z, fmaf(qv.w,k0.w, s0))));
            s1 = fmaf(qv.x,k1.x, fmaf(qv.y,k1.y, fmaf(qv.z,k1.z, fmaf(qv.w,k1.w, s1))));
        }
        {
            int ta = t0 + lane, tb = t0 + lane + 32;
            s0 = (ta >= 0 && ta < SEQ) ? s0*SCALE : -1e38f;
            s1 = (tb >= 0 && tb < SEQ) ? s1*SCALE : -1e38f;
        }
        __syncthreads();
        #pragma unroll
        for (int it=0; it<2; it++) {
            int idx = it*1024 + threadIdx.x;
            int r = idx >> 5, c4 = idx & 31;
            int t = t0 + r;
            float4 vv = make_float4(0.f,0.f,0.f,0.f);
            if (t >= 0 && t < SEQ)
                vv = *reinterpret_cast<const float4*>(g_v + (size_t)(b*SEQ+t)*DM + c4*4);
            *reinterpret_cast<float4*>(tile + r*128 + c4*4) = vv;
        }
        float cm = fmaxf(s0, s1);
        #pragma unroll
        for (int o=16;o;o>>=1) cm = fmaxf(cm, __shfl_xor_sync(~0u,cm,o));
        float mn = fmaxf(m, cm);
        float corr = EXPF(m - mn);
        l *= corr; acc.x*=corr; acc.y*=corr; acc.z*=corr; acc.w*=corr;
        float p0 = EXPF(s0 - mn), p1 = EXPF(s1 - mn);
        l += p0 + p1;
        scores[warp*64 + lane] = p0;
        scores[warp*64 + lane + 32] = p1;
        __syncthreads();
        for (int j=0; j<64; j++) {
            float p = scores[warp*64 + j];
            float4 vv = *reinterpret_cast<const float4*>(tile + j*128 + lane*4);
            acc.x = fmaf(p, vv.x, acc.x);
            acc.y = fmaf(p, vv.y, acc.y);
            acc.z = fmaf(p, vv.z, acc.z);
            acc.w = fmaf(p, vv.w, acc.w);
        }
        m = mn;
    }
    #pragma unroll
    for (int o=16;o;o>>=1) l += __shfl_xor_sync(~0u,l,o);
    float inv = 1.f/l;
    uint2 hv;
    hv.x = pack2h(acc.x*inv, acc.y*inv);
    hv.y = pack2h(acc.z*inv, acc.w*inv);
    *reinterpret_cast<uint2*>(g_sh + qoff + lane*4) = hv;
}

// ---------------- k column max (heads 1..3) ----------------------------------
__global__ void kmax_kernel() {
    int bh = blockIdx.x;
    int b = bh/3, hh = bh%3 + 1;
    int d = blockIdx.y*32 + threadIdx.x;
    int ty = threadIdx.y;
    int col = hh*DH + d;
    float m = -1e30f;
    for (int t = ty; t < SEQ; t += 8)
        m = fmaxf(m, g_k[(size_t)(b*SEQ+t)*DM + col]);
    __shared__ float sm[8][32];
    sm[ty][threadIdx.x] = m;
    __syncthreads();
    if (ty == 0) {
        #pragma unroll
        for (int r=1;r<8;r++) m = fmaxf(m, sm[r][threadIdx.x]);
        g_kmax[bh*DH + d] = m;
    }
}

// ---------------- ctx partial: unnormalized e@v + lse partials (poly exp) ----
__global__ __launch_bounds__(256) void ctx_partial_kernel() {
    __shared__ float kt[32][132];
    __shared__ float vt[32][132];
    __shared__ float smax[DH];
    int bh = blockIdx.x, ks = blockIdx.y;
    int b = bh/3, hh = bh%3 + 1;
    if (threadIdx.x < DH)
        smax[threadIdx.x] = g_kmax[bh*DH + threadIdx.x];
    int tx = threadIdx.x & 15, ty = threadIdx.x >> 4;
    int lr0 = threadIdx.x >> 5, lc4 = threadIdx.x & 31;
    float acc[8][8];
    float4 lacc = make_float4(0.f,0.f,0.f,0.f);
    #pragma unroll
    for (int i=0;i<8;i++)
        #pragma unroll
        for (int j=0;j<8;j++) acc[i][j]=0.f;

    for (int t0=0; t0<512; t0+=32) {
        __syncthreads();
        #pragma unroll
        for (int i=0;i<4;i++) {
            int r = lr0 + 8*i;
            int t = ks*512 + t0 + r;
            size_t off = (size_t)(b*SEQ+t)*DM + hh*DH + lc4*4;
            float4 kv = *reinterpret_cast<const float4*>(g_k + off);
            float4 vv = *reinterpret_cast<const float4*>(g_v + off);
            int d0 = lc4*4;
            float e0 = EXPF(kv.x - smax[d0+0]);
            float e1 = EXPF(kv.y - smax[d0+1]);
            float e2 = EXPF(kv.z - smax[d0+2]);
            float e3 = EXPF(kv.w - smax[d0+3]);
            kt[r][d0+0] = e0; kt[r][d0+1] = e1; kt[r][d0+2] = e2; kt[r][d0+3] = e3;
            lacc.x += e0; lacc.y += e1; lacc.z += e2; lacc.w += e3;
            *reinterpret_cast<float4*>(&vt[r][d0]) = vv;
        }
        __syncthreads();
        #pragma unroll
        for (int kk=0; kk<32; kk++) {
            float a[8], bb[8];
            *reinterpret_cast<float4*>(&a[0])  = *reinterpret_cast<const float4*>(&kt[kk][ty*8]);
            *reinterpret_cast<float4*>(&a[4])  = *reinterpret_cast<const float4*>(&kt[kk][ty*8+4]);
            *reinterpret_cast<float4*>(&bb[0]) = *reinterpret_cast<const float4*>(&vt[kk][tx*8]);
            *reinterpret_cast<float4*>(&bb[4]) = *reinterpret_cast<const float4*>(&vt[kk][tx*8+4]);
            #pragma unroll
            for (int i=0;i<8;i++)
                #pragma unroll
                for (int j=0;j<8;j++)
                    acc[i][j] = fmaf(a[i], bb[j], acc[i][j]);
        }
    }
    __syncthreads();
    *reinterpret_cast<float4*>(&kt[lr0][lc4*4]) = lacc;
    __syncthreads();
    if (threadIdx.x < DH) {
        float s = 0.f;
        #pragma unroll
        for (int j=0;j<8;j++) s += kt[j][threadIdx.x];
        g_lsep[(bh*8 + ks)*DH + threadIdx.x] = s;
    }
    float* op = g_ctxp + ((size_t)bh*8 + ks)*DH*DH;
    #pragma unroll
    for (int i=0;i<8;i++)
        #pragma unroll
        for (int j=0;j<8;j+=4) {
            float4 o4 = make_float4(acc[i][j],acc[i][j+1],acc[i][j+2],acc[i][j+3]);
            *reinterpret_cast<float4*>(op + (size_t)(ty*8+i)*DH + tx*8 + j) = o4;
        }
}

// ---------------- ctx reduce + normalize by lse ------------------------------
__global__ void ctx_reduce_kernel() {
    int idx = blockIdx.x*256 + threadIdx.x;
    if (idx >= BSZ*3*DH*DH) return;
    int bh = idx / (DH*DH);
    int de = idx - bh*DH*DH;
    int d = de >> 7;
    float s = 0.f, ls = 0.f;
    #pragma unroll
    for (int ks=0;ks<8;ks++) {
        s  += g_ctxp[((size_t)bh*8+ks)*DH*DH + de];
        ls += g_lsep[(bh*8+ks)*DH + d];
    }
    g_ctx[idx] = s / ls;
}

// ---------------- linear-attn output -> fp16 (poly exp) ----------------------
__global__ __launch_bounds__(256) void lin_out_kernel() {
    __shared__ float sctx[64][DH];
    int bh = blockIdx.x;
    int b = bh/3, hh = bh%3 + 1;
    int warp = threadIdx.x >> 5, lane = threadIdx.x & 31;
    const float* ctxp = g_ctx + (size_t)bh*DH*DH;
    float pr[4][4], o[4][4];
    int tbase = blockIdx.y*32 + warp*4;
    #pragma unroll
    for (int tt=0;tt<4;tt++) {
        int t = tbase + tt;
        const float* qp = g_q + (size_t)(b*SEQ+t)*DM + hh*DH;
        float4 q4 = *reinterpret_cast<const float4*>(qp + lane*4);
        float mx = fmaxf(fmaxf(q4.x,q4.y),fmaxf(q4.z,q4.w));
        #pragma unroll
        for (int s=16;s;s>>=1) mx = fmaxf(mx, __shfl_xor_sync(~0u,mx,s));
        float e0=EXPF(q4.x-mx), e1=EXPF(q4.y-mx), e2=EXPF(q4.z-mx), e3=EXPF(q4.w-mx);
        float sm = e0+e1+e2+e3;
        #pragma unroll
        for (int s=16;s;s>>=1) sm += __shfl_xor_sync(~0u,sm,s);
        float inv = SCALE/sm;
        pr[tt][0]=e0*inv; pr[tt][1]=e1*inv; pr[tt][2]=e2*inv; pr[tt][3]=e3*inv;
        o[tt][0]=0.f; o[tt][1]=0.f; o[tt][2]=0.f; o[tt][3]=0.f;
    }
    for (int ph=0; ph<2; ph++) {
        __syncthreads();
        #pragma unroll
        for (int i=0;i<8;i++) {
            int idx = i*256 + threadIdx.x;
            int r = idx >> 5, c4 = idx & 31;
            *reinterpret_cast<float4*>(&sctx[r][c4*4]) =
                *reinterpret_cast<const float4*>(ctxp + (size_t)(ph*64+r)*DH + c4*4);
        }
        __syncthreads();
        #pragma unroll
        for (int dl=0; dl<16; dl++) {
            int src = ph*16 + dl;
            #pragma unroll
            for (int tt=0;tt<4;tt++) {
                float b0 = __shfl_sync(~0u, pr[tt][0], src);
                float b1 = __shfl_sync(~0u, pr[tt][1], src);
                float b2 = __shfl_sync(~0u, pr[tt][2], src);
                float b3 = __shfl_sync(~0u, pr[tt][3], src);
                float4 c0 = *reinterpret_cast<const float4*>(&sctx[dl*4+0][lane*4]);
                float4 c1 = *reinterpret_cast<const float4*>(&sctx[dl*4+1][lane*4]);
                float4 c2 = *reinterpret_cast<const float4*>(&sctx[dl*4+2][lane*4]);
                float4 c3 = *reinterpret_cast<const float4*>(&sctx[dl*4+3][lane*4]);
                o[tt][0] += b0*c0.x + b1*c1.x + b2*c2.x + b3*c3.x;
                o[tt][1] += b0*c0.y + b1*c1.y + b2*c2.y + b3*c3.y;
                o[tt][2] += b0*c0.z + b1*c1.z + b2*c2.z + b3*c3.z;
                o[tt][3] += b0*c0.w + b1*c1.w + b2*c2.w + b3*c3.w;
            }
        }
    }
    #pragma unroll
    for (int tt=0;tt<4;tt++) {
        int t = tbase + tt;
        uint2 hv;
        hv.x = pack2h(o[tt][0], o[tt][1]);
        hv.y = pack2h(o[tt][2], o[tt][3]);
        *reinterpret_cast<uint2*>(g_sh + (size_t)(b*SEQ+t)*DM + hh*DH + lane*4) = hv;
    }
}

// ---------------- host ---------------------------------------------------
static inline void tc_gemm(cudaStream_t st, const fp16* A, const fp16* B,
                           const float* bias, const float* res,
                           float* C, float* Ck, float* Cv, fp16* Ch,
                           int N, int K, int act, int omul = SEQ) {
    dim3 grid((N + 127) / 128, BSZ*MTPB);
    tc_gemm_kernel<<<grid, 256, GEMM_SMEM, st>>>(A, B, bias, res, C, Ck, Cv, Ch,
                                                 N, K, act, omul);
}

extern "C" void kernel_launch(void* const* d_in, const int* in_sizes, int n_in,
                              void* d_out, int out_size) {
    const float* x    = (const float*)d_in[0];
    const float* W1   = (const float*)d_in[1];
    const float* b1   = (const float*)d_in[2];
    const float* ln1g = (const float*)d_in[3];
    const float* ln1b = (const float*)d_in[4];
    const float* Wq   = (const float*)d_in[5];
    const float* Wk   = (const float*)d_in[6];
    const float* Wv   = (const float*)d_in[7];
    const float* Wo   = (const float*)d_in[8];
    const float* bo   = (const float*)d_in[9];
    const float* ln2g = (const float*)d_in[10];
    const float* ln2b = (const float*)d_in[11];
    const float* Wf1  = (const float*)d_in[12];
    const float* bf1  = (const float*)d_in[13];
    const float* Wf2  = (const float*)d_in[14];
    const float* bf2  = (const float*)d_in[15];
    const float* W2   = (const float*)d_in[16];
    const float* b2   = (const float*)d_in[17];
    float* out = (float*)d_out;

    static int init_done = 0;
    static cudaStream_t st1, st2;
    static cudaEvent_t evStart, evT1, evQKV, evPad, evLin;
    if (!init_done) {
        cudaFuncSetAttribute(tc_gemm_kernel, cudaFuncAttributeMaxDynamicSharedMemorySize, GEMM_SMEM);
        cudaFuncSetAttribute(local_attn_kernel, cudaFuncAttributeMaxDynamicSharedMemorySize, LA_SMEM);
        cudaStreamCreateWithFlags(&st1, cudaStreamNonBlocking);
        cudaStreamCreateWithFlags(&st2, cudaStreamNonBlocking);
        cudaEventCreateWithFlags(&evStart, cudaEventDisableTiming);
        cudaEventCreateWithFlags(&evT1,    cudaEventDisableTiming);
        cudaEventCreateWithFlags(&evQKV,   cudaEventDisableTiming);
        cudaEventCreateWithFlags(&evPad,   cudaEventDisableTiming);
        cudaEventCreateWithFlags(&evLin,   cudaEventDisableTiming);
        init_done = 1;
    }

    float *h,*q,*k,*v;
    fp16 *sh,*s2h;
    fp16 *w1h,*wqkv,*woh,*wf1h,*wf2h,*w2h;
    cudaGetSymbolAddress((void**)&h,    g_h);
    cudaGetSymbolAddress((void**)&q,    g_q);
    cudaGetSymbolAddress((void**)&k,    g_k);
    cudaGetSymbolAddress((void**)&v,    g_v);
    cudaGetSymbolAddress((void**)&sh,   g_sh);
    cudaGetSymbolAddress((void**)&s2h,  g_s2h);
    cudaGetSymbolAddress((void**)&w1h,  g_w1h);
    cudaGetSymbolAddress((void**)&wqkv, g_wqkv);
    cudaGetSymbolAddress((void**)&woh,  g_woh);
    cudaGetSymbolAddress((void**)&wf1h, g_wf1h);
    cudaGetSymbolAddress((void**)&wf2h, g_wf2h);
    cudaGetSymbolAddress((void**)&w2h,  g_w2h);

    dim3 tb(32, 8);

    // fork: pad-row chain (st2) and weight transposes (st1)
    cudaEventRecord(evStart, 0);
    cudaStreamWaitEvent(st2, evStart, 0);
    pad_ln_kernel<<<1, 512, 0, st2>>>(b1, ln1g, ln1b);
    pad_kv_kernel<<<4, 256, 0, st2>>>(Wk, Wv);
    padfill_kernel<<<(BSZ*(SEQ-NTOK)*(DM/4) + 255)/256, 256, 0, st2>>>();
    cudaEventRecord(evPad, st2);

    cudaStreamWaitEvent(st1, evStart, 0);
    transpose_h_kernel<<<dim3(DM/32,  DM/32),  tb, 0, st1>>>(Wq,  wqkv,            DM,  DM);
    transpose_h_kernel<<<dim3(DM/32,  DM/32),  tb, 0, st1>>>(Wk,  wqkv + DM*DM,    DM,  DM);
    transpose_h_kernel<<<dim3(DM/32,  DM/32),  tb, 0, st1>>>(Wv,  wqkv + 2*DM*DM,  DM,  DM);
    transpose_h_kernel<<<dim3(DM/32,  DM/32),  tb, 0, st1>>>(Wo,  woh,  DM,  DM);
    transpose_h_kernel<<<dim3(DFF/32, DM/32),  tb, 0, st1>>>(Wf1, wf1h, DM,  DFF);
    transpose_h_kernel<<<dim3(DM/32,  DFF/32), tb, 0, st1>>>(Wf2, wf2h, DFF, DM);
    transpose_h_kernel<<<dim3(DOUT/32,DM/32),  tb, 0, st1>>>(W2,  w2h,  DM,  DOUT);
    cudaEventRecord(evT1, st1);

    // main stream
    transpose_h_kernel<<<dim3(DM/32, DIN/32), tb>>>(W1, w1h, DIN, DM);
    pad_split_kernel<<<(BSZ*NTOK*(DIN/4) + 255)/256, 256>>>(x);
    tc_gemm(0, sh, w1h, b1, nullptr, h, nullptr, nullptr, nullptr, DM, DIN, 1);
    ln_kernel<<<BSZ*NTOK/8, 256>>>(h, ln1g, ln1b);
    cudaStreamWaitEvent(0, evT1, 0);
    // fused QKV: N=1536, routed epilogue (q | k | v), stride 512
    tc_gemm(0, sh, wqkv, nullptr, nullptr, q, k, v, nullptr, 3*DM, DM, 0);
    cudaEventRecord(evQKV, 0);

    // linear-attn chain on st1, local attention on main stream
    cudaStreamWaitEvent(st1, evQKV, 0);
    cudaStreamWaitEvent(st1, evPad, 0);
    kmax_kernel<<<dim3(BSZ*3,4), dim3(32,8), 0, st1>>>();
    ctx_partial_kernel<<<dim3(BSZ*3,8), 256, 0, st1>>>();
    ctx_reduce_kernel<<<(BSZ*3*DH*DH + 255)/256, 256, 0, st1>>>();
    lin_out_kernel<<<dim3(BSZ*3, 94), 256, 0, st1>>>();
    cudaEventRecord(evLin, st1);

    cudaStreamWaitEvent(0, evPad, 0);
    local_attn_kernel<<<BSZ*94, 1024, LA_SMEM>>>();
    cudaStreamWaitEvent(0, evLin, 0);

    // tail on main stream
    tc_gemm(0, sh, woh, bo, h, h, nullptr, nullptr, nullptr, DM, DM, 0);
    ln_kernel<<<BSZ*NTOK/8, 256>>>(h, ln2g, ln2b);
    tc_gemm(0, sh, wf1h, bf1, nullptr, nullptr, nullptr, nullptr, s2h, DFF, DM, 2);
    tc_gemm(0, s2h, wf2h, bf2, h, nullptr, nullptr, nullptr, sh, DM, DFF, 0);
    tc_gemm(0, sh, w2h, b2, nullptr, out, nullptr, nullptr, nullptr, DOUT, DM, 0, NTOK);
}

// round 12
// speedup vs baseline: 1.1288x; 1.1288x over previous
#include <cuda_runtime.h>
#include <cuda_fp16.h>
#include <math.h>
#include <stdint.h>

#define BSZ   8
#define SEQ   4096
#define NTOK  3000
#define DIN   128
#define DM    512
#define DFF   2048
#define DOUT  64
#define DH    128
#define MTOT  (BSZ*SEQ)
#define MTPB  24                     // M-tiles per batch: ceil(3000/128)
#define QBPB  47                     // query blocks per batch: ceil(3000/64)
#define SCALE 0.08838834764831845f   // 1/sqrt(128)
#define GEMM_SMEM (3*32768)          // 3 stages x (2 subchunks x 2 arrays x 8KB)
#define LA_SMEM   114688             // K 32K + V 32K + q 32K + scores 16K

typedef __half fp16;

// ---------------- scratch (static device globals: no allocation) -------------
__device__ float g_h[MTOT*DM];
__device__ float g_q[MTOT*DM];
__device__ float g_k[MTOT*DM];
__device__ float g_v[MTOT*DM];
__device__ float g_kmax[BSZ*3*DH];
__device__ float g_lsep[BSZ*3*8*DH];
__device__ float g_ctxp[BSZ*3*8*DH*DH];
__device__ float g_ctx[BSZ*3*DH*DH];
__device__ float g_lnpad[DM];
__device__ float g_kpad[DM];
__device__ float g_vpad[DM];
// fp16 activation buffers
__device__ fp16 g_sh[MTOT*DM];
__device__ fp16 g_s2h[MTOT*DFF];
// transposed weights [N][K], fp16
__device__ fp16 g_w1h[DM*DIN];
__device__ fp16 g_wqkv[3*DM*DM];
__device__ fp16 g_woh[DM*DM];
__device__ fp16 g_wf1h[DFF*DM];
__device__ fp16 g_wf2h[DM*DFF];
__device__ fp16 g_w2h[DOUT*DM];

// ---------------- helpers ----------------
__device__ __forceinline__ uint32_t smem_u32(const void* p) {
    uint32_t a;
    asm("{ .reg .u64 t; cvta.to.shared.u64 t, %1; cvt.u32.u64 %0, t; }" : "=r"(a) : "l"(p));
    return a;
}
__device__ __forceinline__ uint32_t pack2h(float x, float y) {
    __half2 h = __floats2half2_rn(x, y);
    return *reinterpret_cast<uint32_t*>(&h);
}
// fast exp for x <= 0 on the FMA pipe. rel err ~1e-7.
__device__ __forceinline__ float fexp(float x) {
    x = fmaxf(x, -87.0f);
    float t = x * 1.4426950408889634f;
    float fn = rintf(t);
    float r = t - fn;
    float p =            1.5403530394e-4f;
    p = fmaf(p, r, 1.3333558146e-3f);
    p = fmaf(p, r, 9.6181291076e-3f);
    p = fmaf(p, r, 5.5504108665e-2f);
    p = fmaf(p, r, 2.4022650696e-1f);
    p = fmaf(p, r, 6.9314718056e-1f);
    p = fmaf(p, r, 1.0f);
    return __int_as_float(__float_as_int(p) + (((int)fn) << 23));
}
#define EXPF(x) fexp(x)

#define LDSM_X4(r0,r1,r2,r3,addr) \
    asm volatile("ldmatrix.sync.aligned.m8n8.x4.shared.b16 {%0,%1,%2,%3}, [%4];" \
        : "=r"(r0),"=r"(r1),"=r"(r2),"=r"(r3) : "r"(addr))
#define MMA16816(d, a0,a1,a2,a3, b0,b1) \
    asm volatile("mma.sync.aligned.m16n8k16.row.col.f32.f16.f16.f32 " \
        "{%0,%1,%2,%3},{%4,%5,%6,%7},{%8,%9},{%0,%1,%2,%3};" \
        : "+f"((d)[0]),"+f"((d)[1]),"+f"((d)[2]),"+f"((d)[3]) \
        : "r"(a0),"r"(a1),"r"(a2),"r"(a3),"r"(b0),"r"(b1))
#define CP_ASYNC16(dst, src, sz) \
    asm volatile("cp.async.cg.shared.global [%0], [%1], 16, %2;" :: "r"(dst), "l"(src), "r"(sz))
#define CP_COMMIT()  asm volatile("cp.async.commit_group;" ::: "memory")
#define CP_WAIT0()   asm volatile("cp.async.wait_group 0;" ::: "memory")
#define CP_WAIT1()   asm volatile("cp.async.wait_group 1;" ::: "memory")

// ---------------- weight transpose + fp16: T[n][k] = h(W[k][n]) --------------
__global__ void transpose_h_kernel(const float* __restrict__ W,
                                   fp16* __restrict__ Th, int K, int N) {
    __shared__ float t[32][33];
    int bx = blockIdx.x * 32, by = blockIdx.y * 32;
    int x = bx + threadIdx.x;
    #pragma unroll
    for (int i = 0; i < 32; i += 8) {
        int y = by + threadIdx.y + i;
        if (x < N && y < K) t[threadIdx.y + i][threadIdx.x] = W[(size_t)y * N + x];
    }
    __syncthreads();
    int xk = by + threadIdx.x;
    #pragma unroll
    for (int i = 0; i < 32; i += 8) {
        int yn = bx + threadIdx.y + i;
        if (xk < K && yn < N)
            Th[(size_t)yn * K + xk] = __float2half_rn(t[threadIdx.x][threadIdx.y + i]);
    }
}

// ---------------- x (real rows only) -> g_sh fp16 ----------------------------
__global__ void pad_split_kernel(const float* __restrict__ x) {
    int idx = blockIdx.x*256 + threadIdx.x;
    const int total = BSZ*NTOK*(DIN/4);
    if (idx >= total) return;
    int rr = idx >> 5;
    int c4 = idx & 31;
    int b = rr / NTOK, t = rr - b*NTOK;
    float4 val = reinterpret_cast<const float4*>(x)[(size_t)rr*32 + c4];
    uint2 hv;
    hv.x = pack2h(val.x, val.y);
    hv.y = pack2h(val.z, val.w);
    *reinterpret_cast<uint2*>(g_sh + (size_t)(b*SEQ + t)*DIN + c4*4) = hv;
}

// ---------------- pad-row LN: lnpad = LN(tanh(b1)) ---------------------------
__global__ void pad_ln_kernel(const float* __restrict__ b1, const float* __restrict__ gam,
                              const float* __restrict__ bet) {
    __shared__ float ss[16], ss2[16], stat[2];
    int t = threadIdx.x;
    float h = tanhf(b1[t]);
    float s = h, s2 = h*h;
    #pragma unroll
    for (int o=16;o;o>>=1) { s += __shfl_xor_sync(~0u,s,o); s2 += __shfl_xor_sync(~0u,s2,o); }
    if ((t & 31) == 0) { ss[t>>5] = s; ss2[t>>5] = s2; }
    __syncthreads();
    if (t == 0) {
        float S=0.f, S2=0.f;
        #pragma unroll
        for (int i=0;i<16;i++) { S += ss[i]; S2 += ss2[i]; }
        float mu = S*(1.f/512.f);
        float var = S2*(1.f/512.f) - mu*mu;
        stat[0] = mu; stat[1] = rsqrtf(var + 1e-5f);
    }
    __syncthreads();
    g_lnpad[t] = (h - stat[0])*stat[1]*gam[t] + bet[t];
}

// ---------------- pad-row k/v ------------------------------------------------
__global__ void pad_kv_kernel(const float* __restrict__ Wk, const float* __restrict__ Wv) {
    int d = blockIdx.x*256 + threadIdx.x;
    if (d >= 2*DM) return;
    const float* W = (d < DM) ? Wk : Wv;
    int dd = d & (DM-1);
    float s = 0.f;
    for (int kk = 0; kk < DM; kk++) s += g_lnpad[kk] * W[(size_t)kk*DM + dd];
    if (d < DM) g_kpad[dd] = s; else g_vpad[dd] = s;
}

// ---------------- broadcast pad k/v rows -------------------------------------
__global__ void padfill_kernel() {
    int idx = blockIdx.x*256 + threadIdx.x;
    const int per = (SEQ-NTOK)*(DM/4);
    if (idx >= BSZ*per) return;
    int b = idx / per, r = idx - b*per;
    int t = NTOK + r/(DM/4), c4 = r % (DM/4);
    size_t off = (size_t)(b*SEQ + t)*DM + c4*4;
    *reinterpret_cast<float4*>(g_k + off) = *reinterpret_cast<const float4*>(g_kpad + c4*4);
    *reinterpret_cast<float4*>(g_v + off) = *reinterpret_cast<const float4*>(g_vpad + c4*4);
}

// ---------------- fp16 tensor-core GEMM, K-chunk 64 (real rows) --------------
__global__ __launch_bounds__(256, 2) void tc_gemm_kernel(
    const fp16* __restrict__ A, const fp16* __restrict__ B,
    const float* __restrict__ bias, const float* __restrict__ res,
    float* __restrict__ C, float* __restrict__ Ck, float* __restrict__ Cv,
    fp16* __restrict__ Ch,
    int N, int K, int act, int omul)
{
    extern __shared__ __align__(1024) char smc[];
    uint32_t sbase = smem_u32(smc);
    int tid = threadIdx.x;
    int mtile = blockIdx.y;
    int bb = mtile / MTPB, t0 = (mtile - bb*MTPB) << 7;
    int bm = bb*SEQ + t0;
    int alim = NTOK - t0;
    int rowlim = bm + alim;
    int odelta = bb*(omul - SEQ);
    int bn = blockIdx.x << 7;
    int lane = tid & 31, w = tid >> 5;
    int wm = w & 1, wn = w >> 1;
    int grp = lane >> 2, qp = lane & 3;

    uint32_t swz = (lane >> 1) & 3;
    uint32_t a_base = (uint32_t)(wm*64 + (lane & 15))*64 + (((uint32_t)(lane >> 4) ^ swz) << 4);
    uint32_t b_base = (uint32_t)(wn*32 + ((lane >> 4) & 1)*8 + (lane & 7))*64
                    + ((((uint32_t)(lane >> 3) & 1) ^ swz) << 4);

    float acc[4][4][4];
    #pragma unroll
    for (int i=0;i<4;i++)
        #pragma unroll
        for (int j=0;j<4;j++)
            #pragma unroll
            for (int r=0;r<4;r++) acc[i][j][r] = 0.f;

    const int NC = K >> 6;

    #define STAGE_LOAD(c_, buf_) do { \
        uint32_t sb = sbase + (uint32_t)(buf_)*32768u; \
        _Pragma("unroll") \
        for (int i_ = 0; i_ < 8; i_++) { \
            const int sub_ = i_ >> 2; \
            const int arr_ = (i_ >> 1) & 1; \
            int j_ = ((i_ & 1) << 8) + tid; \
            int r_ = j_ >> 2, cc_ = j_ & 3; \
            int k0 = ((c_) << 6) + sub_*32; \
            uint32_t dst_ = sb + (uint32_t)sub_*16384u + (uint32_t)arr_*8192u \
                          + (uint32_t)r_*64u + ((uint32_t)(cc_ ^ ((r_ >> 1) & 3)) << 4); \
            const fp16* g_; int sz_ = 16; \
            if (arr_ == 0) { \
                if (r_ < alim) g_ = A + (size_t)(bm + r_)*K + k0 + cc_*8; \
                else { g_ = A; sz_ = 0; } \
            } else { \
                int rowv_ = bn + r_; \
                if (rowv_ < N) g_ = B + (size_t)rowv_*K + k0 + cc_*8; \
                else { g_ = B; sz_ = 0; } \
            } \
            CP_ASYNC16(dst_, g_, sz_); \
        } \
        CP_COMMIT(); \
    } while (0)

    STAGE_LOAD(0, 0);
    if (NC > 1) STAGE_LOAD(1, 1);

    int buf = 0, bufn = 2;
    for (int c = 0; c < NC; c++) {
        if (c + 1 < NC) CP_WAIT1(); else CP_WAIT0();
        __syncthreads();
        if (c + 2 < NC) {
            STAGE_LOAD(c + 2, bufn);
            bufn = (bufn == 2) ? 0 : bufn + 1;
        }
        uint32_t stg = sbase + (uint32_t)buf*32768u;
        buf = (buf == 2) ? 0 : buf + 1;

        #pragma unroll
        for (int sub = 0; sub < 2; sub++) {
            uint32_t sA = stg + (uint32_t)sub*16384u;
            uint32_t sB = sA + 8192u;
            #pragma unroll
            for (int ks = 0; ks < 2; ks++) {
                uint32_t kx = ks ? 32u : 0u;
                uint32_t bh[4][2], a[4][4];
                #pragma unroll
                for (int p = 0; p < 2; p++)
                    LDSM_X4(bh[2*p][0], bh[2*p][1], bh[2*p+1][0], bh[2*p+1][1],
                            sB + ((b_base + p*1024u) ^ kx));
                #pragma unroll
                for (int mt = 0; mt < 4; mt++)
                    LDSM_X4(a[mt][0], a[mt][1], a[mt][2], a[mt][3],
                            sA + ((a_base + mt*1024u) ^ kx));
                #pragma unroll
                for (int mt = 0; mt < 4; mt++)
                    #pragma unroll
                    for (int nt = 0; nt < 4; nt++)
                        MMA16816(acc[mt][nt], a[mt][0],a[mt][1],a[mt][2],a[mt][3],
                                 bh[nt][0],bh[nt][1]);
            }
        }
    }
    #undef STAGE_LOAD

    // ---- epilogue (valid rows only) ----
    #pragma unroll
    for (int mt = 0; mt < 4; mt++) {
        #pragma unroll
        for (int nt = 0; nt < 4; nt++) {
            int c0 = bn + wn*32 + nt*8 + qp*2;
            if (c0 >= N) continue;
            int rbase = bm + wm*64 + mt*16 + grp;
            float bs0 = 0.f, bs1 = 0.f;
            if (bias) { bs0 = bias[c0]; bs1 = bias[c0 + 1]; }
            #pragma unroll
            for (int half = 0; half < 2; half++) {
                int r = rbase + half*8;
                if (r >= rowlim) continue;
                float v0 = acc[mt][nt][half*2 + 0] + bs0;
                float v1 = acc[mt][nt][half*2 + 1] + bs1;
                if (act == 1) { v0 = tanhf(v0); v1 = tanhf(v1); }
                else if (act == 2) {
                    v0 = 0.5f*v0*(1.f + erff(v0*0.7071067811865476f));
                    v1 = 0.5f*v1*(1.f + erff(v1*0.7071067811865476f));
                }
                if (res) {
                    v0 += res[(size_t)r*N + c0];
                    v1 += res[(size_t)r*N + c0 + 1];
                }
                size_t orow = (size_t)(r + odelta);
                if (Ck) {
                    float* dst; int cc;
                    if (c0 < 512)       { dst = C;  cc = c0; }
                    else if (c0 < 1024) { dst = Ck; cc = c0 - 512; }
                    else                { dst = Cv; cc = c0 - 1024; }
                    float2 o; o.x = v0; o.y = v1;
                    *reinterpret_cast<float2*>(dst + orow*512 + cc) = o;
                } else if (Ch) {
                    *reinterpret_cast<uint32_t*>(Ch + orow*N + c0) = pack2h(v0, v1);
                } else {
                    float2 o; o.x = v0; o.y = v1;
                    *reinterpret_cast<float2*>(C + orow*N + c0) = o;
                }
            }
        }
    }
}

// ---------------- LayerNorm (real rows) -> fp16 ------------------------------
__global__ void ln_kernel(const float* __restrict__ in, const float* __restrict__ gam,
                          const float* __restrict__ bet) {
    int gw = (blockIdx.x*blockDim.x + threadIdx.x) >> 5;
    int lane = threadIdx.x & 31;
    if (gw >= BSZ*NTOK) return;
    int b = gw / NTOK, t = gw - b*NTOK;
    size_t row = (size_t)(b*SEQ + t);
    const float4* rp = reinterpret_cast<const float4*>(in + row*DM);
    float4 v[4];
    float s=0.f, s2=0.f;
    #pragma unroll
    for (int i=0;i<4;i++) {
        v[i] = rp[lane + 32*i];
        s  += v[i].x+v[i].y+v[i].z+v[i].w;
        s2 += v[i].x*v[i].x + v[i].y*v[i].y + v[i].z*v[i].z + v[i].w*v[i].w;
    }
    #pragma unroll
    for (int o=16;o;o>>=1) { s += __shfl_xor_sync(~0u,s,o); s2 += __shfl_xor_sync(~0u,s2,o); }
    float mu  = s*(1.f/512.f);
    float var = s2*(1.f/512.f) - mu*mu;
    float r = rsqrtf(var + 1e-5f);
    #pragma unroll
    for (int i=0;i<4;i++) {
        int c = (lane + 32*i)*4;
        float4 g4 = *reinterpret_cast<const float4*>(gam + c);
        float4 b4 = *reinterpret_cast<const float4*>(bet + c);
        uint2 hv;
        hv.x = pack2h((v[i].x-mu)*r*g4.x + b4.x, (v[i].y-mu)*r*g4.y + b4.y);
        hv.y = pack2h((v[i].z-mu)*r*g4.z + b4.z, (v[i].w-mu)*r*g4.w + b4.w);
        *reinterpret_cast<uint2*>(g_sh + row*DM + c) = hv;
    }
}

// ---------------- local attention, head 0: 2 queries/warp, K+V co-resident ---
// dyn smem floats: kt[64][128]@0, vt[64][128]@8192, qs[64][128]@16384,
//                  sc[64][64]@24576
__global__ __launch_bounds__(1024) void local_attn_kernel() {
    extern __shared__ float dyn[];
    float* kt = dyn;
    float* vt = dyn + 8192;
    float* qs = dyn + 16384;
    float* sc = dyn + 24576;
    int b   = blockIdx.x / QBPB;
    int blk = blockIdx.x - b*QBPB;
    int qbase = blk*64;
    int win = qbase >> 7;
    int warp = threadIdx.x >> 5, lane = threadIdx.x & 31;
    int qt0 = qbase + warp, qt1 = qbase + warp + 32;
    size_t qoff0 = (size_t)(b*SEQ + qt0)*DM;
    size_t qoff1 = (size_t)(b*SEQ + qt1)*DM;
    {
        *reinterpret_cast<float4*>(qs + warp*128 + lane*4) =
            *reinterpret_cast<const float4*>(g_q + qoff0 + lane*4);
        *reinterpret_cast<float4*>(qs + (warp+32)*128 + lane*4) =
            *reinterpret_cast<const float4*>(g_q + qoff1 + lane*4);
    }
    float m0 = -1e30f, l0 = 0.f, m1 = -1e30f, l1 = 0.f;
    float4 acc0 = make_float4(0.f,0.f,0.f,0.f);
    float4 acc1 = make_float4(0.f,0.f,0.f,0.f);
    int kbase = win*128 - 128;
    for (int ch=0; ch<6; ch++) {
        int t0 = kbase + ch*64;
        __syncthreads();                 // prior PV done before overwrite
        #pragma unroll
        for (int it=0; it<4; it++) {     // K (it 0-1) then V (it 2-3)
            int idx = (it & 1)*1024 + threadIdx.x;
            int r = idx >> 5, c4 = idx & 31;
            int t = t0 + r;
            float* dst = (it < 2) ? kt : vt;
            const float* src = (it < 2) ? g_k : g_v;
            float4 val = make_float4(0.f,0.f,0.f,0.f);
            if (t >= 0 && t < SEQ)
                val = *reinterpret_cast<const float4*>(src + (size_t)(b*SEQ+t)*DM + c4*4);
            *reinterpret_cast<float4*>(dst + r*128 + c4*4) = val;
        }
        __syncthreads();
        // scores: 2 queries x 2 keys per lane, shared K reads
        float s00 = 0.f, s01 = 0.f, s10 = 0.f, s11 = 0.f;
        const float* qa = qs + warp*128;
        const float* qb = qs + (warp+32)*128;
        #pragma unroll
        for (int it=0; it<32; it++) {
            int d4 = ((it + lane) & 31)*4;
            float4 q0 = *reinterpret_cast<const float4*>(qa + d4);
            float4 q1 = *reinterpret_cast<const float4*>(qb + d4);
            float4 k0 = *reinterpret_cast<const float4*>(kt + lane*128 + d4);
            float4 k1 = *reinterpret_cast<const float4*>(kt + (lane+32)*128 + d4);
            s00 = fmaf(q0.x,k0.x, fmaf(q0.y,k0.y, fmaf(q0.z,k0.z, fmaf(q0.w,k0.w, s00))));
            s01 = fmaf(q0.x,k1.x, fmaf(q0.y,k1.y, fmaf(q0.z,k1.z, fmaf(q0.w,k1.w, s01))));
            s10 = fmaf(q1.x,k0.x, fmaf(q1.y,k0.y, fmaf(q1.z,k0.z, fmaf(q1.w,k0.w, s10))));
            s11 = fmaf(q1.x,k1.x, fmaf(q1.y,k1.y, fmaf(q1.z,k1.z, fmaf(q1.w,k1.w, s11))));
        }
        {
            int ta = t0 + lane, tb = t0 + lane + 32;
            bool va = (ta >= 0 && ta < SEQ), vb = (tb >= 0 && tb < SEQ);
            s00 = va ? s00*SCALE : -1e38f;
            s01 = vb ? s01*SCALE : -1e38f;
            s10 = va ? s10*SCALE : -1e38f;
            s11 = vb ? s11*SCALE : -1e38f;
        }
        // online softmax per query
        float cm0 = fmaxf(s00, s01), cm1 = fmaxf(s10, s11);
        #pragma unroll
        for (int o=16;o;o>>=1) {
            cm0 = fmaxf(cm0, __shfl_xor_sync(~0u,cm0,o));
            cm1 = fmaxf(cm1, __shfl_xor_sync(~0u,cm1,o));
        }
        float mn0 = fmaxf(m0, cm0), mn1 = fmaxf(m1, cm1);
        float c0 = EXPF(m0 - mn0), c1 = EXPF(m1 - mn1);
        l0 *= c0; acc0.x*=c0; acc0.y*=c0; acc0.z*=c0; acc0.w*=c0;
        l1 *= c1; acc1.x*=c1; acc1.y*=c1; acc1.z*=c1; acc1.w*=c1;
        float p00 = EXPF(s00 - mn0), p01 = EXPF(s01 - mn0);
        float p10 = EXPF(s10 - mn1), p11 = EXPF(s11 - mn1);
        l0 += p00 + p01; l1 += p10 + p11;
        sc[warp*64 + lane]        = p00;
        sc[warp*64 + lane + 32]   = p01;
        sc[(warp+32)*64 + lane]      = p10;
        sc[(warp+32)*64 + lane + 32] = p11;
        __syncwarp();
        // PV: shared V read for both queries
        for (int j=0; j<64; j++) {
            float p0 = sc[warp*64 + j];
            float p1 = sc[(warp+32)*64 + j];
            float4 vv = *reinterpret_cast<const float4*>(vt + j*128 + lane*4);
            acc0.x = fmaf(p0, vv.x, acc0.x);
            acc0.y = fmaf(p0, vv.y, acc0.y);
            acc0.z = fmaf(p0, vv.z, acc0.z);
            acc0.w = fmaf(p0, vv.w, acc0.w);
            acc1.x = fmaf(p1, vv.x, acc1.x);
            acc1.y = fmaf(p1, vv.y, acc1.y);
            acc1.z = fmaf(p1, vv.z, acc1.z);
            acc1.w = fmaf(p1, vv.w, acc1.w);
        }
        m0 = mn0; m1 = mn1;
    }
    #pragma unroll
    for (int o=16;o;o>>=1) {
        l0 += __shfl_xor_sync(~0u,l0,o);
        l1 += __shfl_xor_sync(~0u,l1,o);
    }
    float i0 = 1.f/l0, i1 = 1.f/l1;
    uint2 hv;
    hv.x = pack2h(acc0.x*i0, acc0.y*i0);
    hv.y = pack2h(acc0.z*i0, acc0.w*i0);
    *reinterpret_cast<uint2*>(g_sh + qoff0 + lane*4) = hv;
    hv.x = pack2h(acc1.x*i1, acc1.y*i1);
    hv.y = pack2h(acc1.z*i1, acc1.w*i1);
    *reinterpret_cast<uint2*>(g_sh + qoff1 + lane*4) = hv;
}

// ---------------- k column max (heads 1..3) ----------------------------------
__global__ void kmax_kernel() {
    int bh = blockIdx.x;
    int b = bh/3, hh = bh%3 + 1;
    int d = blockIdx.y*32 + threadIdx.x;
    int ty = threadIdx.y;
    int col = hh*DH + d;
    float m = -1e30f;
    for (int t = ty; t < SEQ; t += 8)
        m = fmaxf(m, g_k[(size_t)(b*SEQ+t)*DM + col]);
    __shared__ float sm[8][32];
    sm[ty][threadIdx.x] = m;
    __syncthreads();
    if (ty == 0) {
        #pragma unroll
        for (int r=1;r<8;r++) m = fmaxf(m, sm[r][threadIdx.x]);
        g_kmax[bh*DH + d] = m;
    }
}

// ---------------- ctx partial: unnormalized e@v + lse partials ---------------
__global__ __launch_bounds__(256) void ctx_partial_kernel() {
    __shared__ float kt[32][132];
    __shared__ float vt[32][132];
    __shared__ float smax[DH];
    int bh = blockIdx.x, ks = blockIdx.y;
    int b = bh/3, hh = bh%3 + 1;
    if (threadIdx.x < DH)
        smax[threadIdx.x] = g_kmax[bh*DH + threadIdx.x];
    int tx = threadIdx.x & 15, ty = threadIdx.x >> 4;
    int lr0 = threadIdx.x >> 5, lc4 = threadIdx.x & 31;
    float acc[8][8];
    float4 lacc = make_float4(0.f,0.f,0.f,0.f);
    #pragma unroll
    for (int i=0;i<8;i++)
        #pragma unroll
        for (int j=0;j<8;j++) acc[i][j]=0.f;

    for (int t0=0; t0<512; t0+=32) {
        __syncthreads();
        #pragma unroll
        for (int i=0;i<4;i++) {
            int r = lr0 + 8*i;
            int t = ks*512 + t0 + r;
            size_t off = (size_t)(b*SEQ+t)*DM + hh*DH + lc4*4;
            float4 kv = *reinterpret_cast<const float4*>(g_k + off);
            float4 vv = *reinterpret_cast<const float4*>(g_v + off);
            int d0 = lc4*4;
            float e0 = EXPF(kv.x - smax[d0+0]);
            float e1 = EXPF(kv.y - smax[d0+1]);
            float e2 = EXPF(kv.z - smax[d0+2]);
            float e3 = EXPF(kv.w - smax[d0+3]);
            kt[r][d0+0] = e0; kt[r][d0+1] = e1; kt[r][d0+2] = e2; kt[r][d0+3] = e3;
            lacc.x += e0; lacc.y += e1; lacc.z += e2; lacc.w += e3;
            *reinterpret_cast<float4*>(&vt[r][d0]) = vv;
        }
        __syncthreads();
        #pragma unroll
        for (int kk=0; kk<32; kk++) {
            float a[8], bb[8];
            *reinterpret_cast<float4*>(&a[0])  = *reinterpret_cast<const float4*>(&kt[kk][ty*8]);
            *reinterpret_cast<float4*>(&a[4])  = *reinterpret_cast<const float4*>(&kt[kk][ty*8+4]);
            *reinterpret_cast<float4*>(&bb[0]) = *reinterpret_cast<const float4*>(&vt[kk][tx*8]);
            *reinterpret_cast<float4*>(&bb[4]) = *reinterpret_cast<const float4*>(&vt[kk][tx*8+4]);
            #pragma unroll
            for (int i=0;i<8;i++)
                #pragma unroll
                for (int j=0;j<8;j++)
                    acc[i][j] = fmaf(a[i], bb[j], acc[i][j]);
        }
    }
    __syncthreads();
    *reinterpret_cast<float4*>(&kt[lr0][lc4*4]) = lacc;
    __syncthreads();
    if (threadIdx.x < DH) {
        float s = 0.f;
        #pragma unroll
        for (int j=0;j<8;j++) s += kt[j][threadIdx.x];
        g_lsep[(bh*8 + ks)*DH + threadIdx.x] = s;
    }
    float* op = g_ctxp + ((size_t)bh*8 + ks)*DH*DH;
    #pragma unroll
    for (int i=0;i<8;i++)
        #pragma unroll
        for (int j=0;j<8;j+=4) {
            float4 o4 = make_float4(acc[i][j],acc[i][j+1],acc[i][j+2],acc[i][j+3]);
            *reinterpret_cast<float4*>(op + (size_t)(ty*8+i)*DH + tx*8 + j) = o4;
        }
}

// ---------------- ctx reduce + normalize by lse ------------------------------
__global__ void ctx_reduce_kernel() {
    int idx = blockIdx.x*256 + threadIdx.x;
    if (idx >= BSZ*3*DH*DH) return;
    int bh = idx / (DH*DH);
    int de = idx - bh*DH*DH;
    int d = de >> 7;
    float s = 0.f, ls = 0.f;
    #pragma unroll
    for (int ks=0;ks<8;ks++) {
        s  += g_ctxp[((size_t)bh*8+ks)*DH*DH + de];
        ls += g_lsep[(bh*8+ks)*DH + d];
    }
    g_ctx[idx] = s / ls;
}

// ---------------- linear-attn output -> fp16 ---------------------------------
__global__ __launch_bounds__(256) void lin_out_kernel() {
    __shared__ float sctx[64][DH];
    int bh = blockIdx.x;
    int b = bh/3, hh = bh%3 + 1;
    int warp = threadIdx.x >> 5, lane = threadIdx.x & 31;
    const float* ctxp = g_ctx + (size_t)bh*DH*DH;
    float pr[4][4], o[4][4];
    int tbase = blockIdx.y*32 + warp*4;
    #pragma unroll
    for (int tt=0;tt<4;tt++) {
        int t = tbase + tt;
        const float* qp = g_q + (size_t)(b*SEQ+t)*DM + hh*DH;
        float4 q4 = *reinterpret_cast<const float4*>(qp + lane*4);
        float mx = fmaxf(fmaxf(q4.x,q4.y),fmaxf(q4.z,q4.w));
        #pragma unroll
        for (int s=16;s;s>>=1) mx = fmaxf(mx, __shfl_xor_sync(~0u,mx,s));
        float e0=EXPF(q4.x-mx), e1=EXPF(q4.y-mx), e2=EXPF(q4.z-mx), e3=EXPF(q4.w-mx);
        float sm = e0+e1+e2+e3;
        #pragma unroll
        for (int s=16;s;s>>=1) sm += __shfl_xor_sync(~0u,sm,s);
        float inv = SCALE/sm;
        pr[tt][0]=e0*inv; pr[tt][1]=e1*inv; pr[tt][2]=e2*inv; pr[tt][3]=e3*inv;
        o[tt][0]=0.f; o[tt][1]=0.f; o[tt][2]=0.f; o[tt][3]=0.f;
    }
    for (int ph=0; ph<2; ph++) {
        __syncthreads();
        #pragma unroll
        for (int i=0;i<8;i++) {
            int idx = i*256 + threadIdx.x;
            int r = idx >> 5, c4 = idx & 31;
            *reinterpret_cast<float4*>(&sctx[r][c4*4]) =
                *reinterpret_cast<const float4*>(ctxp + (size_t)(ph*64+r)*DH + c4*4);
        }
        __syncthreads();
        #pragma unroll
        for (int dl=0; dl<16; dl++) {
            int src = ph*16 + dl;
            #pragma unroll
            for (int tt=0;tt<4;tt++) {
                float b0 = __shfl_sync(~0u, pr[tt][0], src);
                float b1 = __shfl_sync(~0u, pr[tt][1], src);
                float b2 = __shfl_sync(~0u, pr[tt][2], src);
                float b3 = __shfl_sync(~0u, pr[tt][3], src);
                float4 c0 = *reinterpret_cast<const float4*>(&sctx[dl*4+0][lane*4]);
                float4 c1 = *reinterpret_cast<const float4*>(&sctx[dl*4+1][lane*4]);
                float4 c2 = *reinterpret_cast<const float4*>(&sctx[dl*4+2][lane*4]);
                float4 c3 = *reinterpret_cast<const float4*>(&sctx[dl*4+3][lane*4]);
                o[tt][0] += b0*c0.x + b1*c1.x + b2*c2.x + b3*c3.x;
                o[tt][1] += b0*c0.y + b1*c1.y + b2*c2.y + b3*c3.y;
                o[tt][2] += b0*c0.z + b1*c1.z + b2*c2.z + b3*c3.z;
                o[tt][3] += b0*c0.w + b1*c1.w + b2*c2.w + b3*c3.w;
            }
        }
    }
    #pragma unroll
    for (int tt=0;tt<4;tt++) {
        int t = tbase + tt;
        uint2 hv;
        hv.x = pack2h(o[tt][0], o[tt][1]);
        hv.y = pack2h(o[tt][2], o[tt][3]);
        *reinterpret_cast<uint2*>(g_sh + (size_t)(b*SEQ+t)*DM + hh*DH + lane*4) = hv;
    }
}

// ---------------- host ---------------------------------------------------
static inline void tc_gemm(cudaStream_t st, const fp16* A, const fp16* B,
                           const float* bias, const float* res,
                           float* C, float* Ck, float* Cv, fp16* Ch,
                           int N, int K, int act, int omul = SEQ) {
    dim3 grid((N + 127) / 128, BSZ*MTPB);
    tc_gemm_kernel<<<grid, 256, GEMM_SMEM, st>>>(A, B, bias, res, C, Ck, Cv, Ch,
                                                 N, K, act, omul);
}

extern "C" void kernel_launch(void* const* d_in, const int* in_sizes, int n_in,
                              void* d_out, int out_size) {
    const float* x    = (const float*)d_in[0];
    const float* W1   = (const float*)d_in[1];
    const float* b1   = (const float*)d_in[2];
    const float* ln1g = (const float*)d_in[3];
    const float* ln1b = (const float*)d_in[4];
    const float* Wq   = (const float*)d_in[5];
    const float* Wk   = (const float*)d_in[6];
    const float* Wv   = (const float*)d_in[7];
    const float* Wo   = (const float*)d_in[8];
    const float* bo   = (const float*)d_in[9];
    const float* ln2g = (const float*)d_in[10];
    const float* ln2b = (const float*)d_in[11];
    const float* Wf1  = (const float*)d_in[12];
    const float* bf1  = (const float*)d_in[13];
    const float* Wf2  = (const float*)d_in[14];
    const float* bf2  = (const float*)d_in[15];
    const float* W2   = (const float*)d_in[16];
    const float* b2   = (const float*)d_in[17];
    float* out = (float*)d_out;

    static int init_done = 0;
    static cudaStream_t st1, st2;
    static cudaEvent_t evStart, evT1, evQKV, evPad, evLin;
    if (!init_done) {
        cudaFuncSetAttribute(tc_gemm_kernel, cudaFuncAttributeMaxDynamicSharedMemorySize, GEMM_SMEM);
        cudaFuncSetAttribute(local_attn_kernel, cudaFuncAttributeMaxDynamicSharedMemorySize, LA_SMEM);
        cudaStreamCreateWithFlags(&st1, cudaStreamNonBlocking);
        cudaStreamCreateWithFlags(&st2, cudaStreamNonBlocking);
        cudaEventCreateWithFlags(&evStart, cudaEventDisableTiming);
        cudaEventCreateWithFlags(&evT1,    cudaEventDisableTiming);
        cudaEventCreateWithFlags(&evQKV,   cudaEventDisableTiming);
        cudaEventCreateWithFlags(&evPad,   cudaEventDisableTiming);
        cudaEventCreateWithFlags(&evLin,   cudaEventDisableTiming);
        init_done = 1;
    }

    float *h,*q,*k,*v;
    fp16 *sh,*s2h;
    fp16 *w1h,*wqkv,*woh,*wf1h,*wf2h,*w2h;
    cudaGetSymbolAddress((void**)&h,    g_h);
    cudaGetSymbolAddress((void**)&q,    g_q);
    cudaGetSymbolAddress((void**)&k,    g_k);
    cudaGetSymbolAddress((void**)&v,    g_v);
    cudaGetSymbolAddress((void**)&sh,   g_sh);
    cudaGetSymbolAddress((void**)&s2h,  g_s2h);
    cudaGetSymbolAddress((void**)&w1h,  g_w1h);
    cudaGetSymbolAddress((void**)&wqkv, g_wqkv);
    cudaGetSymbolAddress((void**)&woh,  g_woh);
    cudaGetSymbolAddress((void**)&wf1h, g_wf1h);
    cudaGetSymbolAddress((void**)&wf2h, g_wf2h);
    cudaGetSymbolAddress((void**)&w2h,  g_w2h);

    dim3 tb(32, 8);

    // fork: pad-row chain (st2) and weight transposes (st1)
    cudaEventRecord(evStart, 0);
    cudaStreamWaitEvent(st2, evStart, 0);
    pad_ln_kernel<<<1, 512, 0, st2>>>(b1, ln1g, ln1b);
    pad_kv_kernel<<<4, 256, 0, st2>>>(Wk, Wv);
    padfill_kernel<<<(BSZ*(SEQ-NTOK)*(DM/4) + 255)/256, 256, 0, st2>>>();
    cudaEventRecord(evPad, st2);

    cudaStreamWaitEvent(st1, evStart, 0);
    transpose_h_kernel<<<dim3(DM/32,  DM/32),  tb, 0, st1>>>(Wq,  wqkv,            DM,  DM);
    transpose_h_kernel<<<dim3(DM/32,  DM/32),  tb, 0, st1>>>(Wk,  wqkv + DM*DM,    DM,  DM);
    transpose_h_kernel<<<dim3(DM/32,  DM/32),  tb, 0, st1>>>(Wv,  wqkv + 2*DM*DM,  DM,  DM);
    transpose_h_kernel<<<dim3(DM/32,  DM/32),  tb, 0, st1>>>(Wo,  woh,  DM,  DM);
    transpose_h_kernel<<<dim3(DFF/32, DM/32),  tb, 0, st1>>>(Wf1, wf1h, DM,  DFF);
    transpose_h_kernel<<<dim3(DM/32,  DFF/32), tb, 0, st1>>>(Wf2, wf2h, DFF, DM);
    transpose_h_kernel<<<dim3(DOUT/32,DM/32),  tb, 0, st1>>>(W2,  w2h,  DM,  DOUT);
    cudaEventRecord(evT1, st1);

    // main stream
    transpose_h_kernel<<<dim3(DM/32, DIN/32), tb>>>(W1, w1h, DIN, DM);
    pad_split_kernel<<<(BSZ*NTOK*(DIN/4) + 255)/256, 256>>>(x);
    tc_gemm(0, sh, w1h, b1, nullptr, h, nullptr, nullptr, nullptr, DM, DIN, 1);
    ln_kernel<<<BSZ*NTOK/8, 256>>>(h, ln1g, ln1b);
    cudaStreamWaitEvent(0, evT1, 0);
    tc_gemm(0, sh, wqkv, nullptr, nullptr, q, k, v, nullptr, 3*DM, DM, 0);
    cudaEventRecord(evQKV, 0);

    // linear-attn chain on st1, local attention on main stream
    cudaStreamWaitEvent(st1, evQKV, 0);
    cudaStreamWaitEvent(st1, evPad, 0);
    kmax_kernel<<<dim3(BSZ*3,4), dim3(32,8), 0, st1>>>();
    ctx_partial_kernel<<<dim3(BSZ*3,8), 256, 0, st1>>>();
    ctx_reduce_kernel<<<(BSZ*3*DH*DH + 255)/256, 256, 0, st1>>>();
    lin_out_kernel<<<dim3(BSZ*3, 94), 256, 0, st1>>>();
    cudaEventRecord(evLin, st1);

    cudaStreamWaitEvent(0, evPad, 0);
    local_attn_kernel<<<BSZ*QBPB, 1024, LA_SMEM>>>();
    cudaStreamWaitEvent(0, evLin, 0);

    // tail on main stream
    tc_gemm(0, sh, woh, bo, h, h, nullptr, nullptr, nullptr, DM, DM, 0);
    ln_kernel<<<BSZ*NTOK/8, 256>>>(h, ln2g, ln2b);
    tc_gemm(0, sh, wf1h, bf1, nullptr, nullptr, nullptr, nullptr, s2h, DFF, DM, 2);
    tc_gemm(0, s2h, wf2h, bf2, h, nullptr, nullptr, nullptr, sh, DM, DFF, 0);
    tc_gemm(0, sh, w2h, b2, nullptr, out, nullptr, nullptr, nullptr, DOUT, DM, 0, NTOK);
}

// round 13
// speedup vs baseline: 1.1680x; 1.0347x over previous
#include <cuda_runtime.h>
#include <cuda_fp16.h>
#include <math.h>
#include <stdint.h>

#define BSZ   8
#define SEQ   4096
#define NTOK  3000
#define DIN   128
#define DM    512
#define DFF   2048
#define DOUT  64
#define DH    128
#define MTOT  (BSZ*SEQ)
#define MTPB  24                     // M-tiles per batch: ceil(3000/128)
#define QBPB  47                     // query blocks per batch: ceil(3000/64)
#define KSPL  32                     // linear-attn K splits
#define SCALE 0.08838834764831845f   // 1/sqrt(128)
#define GEMM_SMEM (3*32768)
#define LA_SMEM   114688

typedef __half fp16;

// ---------------- scratch (static device globals: no allocation) -------------
__device__ float g_h[MTOT*DM];
__device__ float g_q[MTOT*DM];
__device__ float g_k[MTOT*DM];
__device__ float g_v[MTOT*DM];
__device__ float g_kmax[BSZ*3*DH];
__device__ float g_lsep[BSZ*3*KSPL*DH];
__device__ float g_ctxp[(size_t)BSZ*3*KSPL*DH*DH];
__device__ float g_ctx[BSZ*3*DH*DH];
__device__ float g_lnpad[DM];
__device__ float g_kpad[DM];
__device__ float g_vpad[DM];
// fp16 activation buffers
__device__ fp16 g_sh[MTOT*DM];
__device__ fp16 g_s2h[MTOT*DFF];
// transposed weights [N][K], fp16
__device__ fp16 g_w1h[DM*DIN];
__device__ fp16 g_wqkv[3*DM*DM];
__device__ fp16 g_woh[DM*DM];
__device__ fp16 g_wf1h[DFF*DM];
__device__ fp16 g_wf2h[DM*DFF];
__device__ fp16 g_w2h[DOUT*DM];

// ---------------- helpers ----------------
__device__ __forceinline__ uint32_t smem_u32(const void* p) {
    uint32_t a;
    asm("{ .reg .u64 t; cvta.to.shared.u64 t, %1; cvt.u32.u64 %0, t; }" : "=r"(a) : "l"(p));
    return a;
}
__device__ __forceinline__ uint32_t pack2h(float x, float y) {
    __half2 h = __floats2half2_rn(x, y);
    return *reinterpret_cast<uint32_t*>(&h);
}
// fast exp for x <= 0 on the FMA pipe. rel err ~1e-7.
__device__ __forceinline__ float fexp(float x) {
    x = fmaxf(x, -87.0f);
    float t = x * 1.4426950408889634f;
    float fn = rintf(t);
    float r = t - fn;
    float p =            1.5403530394e-4f;
    p = fmaf(p, r, 1.3333558146e-3f);
    p = fmaf(p, r, 9.6181291076e-3f);
    p = fmaf(p, r, 5.5504108665e-2f);
    p = fmaf(p, r, 2.4022650696e-1f);
    p = fmaf(p, r, 6.9314718056e-1f);
    p = fmaf(p, r, 1.0f);
    return __int_as_float(__float_as_int(p) + (((int)fn) << 23));
}
#define EXPF(x) fexp(x)

#define LDSM_X4(r0,r1,r2,r3,addr) \
    asm volatile("ldmatrix.sync.aligned.m8n8.x4.shared.b16 {%0,%1,%2,%3}, [%4];" \
        : "=r"(r0),"=r"(r1),"=r"(r2),"=r"(r3) : "r"(addr))
#define MMA16816(d, a0,a1,a2,a3, b0,b1) \
    asm volatile("mma.sync.aligned.m16n8k16.row.col.f32.f16.f16.f32 " \
        "{%0,%1,%2,%3},{%4,%5,%6,%7},{%8,%9},{%0,%1,%2,%3};" \
        : "+f"((d)[0]),"+f"((d)[1]),"+f"((d)[2]),"+f"((d)[3]) \
        : "r"(a0),"r"(a1),"r"(a2),"r"(a3),"r"(b0),"r"(b1))
#define CP_ASYNC16(dst, src, sz) \
    asm volatile("cp.async.cg.shared.global [%0], [%1], 16, %2;" :: "r"(dst), "l"(src), "r"(sz))
#define CP_COMMIT()  asm volatile("cp.async.commit_group;" ::: "memory")
#define CP_WAIT0()   asm volatile("cp.async.wait_group 0;" ::: "memory")
#define CP_WAIT1()   asm volatile("cp.async.wait_group 1;" ::: "memory")

// ---------------- weight transpose + fp16: T[n][k] = h(W[k][n]) --------------
__global__ void transpose_h_kernel(const float* __restrict__ W,
                                   fp16* __restrict__ Th, int K, int N) {
    __shared__ float t[32][33];
    int bx = blockIdx.x * 32, by = blockIdx.y * 32;
    int x = bx + threadIdx.x;
    #pragma unroll
    for (int i = 0; i < 32; i += 8) {
        int y = by + threadIdx.y + i;
        if (x < N && y < K) t[threadIdx.y + i][threadIdx.x] = W[(size_t)y * N + x];
    }
    __syncthreads();
    int xk = by + threadIdx.x;
    #pragma unroll
    for (int i = 0; i < 32; i += 8) {
        int yn = bx + threadIdx.y + i;
        if (xk < K && yn < N)
            Th[(size_t)yn * K + xk] = __float2half_rn(t[threadIdx.x][threadIdx.y + i]);
    }
}

// ---------------- x (real rows only) -> g_sh fp16 ----------------------------
__global__ void pad_split_kernel(const float* __restrict__ x) {
    int idx = blockIdx.x*256 + threadIdx.x;
    const int total = BSZ*NTOK*(DIN/4);
    if (idx >= total) return;
    int rr = idx >> 5;
    int c4 = idx & 31;
    int b = rr / NTOK, t = rr - b*NTOK;
    float4 val = reinterpret_cast<const float4*>(x)[(size_t)rr*32 + c4];
    uint2 hv;
    hv.x = pack2h(val.x, val.y);
    hv.y = pack2h(val.z, val.w);
    *reinterpret_cast<uint2*>(g_sh + (size_t)(b*SEQ + t)*DIN + c4*4) = hv;
}

// ---------------- pad-row LN: lnpad = LN(tanh(b1)) ---------------------------
__global__ void pad_ln_kernel(const float* __restrict__ b1, const float* __restrict__ gam,
                              const float* __restrict__ bet) {
    __shared__ float ss[16], ss2[16], stat[2];
    int t = threadIdx.x;
    float h = tanhf(b1[t]);
    float s = h, s2 = h*h;
    #pragma unroll
    for (int o=16;o;o>>=1) { s += __shfl_xor_sync(~0u,s,o); s2 += __shfl_xor_sync(~0u,s2,o); }
    if ((t & 31) == 0) { ss[t>>5] = s; ss2[t>>5] = s2; }
    __syncthreads();
    if (t == 0) {
        float S=0.f, S2=0.f;
        #pragma unroll
        for (int i=0;i<16;i++) { S += ss[i]; S2 += ss2[i]; }
        float mu = S*(1.f/512.f);
        float var = S2*(1.f/512.f) - mu*mu;
        stat[0] = mu; stat[1] = rsqrtf(var + 1e-5f);
    }
    __syncthreads();
    g_lnpad[t] = (h - stat[0])*stat[1]*gam[t] + bet[t];
}

// ---------------- pad-row k/v ------------------------------------------------
__global__ void pad_kv_kernel(const float* __restrict__ Wk, const float* __restrict__ Wv) {
    int d = blockIdx.x*256 + threadIdx.x;
    if (d >= 2*DM) return;
    const float* W = (d < DM) ? Wk : Wv;
    int dd = d & (DM-1);
    float s = 0.f;
    for (int kk = 0; kk < DM; kk++) s += g_lnpad[kk] * W[(size_t)kk*DM + dd];
    if (d < DM) g_kpad[dd] = s; else g_vpad[dd] = s;
}

// ---------------- broadcast pad k/v rows -------------------------------------
__global__ void padfill_kernel() {
    int idx = blockIdx.x*256 + threadIdx.x;
    const int per = (SEQ-NTOK)*(DM/4);
    if (idx >= BSZ*per) return;
    int b = idx / per, r = idx - b*per;
    int t = NTOK + r/(DM/4), c4 = r % (DM/4);
    size_t off = (size_t)(b*SEQ + t)*DM + c4*4;
    *reinterpret_cast<float4*>(g_k + off) = *reinterpret_cast<const float4*>(g_kpad + c4*4);
    *reinterpret_cast<float4*>(g_v + off) = *reinterpret_cast<const float4*>(g_vpad + c4*4);
}

// ---------------- fp16 tensor-core GEMM, K-chunk 64 (real rows) --------------
__global__ __launch_bounds__(256, 2) void tc_gemm_kernel(
    const fp16* __restrict__ A, const fp16* __restrict__ B,
    const float* __restrict__ bias, const float* __restrict__ res,
    float* __restrict__ C, float* __restrict__ Ck, float* __restrict__ Cv,
    fp16* __restrict__ Ch,
    int N, int K, int act, int omul)
{
    extern __shared__ __align__(1024) char smc[];
    uint32_t sbase = smem_u32(smc);
    int tid = threadIdx.x;
    int mtile = blockIdx.y;
    int bb = mtile / MTPB, t0 = (mtile - bb*MTPB) << 7;
    int bm = bb*SEQ + t0;
    int alim = NTOK - t0;
    int rowlim = bm + alim;
    int odelta = bb*(omul - SEQ);
    int bn = blockIdx.x << 7;
    int lane = tid & 31, w = tid >> 5;
    int wm = w & 1, wn = w >> 1;
    int grp = lane >> 2, qp = lane & 3;

    uint32_t swz = (lane >> 1) & 3;
    uint32_t a_base = (uint32_t)(wm*64 + (lane & 15))*64 + (((uint32_t)(lane >> 4) ^ swz) << 4);
    uint32_t b_base = (uint32_t)(wn*32 + ((lane >> 4) & 1)*8 + (lane & 7))*64
                    + ((((uint32_t)(lane >> 3) & 1) ^ swz) << 4);

    float acc[4][4][4];
    #pragma unroll
    for (int i=0;i<4;i++)
        #pragma unroll
        for (int j=0;j<4;j++)
            #pragma unroll
            for (int r=0;r<4;r++) acc[i][j][r] = 0.f;

    const int NC = K >> 6;

    #define STAGE_LOAD(c_, buf_) do { \
        uint32_t sb = sbase + (uint32_t)(buf_)*32768u; \
        _Pragma("unroll") \
        for (int i_ = 0; i_ < 8; i_++) { \
            const int sub_ = i_ >> 2; \
            const int arr_ = (i_ >> 1) & 1; \
            int j_ = ((i_ & 1) << 8) + tid; \
            int r_ = j_ >> 2, cc_ = j_ & 3; \
            int k0 = ((c_) << 6) + sub_*32; \
            uint32_t dst_ = sb + (uint32_t)sub_*16384u + (uint32_t)arr_*8192u \
                          + (uint32_t)r_*64u + ((uint32_t)(cc_ ^ ((r_ >> 1) & 3)) << 4); \
            const fp16* g_; int sz_ = 16; \
            if (arr_ == 0) { \
                if (r_ < alim) g_ = A + (size_t)(bm + r_)*K + k0 + cc_*8; \
                else { g_ = A; sz_ = 0; } \
            } else { \
                int rowv_ = bn + r_; \
                if (rowv_ < N) g_ = B + (size_t)rowv_*K + k0 + cc_*8; \
                else { g_ = B; sz_ = 0; } \
            } \
            CP_ASYNC16(dst_, g_, sz_); \
        } \
        CP_COMMIT(); \
    } while (0)

    STAGE_LOAD(0, 0);
    if (NC > 1) STAGE_LOAD(1, 1);

    int buf = 0, bufn = 2;
    for (int c = 0; c < NC; c++) {
        if (c + 1 < NC) CP_WAIT1(); else CP_WAIT0();
        __syncthreads();
        if (c + 2 < NC) {
            STAGE_LOAD(c + 2, bufn);
            bufn = (bufn == 2) ? 0 : bufn + 1;
        }
        uint32_t stg = sbase + (uint32_t)buf*32768u;
        buf = (buf == 2) ? 0 : buf + 1;

        #pragma unroll
        for (int sub = 0; sub < 2; sub++) {
            uint32_t sA = stg + (uint32_t)sub*16384u;
            uint32_t sB = sA + 8192u;
            #pragma unroll
            for (int ks = 0; ks < 2; ks++) {
                uint32_t kx = ks ? 32u : 0u;
                uint32_t bh[4][2], a[4][4];
                #pragma unroll
                for (int p = 0; p < 2; p++)
                    LDSM_X4(bh[2*p][0], bh[2*p][1], bh[2*p+1][0], bh[2*p+1][1],
                            sB + ((b_base + p*1024u) ^ kx));
                #pragma unroll
                for (int mt = 0; mt < 4; mt++)
                    LDSM_X4(a[mt][0], a[mt][1], a[mt][2], a[mt][3],
                            sA + ((a_base + mt*1024u) ^ kx));
                #pragma unroll
                for (int mt = 0; mt < 4; mt++)
                    #pragma unroll
                    for (int nt = 0; nt < 4; nt++)
                        MMA16816(acc[mt][nt], a[mt][0],a[mt][1],a[mt][2],a[mt][3],
                                 bh[nt][0],bh[nt][1]);
            }
        }
    }
    #undef STAGE_LOAD

    // ---- epilogue (valid rows only) ----
    #pragma unroll
    for (int mt = 0; mt < 4; mt++) {
        #pragma unroll
        for (int nt = 0; nt < 4; nt++) {
            int c0 = bn + wn*32 + nt*8 + qp*2;
            if (c0 >= N) continue;
            int rbase = bm + wm*64 + mt*16 + grp;
            float bs0 = 0.f, bs1 = 0.f;
            if (bias) { bs0 = bias[c0]; bs1 = bias[c0 + 1]; }
            #pragma unroll
            for (int half = 0; half < 2; half++) {
                int r = rbase + half*8;
                if (r >= rowlim) continue;
                float v0 = acc[mt][nt][half*2 + 0] + bs0;
                float v1 = acc[mt][nt][half*2 + 1] + bs1;
                if (act == 1) { v0 = tanhf(v0); v1 = tanhf(v1); }
                else if (act == 2) {
                    v0 = 0.5f*v0*(1.f + erff(v0*0.7071067811865476f));
                    v1 = 0.5f*v1*(1.f + erff(v1*0.7071067811865476f));
                }
                if (res) {
                    v0 += res[(size_t)r*N + c0];
                    v1 += res[(size_t)r*N + c0 + 1];
                }
                size_t orow = (size_t)(r + odelta);
                if (Ck) {
                    float* dst; int cc;
                    if (c0 < 512)       { dst = C;  cc = c0; }
                    else if (c0 < 1024) { dst = Ck; cc = c0 - 512; }
                    else                { dst = Cv; cc = c0 - 1024; }
                    float2 o; o.x = v0; o.y = v1;
                    *reinterpret_cast<float2*>(dst + orow*512 + cc) = o;
                } else if (Ch) {
                    *reinterpret_cast<uint32_t*>(Ch + orow*N + c0) = pack2h(v0, v1);
                } else {
                    float2 o; o.x = v0; o.y = v1;
                    *reinterpret_cast<float2*>(C + orow*N + c0) = o;
                }
            }
        }
    }
}

// ---------------- LayerNorm (real rows) -> fp16 ------------------------------
__global__ void ln_kernel(const float* __restrict__ in, const float* __restrict__ gam,
                          const float* __restrict__ bet) {
    int gw = (blockIdx.x*blockDim.x + threadIdx.x) >> 5;
    int lane = threadIdx.x & 31;
    if (gw >= BSZ*NTOK) return;
    int b = gw / NTOK, t = gw - b*NTOK;
    size_t row = (size_t)(b*SEQ + t);
    const float4* rp = reinterpret_cast<const float4*>(in + row*DM);
    float4 v[4];
    float s=0.f, s2=0.f;
    #pragma unroll
    for (int i=0;i<4;i++) {
        v[i] = rp[lane + 32*i];
        s  += v[i].x+v[i].y+v[i].z+v[i].w;
        s2 += v[i].x*v[i].x + v[i].y*v[i].y + v[i].z*v[i].z + v[i].w*v[i].w;
    }
    #pragma unroll
    for (int o=16;o;o>>=1) { s += __shfl_xor_sync(~0u,s,o); s2 += __shfl_xor_sync(~0u,s2,o); }
    float mu  = s*(1.f/512.f);
    float var = s2*(1.f/512.f) - mu*mu;
    float r = rsqrtf(var + 1e-5f);
    #pragma unroll
    for (int i=0;i<4;i++) {
        int c = (lane + 32*i)*4;
        float4 g4 = *reinterpret_cast<const float4*>(gam + c);
        float4 b4 = *reinterpret_cast<const float4*>(bet + c);
        uint2 hv;
        hv.x = pack2h((v[i].x-mu)*r*g4.x + b4.x, (v[i].y-mu)*r*g4.y + b4.y);
        hv.y = pack2h((v[i].z-mu)*r*g4.z + b4.z, (v[i].w-mu)*r*g4.w + b4.w);
        *reinterpret_cast<uint2*>(g_sh + row*DM + c) = hv;
    }
}

// ---------------- local attention, head 0: 2 queries/warp, K+V co-resident ---
__global__ __launch_bounds__(1024) void local_attn_kernel() {
    extern __shared__ float dyn[];
    float* kt = dyn;
    float* vt = dyn + 8192;
    float* qs = dyn + 16384;
    float* sc = dyn + 24576;
    int b   = blockIdx.x / QBPB;
    int blk = blockIdx.x - b*QBPB;
    int qbase = blk*64;
    int win = qbase >> 7;
    int warp = threadIdx.x >> 5, lane = threadIdx.x & 31;
    int qt0 = qbase + warp, qt1 = qbase + warp + 32;
    size_t qoff0 = (size_t)(b*SEQ + qt0)*DM;
    size_t qoff1 = (size_t)(b*SEQ + qt1)*DM;
    {
        *reinterpret_cast<float4*>(qs + warp*128 + lane*4) =
            *reinterpret_cast<const float4*>(g_q + qoff0 + lane*4);
        *reinterpret_cast<float4*>(qs + (warp+32)*128 + lane*4) =
            *reinterpret_cast<const float4*>(g_q + qoff1 + lane*4);
    }
    float m0 = -1e30f, l0 = 0.f, m1 = -1e30f, l1 = 0.f;
    float4 acc0 = make_float4(0.f,0.f,0.f,0.f);
    float4 acc1 = make_float4(0.f,0.f,0.f,0.f);
    int kbase = win*128 - 128;
    for (int ch=0; ch<6; ch++) {
        int t0 = kbase + ch*64;
        __syncthreads();
        #pragma unroll
        for (int it=0; it<4; it++) {
            int idx = (it & 1)*1024 + threadIdx.x;
            int r = idx >> 5, c4 = idx & 31;
            int t = t0 + r;
            float* dst = (it < 2) ? kt : vt;
            const float* src = (it < 2) ? g_k : g_v;
            float4 val = make_float4(0.f,0.f,0.f,0.f);
            if (t >= 0 && t < SEQ)
                val = *reinterpret_cast<const float4*>(src + (size_t)(b*SEQ+t)*DM + c4*4);
            *reinterpret_cast<float4*>(dst + r*128 + c4*4) = val;
        }
        __syncthreads();
        float s00 = 0.f, s01 = 0.f, s10 = 0.f, s11 = 0.f;
        const float* qa = qs + warp*128;
        const float* qb = qs + (warp+32)*128;
        #pragma unroll
        for (int it=0; it<32; it++) {
            int d4 = ((it + lane) & 31)*4;
            float4 q0 = *reinterpret_cast<const float4*>(qa + d4);
            float4 q1 = *reinterpret_cast<const float4*>(qb + d4);
            float4 k0 = *reinterpret_cast<const float4*>(kt + lane*128 + d4);
            float4 k1 = *reinterpret_cast<const float4*>(kt + (lane+32)*128 + d4);
            s00 = fmaf(q0.x,k0.x, fmaf(q0.y,k0.y, fmaf(q0.z,k0.z, fmaf(q0.w,k0.w, s00))));
            s01 = fmaf(q0.x,k1.x, fmaf(q0.y,k1.y, fmaf(q0.z,k1.z, fmaf(q0.w,k1.w, s01))));
            s10 = fmaf(q1.x,k0.x, fmaf(q1.y,k0.y, fmaf(q1.z,k0.z, fmaf(q1.w,k0.w, s10))));
            s11 = fmaf(q1.x,k1.x, fmaf(q1.y,k1.y, fmaf(q1.z,k1.z, fmaf(q1.w,k1.w, s11))));
        }
        {
            int ta = t0 + lane, tb = t0 + lane + 32;
            bool va = (ta >= 0 && ta < SEQ), vb = (tb >= 0 && tb < SEQ);
            s00 = va ? s00*SCALE : -1e38f;
            s01 = vb ? s01*SCALE : -1e38f;
            s10 = va ? s10*SCALE : -1e38f;
            s11 = vb ? s11*SCALE : -1e38f;
        }
        float cm0 = fmaxf(s00, s01), cm1 = fmaxf(s10, s11);
        #pragma unroll
        for (int o=16;o;o>>=1) {
            cm0 = fmaxf(cm0, __shfl_xor_sync(~0u,cm0,o));
            cm1 = fmaxf(cm1, __shfl_xor_sync(~0u,cm1,o));
        }
        float mn0 = fmaxf(m0, cm0), mn1 = fmaxf(m1, cm1);
        float c0 = EXPF(m0 - mn0), c1 = EXPF(m1 - mn1);
        l0 *= c0; acc0.x*=c0; acc0.y*=c0; acc0.z*=c0; acc0.w*=c0;
        l1 *= c1; acc1.x*=c1; acc1.y*=c1; acc1.z*=c1; acc1.w*=c1;
        float p00 = EXPF(s00 - mn0), p01 = EXPF(s01 - mn0);
        float p10 = EXPF(s10 - mn1), p11 = EXPF(s11 - mn1);
        l0 += p00 + p01; l1 += p10 + p11;
        sc[warp*64 + lane]        = p00;
        sc[warp*64 + lane + 32]   = p01;
        sc[(warp+32)*64 + lane]      = p10;
        sc[(warp+32)*64 + lane + 32] = p11;
        __syncwarp();
        for (int j=0; j<64; j++) {
            float p0 = sc[warp*64 + j];
            float p1 = sc[(warp+32)*64 + j];
            float4 vv = *reinterpret_cast<const float4*>(vt + j*128 + lane*4);
            acc0.x = fmaf(p0, vv.x, acc0.x);
            acc0.y = fmaf(p0, vv.y, acc0.y);
            acc0.z = fmaf(p0, vv.z, acc0.z);
            acc0.w = fmaf(p0, vv.w, acc0.w);
            acc1.x = fmaf(p1, vv.x, acc1.x);
            acc1.y = fmaf(p1, vv.y, acc1.y);
            acc1.z = fmaf(p1, vv.z, acc1.z);
            acc1.w = fmaf(p1, vv.w, acc1.w);
        }
        m0 = mn0; m1 = mn1;
    }
    #pragma unroll
    for (int o=16;o;o>>=1) {
        l0 += __shfl_xor_sync(~0u,l0,o);
        l1 += __shfl_xor_sync(~0u,l1,o);
    }
    float i0 = 1.f/l0, i1 = 1.f/l1;
    uint2 hv;
    hv.x = pack2h(acc0.x*i0, acc0.y*i0);
    hv.y = pack2h(acc0.z*i0, acc0.w*i0);
    *reinterpret_cast<uint2*>(g_sh + qoff0 + lane*4) = hv;
    hv.x = pack2h(acc1.x*i1, acc1.y*i1);
    hv.y = pack2h(acc1.z*i1, acc1.w*i1);
    *reinterpret_cast<uint2*>(g_sh + qoff1 + lane*4) = hv;
}

// ---------------- k column max (heads 1..3) ----------------------------------
__global__ void kmax_kernel() {
    int bh = blockIdx.x;
    int b = bh/3, hh = bh%3 + 1;
    int d = blockIdx.y*32 + threadIdx.x;
    int ty = threadIdx.y;
    int col = hh*DH + d;
    float m = -1e30f;
    for (int t = ty; t < SEQ; t += 8)
        m = fmaxf(m, g_k[(size_t)(b*SEQ+t)*DM + col]);
    __shared__ float sm[8][32];
    sm[ty][threadIdx.x] = m;
    __syncthreads();
    if (ty == 0) {
        #pragma unroll
        for (int r=1;r<8;r++) m = fmaxf(m, sm[r][threadIdx.x]);
        g_kmax[bh*DH + d] = m;
    }
}

// ---------------- ctx partial: KSPL splits of 128 t-rows each ----------------
__global__ __launch_bounds__(256) void ctx_partial_kernel() {
    __shared__ float kt[32][132];
    __shared__ float vt[32][132];
    __shared__ float smax[DH];
    int bh = blockIdx.x, ks = blockIdx.y;
    int b = bh/3, hh = bh%3 + 1;
    if (threadIdx.x < DH)
        smax[threadIdx.x] = g_kmax[bh*DH + threadIdx.x];
    int tx = threadIdx.x & 15, ty = threadIdx.x >> 4;
    int lr0 = threadIdx.x >> 5, lc4 = threadIdx.x & 31;
    float acc[8][8];
    float4 lacc = make_float4(0.f,0.f,0.f,0.f);
    #pragma unroll
    for (int i=0;i<8;i++)
        #pragma unroll
        for (int j=0;j<8;j++) acc[i][j]=0.f;

    const int TPB = SEQ / KSPL;    // 128 t-rows per block
    for (int t0=0; t0<TPB; t0+=32) {
        __syncthreads();
        #pragma unroll
        for (int i=0;i<4;i++) {
            int r = lr0 + 8*i;
            int t = ks*TPB + t0 + r;
            size_t off = (size_t)(b*SEQ+t)*DM + hh*DH + lc4*4;
            float4 kv = *reinterpret_cast<const float4*>(g_k + off);
            float4 vv = *reinterpret_cast<const float4*>(g_v + off);
            int d0 = lc4*4;
            float e0 = EXPF(kv.x - smax[d0+0]);
            float e1 = EXPF(kv.y - smax[d0+1]);
            float e2 = EXPF(kv.z - smax[d0+2]);
            float e3 = EXPF(kv.w - smax[d0+3]);
            kt[r][d0+0] = e0; kt[r][d0+1] = e1; kt[r][d0+2] = e2; kt[r][d0+3] = e3;
            lacc.x += e0; lacc.y += e1; lacc.z += e2; lacc.w += e3;
            *reinterpret_cast<float4*>(&vt[r][d0]) = vv;
        }
        __syncthreads();
        #pragma unroll
        for (int kk=0; kk<32; kk++) {
            float a[8], bb[8];
            *reinterpret_cast<float4*>(&a[0])  = *reinterpret_cast<const float4*>(&kt[kk][ty*8]);
            *reinterpret_cast<float4*>(&a[4])  = *reinterpret_cast<const float4*>(&kt[kk][ty*8+4]);
            *reinterpret_cast<float4*>(&bb[0]) = *reinterpret_cast<const float4*>(&vt[kk][tx*8]);
            *reinterpret_cast<float4*>(&bb[4]) = *reinterpret_cast<const float4*>(&vt[kk][tx*8+4]);
            #pragma unroll
            for (int i=0;i<8;i++)
                #pragma unroll
                for (int j=0;j<8;j++)
                    acc[i][j] = fmaf(a[i], bb[j], acc[i][j]);
        }
    }
    __syncthreads();
    *reinterpret_cast<float4*>(&kt[lr0][lc4*4]) = lacc;
    __syncthreads();
    if (threadIdx.x < DH) {
        float s = 0.f;
        #pragma unroll
        for (int j=0;j<8;j++) s += kt[j][threadIdx.x];
        g_lsep[(bh*KSPL + ks)*DH + threadIdx.x] = s;
    }
    float* op = g_ctxp + ((size_t)bh*KSPL + ks)*DH*DH;
    #pragma unroll
    for (int i=0;i<8;i++)
        #pragma unroll
        for (int j=0;j<8;j+=4) {
            float4 o4 = make_float4(acc[i][j],acc[i][j+1],acc[i][j+2],acc[i][j+3]);
            *reinterpret_cast<float4*>(op + (size_t)(ty*8+i)*DH + tx*8 + j) = o4;
        }
}

// ---------------- ctx reduce + normalize by lse ------------------------------
__global__ void ctx_reduce_kernel() {
    int idx = blockIdx.x*256 + threadIdx.x;
    if (idx >= BSZ*3*DH*DH) return;
    int bh = idx / (DH*DH);
    int de = idx - bh*DH*DH;
    int d = de >> 7;
    float s = 0.f, ls = 0.f;
    #pragma unroll
    for (int ks=0;ks<KSPL;ks++) {
        s  += g_ctxp[((size_t)bh*KSPL+ks)*DH*DH + de];
        ls += g_lsep[(bh*KSPL+ks)*DH + d];
    }
    g_ctx[idx] = s / ls;
}

// ---------------- linear-attn output -> fp16 (grid.y offset for split) -------
__global__ __launch_bounds__(256) void lin_out_kernel(int ybase) {
    __shared__ float sctx[64][DH];
    int bh = blockIdx.x;
    int b = bh/3, hh = bh%3 + 1;
    int warp = threadIdx.x >> 5, lane = threadIdx.x & 31;
    const float* ctxp = g_ctx + (size_t)bh*DH*DH;
    float pr[4][4], o[4][4];
    int tbase = (ybase + blockIdx.y)*32 + warp*4;
    #pragma unroll
    for (int tt=0;tt<4;tt++) {
        int t = tbase + tt;
        const float* qp = g_q + (size_t)(b*SEQ+t)*DM + hh*DH;
        float4 q4 = *reinterpret_cast<const float4*>(qp + lane*4);
        float mx = fmaxf(fmaxf(q4.x,q4.y),fmaxf(q4.z,q4.w));
        #pragma unroll
        for (int s=16;s;s>>=1) mx = fmaxf(mx, __shfl_xor_sync(~0u,mx,s));
        float e0=EXPF(q4.x-mx), e1=EXPF(q4.y-mx), e2=EXPF(q4.z-mx), e3=EXPF(q4.w-mx);
        float sm = e0+e1+e2+e3;
        #pragma unroll
        for (int s=16;s;s>>=1) sm += __shfl_xor_sync(~0u,sm,s);
        float inv = SCALE/sm;
        pr[tt][0]=e0*inv; pr[tt][1]=e1*inv; pr[tt][2]=e2*inv; pr[tt][3]=e3*inv;
        o[tt][0]=0.f; o[tt][1]=0.f; o[tt][2]=0.f; o[tt][3]=0.f;
    }
    for (int ph=0; ph<2; ph++) {
        __syncthreads();
        #pragma unroll
        for (int i=0;i<8;i++) {
            int idx = i*256 + threadIdx.x;
            int r = idx >> 5, c4 = idx & 31;
            *reinterpret_cast<float4*>(&sctx[r][c4*4]) =
                *reinterpret_cast<const float4*>(ctxp + (size_t)(ph*64+r)*DH + c4*4);
        }
        __syncthreads();
        #pragma unroll
        for (int dl=0; dl<16; dl++) {
            int src = ph*16 + dl;
            #pragma unroll
            for (int tt=0;tt<4;tt++) {
                float b0 = __shfl_sync(~0u, pr[tt][0], src);
                float b1 = __shfl_sync(~0u, pr[tt][1], src);
                float b2 = __shfl_sync(~0u, pr[tt][2], src);
                float b3 = __shfl_sync(~0u, pr[tt][3], src);
                float4 c0 = *reinterpret_cast<const float4*>(&sctx[dl*4+0][lane*4]);
                float4 c1 = *reinterpret_cast<const float4*>(&sctx[dl*4+1][lane*4]);
                float4 c2 = *reinterpret_cast<const float4*>(&sctx[dl*4+2][lane*4]);
                float4 c3 = *reinterpret_cast<const float4*>(&sctx[dl*4+3][lane*4]);
                o[tt][0] += b0*c0.x + b1*c1.x + b2*c2.x + b3*c3.x;
                o[tt][1] += b0*c0.y + b1*c1.y + b2*c2.y + b3*c3.y;
                o[tt][2] += b0*c0.z + b1*c1.z + b2*c2.z + b3*c3.z;
                o[tt][3] += b0*c0.w + b1*c1.w + b2*c2.w + b3*c3.w;
            }
        }
    }
    #pragma unroll
    for (int tt=0;tt<4;tt++) {
        int t = tbase + tt;
        uint2 hv;
        hv.x = pack2h(o[tt][0], o[tt][1]);
        hv.y = pack2h(o[tt][2], o[tt][3]);
        *reinterpret_cast<uint2*>(g_sh + (size_t)(b*SEQ+t)*DM + hh*DH + lane*4) = hv;
    }
}

// ---------------- host ---------------------------------------------------
static inline void tc_gemm(cudaStream_t st, const fp16* A, const fp16* B,
                           const float* bias, const float* res,
                           float* C, float* Ck, float* Cv, fp16* Ch,
                           int N, int K, int act, int omul = SEQ) {
    dim3 grid((N + 127) / 128, BSZ*MTPB);
    tc_gemm_kernel<<<grid, 256, GEMM_SMEM, st>>>(A, B, bias, res, C, Ck, Cv, Ch,
                                                 N, K, act, omul);
}

extern "C" void kernel_launch(void* const* d_in, const int* in_sizes, int n_in,
                              void* d_out, int out_size) {
    const float* x    = (const float*)d_in[0];
    const float* W1   = (const float*)d_in[1];
    const float* b1   = (const float*)d_in[2];
    const float* ln1g = (const float*)d_in[3];
    const float* ln1b = (const float*)d_in[4];
    const float* Wq   = (const float*)d_in[5];
    const float* Wk   = (const float*)d_in[6];
    const float* Wv   = (const float*)d_in[7];
    const float* Wo   = (const float*)d_in[8];
    const float* bo   = (const float*)d_in[9];
    const float* ln2g = (const float*)d_in[10];
    const float* ln2b = (const float*)d_in[11];
    const float* Wf1  = (const float*)d_in[12];
    const float* bf1  = (const float*)d_in[13];
    const float* Wf2  = (const float*)d_in[14];
    const float* bf2  = (const float*)d_in[15];
    const float* W2   = (const float*)d_in[16];
    const float* b2   = (const float*)d_in[17];
    float* out = (float*)d_out;

    static int init_done = 0;
    static cudaStream_t st1, st2;
    static cudaEvent_t evStart, evT1, evQKV, evPad, evCtx, evLin;
    if (!init_done) {
        cudaFuncSetAttribute(tc_gemm_kernel, cudaFuncAttributeMaxDynamicSharedMemorySize, GEMM_SMEM);
        cudaFuncSetAttribute(local_attn_kernel, cudaFuncAttributeMaxDynamicSharedMemorySize, LA_SMEM);
        cudaStreamCreateWithFlags(&st1, cudaStreamNonBlocking);
        cudaStreamCreateWithFlags(&st2, cudaStreamNonBlocking);
        cudaEventCreateWithFlags(&evStart, cudaEventDisableTiming);
        cudaEventCreateWithFlags(&evT1,    cudaEventDisableTiming);
        cudaEventCreateWithFlags(&evQKV,   cudaEventDisableTiming);
        cudaEventCreateWithFlags(&evPad,   cudaEventDisableTiming);
        cudaEventCreateWithFlags(&evCtx,   cudaEventDisableTiming);
        cudaEventCreateWithFlags(&evLin,   cudaEventDisableTiming);
        init_done = 1;
    }

    float *h,*q,*k,*v;
    fp16 *sh,*s2h;
    fp16 *w1h,*wqkv,*woh,*wf1h,*wf2h,*w2h;
    cudaGetSymbolAddress((void**)&h,    g_h);
    cudaGetSymbolAddress((void**)&q,    g_q);
    cudaGetSymbolAddress((void**)&k,    g_k);
    cudaGetSymbolAddress((void**)&v,    g_v);
    cudaGetSymbolAddress((void**)&sh,   g_sh);
    cudaGetSymbolAddress((void**)&s2h,  g_s2h);
    cudaGetSymbolAddress((void**)&w1h,  g_w1h);
    cudaGetSymbolAddress((void**)&wqkv, g_wqkv);
    cudaGetSymbolAddress((void**)&woh,  g_woh);
    cudaGetSymbolAddress((void**)&wf1h, g_wf1h);
    cudaGetSymbolAddress((void**)&wf2h, g_wf2h);
    cudaGetSymbolAddress((void**)&w2h,  g_w2h);

    dim3 tb(32, 8);

    // fork: pad-row chain (st2) and weight transposes (st1)
    cudaEventRecord(evStart, 0);
    cudaStreamWaitEvent(st2, evStart, 0);
    pad_ln_kernel<<<1, 512, 0, st2>>>(b1, ln1g, ln1b);
    pad_kv_kernel<<<4, 256, 0, st2>>>(Wk, Wv);
    padfill_kernel<<<(BSZ*(SEQ-NTOK)*(DM/4) + 255)/256, 256, 0, st2>>>();
    cudaEventRecord(evPad, st2);

    cudaStreamWaitEvent(st1, evStart, 0);
    transpose_h_kernel<<<dim3(DM/32,  DM/32),  tb, 0, st1>>>(Wq,  wqkv,            DM,  DM);
    transpose_h_kernel<<<dim3(DM/32,  DM/32),  tb, 0, st1>>>(Wk,  wqkv + DM*DM,    DM,  DM);
    transpose_h_kernel<<<dim3(DM/32,  DM/32),  tb, 0, st1>>>(Wv,  wqkv + 2*DM*DM,  DM,  DM);
    transpose_h_kernel<<<dim3(DM/32,  DM/32),  tb, 0, st1>>>(Wo,  woh,  DM,  DM);
    transpose_h_kernel<<<dim3(DFF/32, DM/32),  tb, 0, st1>>>(Wf1, wf1h, DM,  DFF);
    transpose_h_kernel<<<dim3(DM/32,  DFF/32), tb, 0, st1>>>(Wf2, wf2h, DFF, DM);
    transpose_h_kernel<<<dim3(DOUT/32,DM/32),  tb, 0, st1>>>(W2,  w2h,  DM,  DOUT);
    cudaEventRecord(evT1, st1);

    // main stream
    transpose_h_kernel<<<dim3(DM/32, DIN/32), tb>>>(W1, w1h, DIN, DM);
    pad_split_kernel<<<(BSZ*NTOK*(DIN/4) + 255)/256, 256>>>(x);
    tc_gemm(0, sh, w1h, b1, nullptr, h, nullptr, nullptr, nullptr, DM, DIN, 1);
    ln_kernel<<<BSZ*NTOK/8, 256>>>(h, ln1g, ln1b);
    cudaStreamWaitEvent(0, evT1, 0);
    tc_gemm(0, sh, wqkv, nullptr, nullptr, q, k, v, nullptr, 3*DM, DM, 0);
    cudaEventRecord(evQKV, 0);

    // lin chain on st1 (through ctx); lin_out split across both streams
    cudaStreamWaitEvent(st1, evQKV, 0);
    cudaStreamWaitEvent(st1, evPad, 0);
    kmax_kernel<<<dim3(BSZ*3,4), dim3(32,8), 0, st1>>>();
    ctx_partial_kernel<<<dim3(BSZ*3,KSPL), 256, 0, st1>>>();
    ctx_reduce_kernel<<<(BSZ*3*DH*DH + 255)/256, 256, 0, st1>>>();
    cudaEventRecord(evCtx, st1);
    lin_out_kernel<<<dim3(BSZ*3, 47), 256, 0, st1>>>(0);
    cudaEventRecord(evLin, st1);

    cudaStreamWaitEvent(0, evPad, 0);
    local_attn_kernel<<<BSZ*QBPB, 1024, LA_SMEM>>>();
    cudaStreamWaitEvent(0, evCtx, 0);
    lin_out_kernel<<<dim3(BSZ*3, 47), 256>>>(47);
    cudaStreamWaitEvent(0, evLin, 0);

    // tail on main stream
    tc_gemm(0, sh, woh, bo, h, h, nullptr, nullptr, nullptr, DM, DM, 0);
    ln_kernel<<<BSZ*NTOK/8, 256>>>(h, ln2g, ln2b);
    tc_gemm(0, sh, wf1h, bf1, nullptr, nullptr, nullptr, nullptr, s2h, DFF, DM, 2);
    tc_gemm(0, s2h, wf2h, bf2, h, nullptr, nullptr, nullptr, sh, DM, DFF, 0);
    tc_gemm(0, sh, w2h, b2, nullptr, out, nullptr, nullptr, nullptr, DOUT, DM, 0, NTOK);
}

// round 14
// speedup vs baseline: 1.1962x; 1.0242x over previous
#include <cuda_runtime.h>
#include <cuda_fp16.h>
#include <math.h>
#include <stdint.h>

#define BSZ   8
#define SEQ   4096
#define NTOK  3000
#define DIN   128
#define DM    512
#define DFF   2048
#define DOUT  64
#define DH    128
#define MTOT  (BSZ*SEQ)
#define MTPB  24
#define QBPB  47
#define KSPL  32
#define SCALE 0.08838834764831845f
#define GEMM_SMEM (3*32768)
#define LA_SMEM   114688

typedef __half fp16;

// ---------------- scratch ----------------
__device__ float g_h[MTOT*DM];
__device__ float g_q[MTOT*DM];
__device__ float g_k[MTOT*DM];
__device__ float g_v[MTOT*DM];
__device__ float g_kmax[BSZ*3*DH];
__device__ float g_lsep[BSZ*3*KSPL*DH];
__device__ float g_ctxp[(size_t)BSZ*3*KSPL*DH*DH];
__device__ float g_ctx[BSZ*3*DH*DH];
__device__ float g_lnpad[DM];
__device__ float g_kpad[DM];
__device__ float g_vpad[DM];
__device__ fp16 g_sh[MTOT*DM];
__device__ fp16 g_s2h[MTOT*DFF];
__device__ fp16 g_w1h[DM*DIN];
__device__ fp16 g_wqkv[3*DM*DM];
__device__ fp16 g_woh[DM*DM];
__device__ fp16 g_wf1h[DFF*DM];
__device__ fp16 g_wf2h[DM*DFF];
__device__ fp16 g_w2h[DOUT*DM];

// ---------------- helpers ----------------
__device__ __forceinline__ uint32_t smem_u32(const void* p) {
    uint32_t a;
    asm("{ .reg .u64 t; cvta.to.shared.u64 t, %1; cvt.u32.u64 %0, t; }" : "=r"(a) : "l"(p));
    return a;
}
__device__ __forceinline__ uint32_t pack2h(float x, float y) {
    __half2 h = __floats2half2_rn(x, y);
    return *reinterpret_cast<uint32_t*>(&h);
}
__device__ __forceinline__ float fexp(float x) {
    x = fmaxf(x, -87.0f);
    float t = x * 1.4426950408889634f;
    float fn = rintf(t);
    float r = t - fn;
    float p =            1.5403530394e-4f;
    p = fmaf(p, r, 1.3333558146e-3f);
    p = fmaf(p, r, 9.6181291076e-3f);
    p = fmaf(p, r, 5.5504108665e-2f);
    p = fmaf(p, r, 2.4022650696e-1f);
    p = fmaf(p, r, 6.9314718056e-1f);
    p = fmaf(p, r, 1.0f);
    return __int_as_float(__float_as_int(p) + (((int)fn) << 23));
}
#define EXPF(x) fexp(x)

#define LDSM_X4(r0,r1,r2,r3,addr) \
    asm volatile("ldmatrix.sync.aligned.m8n8.x4.shared.b16 {%0,%1,%2,%3}, [%4];" \
        : "=r"(r0),"=r"(r1),"=r"(r2),"=r"(r3) : "r"(addr))
#define LDSM_X4T(r0,r1,r2,r3,addr) \
    asm volatile("ldmatrix.sync.aligned.m8n8.x4.trans.shared.b16 {%0,%1,%2,%3}, [%4];" \
        : "=r"(r0),"=r"(r1),"=r"(r2),"=r"(r3) : "r"(addr))
#define MMA16816(d, a0,a1,a2,a3, b0,b1) \
    asm volatile("mma.sync.aligned.m16n8k16.row.col.f32.f16.f16.f32 " \
        "{%0,%1,%2,%3},{%4,%5,%6,%7},{%8,%9},{%0,%1,%2,%3};" \
        : "+f"((d)[0]),"+f"((d)[1]),"+f"((d)[2]),"+f"((d)[3]) \
        : "r"(a0),"r"(a1),"r"(a2),"r"(a3),"r"(b0),"r"(b1))
#define CP_ASYNC16(dst, src, sz) \
    asm volatile("cp.async.cg.shared.global [%0], [%1], 16, %2;" :: "r"(dst), "l"(src), "r"(sz))
#define CP_COMMIT()  asm volatile("cp.async.commit_group;" ::: "memory")
#define CP_WAIT0()   asm volatile("cp.async.wait_group 0;" ::: "memory")
#define CP_WAIT1()   asm volatile("cp.async.wait_group 1;" ::: "memory")

// ---------------- weight transpose + fp16 ----------------
__global__ void transpose_h_kernel(const float* __restrict__ W,
                                   fp16* __restrict__ Th, int K, int N) {
    __shared__ float t[32][33];
    int bx = blockIdx.x * 32, by = blockIdx.y * 32;
    int x = bx + threadIdx.x;
    #pragma unroll
    for (int i = 0; i < 32; i += 8) {
        int y = by + threadIdx.y + i;
        if (x < N && y < K) t[threadIdx.y + i][threadIdx.x] = W[(size_t)y * N + x];
    }
    __syncthreads();
    int xk = by + threadIdx.x;
    #pragma unroll
    for (int i = 0; i < 32; i += 8) {
        int yn = bx + threadIdx.y + i;
        if (xk < K && yn < N)
            Th[(size_t)yn * K + xk] = __float2half_rn(t[threadIdx.x][threadIdx.y + i]);
    }
}

// ---------------- x (real rows only) -> g_sh fp16 ----------------
__global__ void pad_split_kernel(const float* __restrict__ x) {
    int idx = blockIdx.x*256 + threadIdx.x;
    const int total = BSZ*NTOK*(DIN/4);
    if (idx >= total) return;
    int rr = idx >> 5;
    int c4 = idx & 31;
    int b = rr / NTOK, t = rr - b*NTOK;
    float4 val = reinterpret_cast<const float4*>(x)[(size_t)rr*32 + c4];
    uint2 hv;
    hv.x = pack2h(val.x, val.y);
    hv.y = pack2h(val.z, val.w);
    *reinterpret_cast<uint2*>(g_sh + (size_t)(b*SEQ + t)*DIN + c4*4) = hv;
}

// ---------------- pad-row LN ----------------
__global__ void pad_ln_kernel(const float* __restrict__ b1, const float* __restrict__ gam,
                              const float* __restrict__ bet) {
    __shared__ float ss[16], ss2[16], stat[2];
    int t = threadIdx.x;
    float h = tanhf(b1[t]);
    float s = h, s2 = h*h;
    #pragma unroll
    for (int o=16;o;o>>=1) { s += __shfl_xor_sync(~0u,s,o); s2 += __shfl_xor_sync(~0u,s2,o); }
    if ((t & 31) == 0) { ss[t>>5] = s; ss2[t>>5] = s2; }
    __syncthreads();
    if (t == 0) {
        float S=0.f, S2=0.f;
        #pragma unroll
        for (int i=0;i<16;i++) { S += ss[i]; S2 += ss2[i]; }
        float mu = S*(1.f/512.f);
        float var = S2*(1.f/512.f) - mu*mu;
        stat[0] = mu; stat[1] = rsqrtf(var + 1e-5f);
    }
    __syncthreads();
    g_lnpad[t] = (h - stat[0])*stat[1]*gam[t] + bet[t];
}

// ---------------- pad-row k/v ----------------
__global__ void pad_kv_kernel(const float* __restrict__ Wk, const float* __restrict__ Wv) {
    int d = blockIdx.x*256 + threadIdx.x;
    if (d >= 2*DM) return;
    const float* W = (d < DM) ? Wk : Wv;
    int dd = d & (DM-1);
    float s = 0.f;
    for (int kk = 0; kk < DM; kk++) s += g_lnpad[kk] * W[(size_t)kk*DM + dd];
    if (d < DM) g_kpad[dd] = s; else g_vpad[dd] = s;
}

// ---------------- broadcast pad k/v rows ----------------
__global__ void padfill_kernel() {
    int idx = blockIdx.x*256 + threadIdx.x;
    const int per = (SEQ-NTOK)*(DM/4);
    if (idx >= BSZ*per) return;
    int b = idx / per, r = idx - b*per;
    int t = NTOK + r/(DM/4), c4 = r % (DM/4);
    size_t off = (size_t)(b*SEQ + t)*DM + c4*4;
    *reinterpret_cast<float4*>(g_k + off) = *reinterpret_cast<const float4*>(g_kpad + c4*4);
    *reinterpret_cast<float4*>(g_v + off) = *reinterpret_cast<const float4*>(g_vpad + c4*4);
}

// ---------------- fp16 tensor-core GEMM (unchanged) ----------------
__global__ __launch_bounds__(256, 2) void tc_gemm_kernel(
    const fp16* __restrict__ A, const fp16* __restrict__ B,
    const float* __restrict__ bias, const float* __restrict__ res,
    float* __restrict__ C, float* __restrict__ Ck, float* __restrict__ Cv,
    fp16* __restrict__ Ch,
    int N, int K, int act, int omul)
{
    extern __shared__ __align__(1024) char smc[];
    uint32_t sbase = smem_u32(smc);
    int tid = threadIdx.x;
    int mtile = blockIdx.y;
    int bb = mtile / MTPB, t0 = (mtile - bb*MTPB) << 7;
    int bm = bb*SEQ + t0;
    int alim = NTOK - t0;
    int rowlim = bm + alim;
    int odelta = bb*(omul - SEQ);
    int bn = blockIdx.x << 7;
    int lane = tid & 31, w = tid >> 5;
    int wm = w & 1, wn = w >> 1;
    int grp = lane >> 2, qp = lane & 3;

    uint32_t swz = (lane >> 1) & 3;
    uint32_t a_base = (uint32_t)(wm*64 + (lane & 15))*64 + (((uint32_t)(lane >> 4) ^ swz) << 4);
    uint32_t b_base = (uint32_t)(wn*32 + ((lane >> 4) & 1)*8 + (lane & 7))*64
                    + ((((uint32_t)(lane >> 3) & 1) ^ swz) << 4);

    float acc[4][4][4];
    #pragma unroll
    for (int i=0;i<4;i++)
        #pragma unroll
        for (int j=0;j<4;j++)
            #pragma unroll
            for (int r=0;r<4;r++) acc[i][j][r] = 0.f;

    const int NC = K >> 6;

    #define STAGE_LOAD(c_, buf_) do { \
        uint32_t sb = sbase + (uint32_t)(buf_)*32768u; \
        _Pragma("unroll") \
        for (int i_ = 0; i_ < 8; i_++) { \
            const int sub_ = i_ >> 2; \
            const int arr_ = (i_ >> 1) & 1; \
            int j_ = ((i_ & 1) << 8) + tid; \
            int r_ = j_ >> 2, cc_ = j_ & 3; \
            int k0 = ((c_) << 6) + sub_*32; \
            uint32_t dst_ = sb + (uint32_t)sub_*16384u + (uint32_t)arr_*8192u \
                          + (uint32_t)r_*64u + ((uint32_t)(cc_ ^ ((r_ >> 1) & 3)) << 4); \
            const fp16* g_; int sz_ = 16; \
            if (arr_ == 0) { \
                if (r_ < alim) g_ = A + (size_t)(bm + r_)*K + k0 + cc_*8; \
                else { g_ = A; sz_ = 0; } \
            } else { \
                int rowv_ = bn + r_; \
                if (rowv_ < N) g_ = B + (size_t)rowv_*K + k0 + cc_*8; \
                else { g_ = B; sz_ = 0; } \
            } \
            CP_ASYNC16(dst_, g_, sz_); \
        } \
        CP_COMMIT(); \
    } while (0)

    STAGE_LOAD(0, 0);
    if (NC > 1) STAGE_LOAD(1, 1);

    int buf = 0, bufn = 2;
    for (int c = 0; c < NC; c++) {
        if (c + 1 < NC) CP_WAIT1(); else CP_WAIT0();
        __syncthreads();
        if (c + 2 < NC) {
            STAGE_LOAD(c + 2, bufn);
            bufn = (bufn == 2) ? 0 : bufn + 1;
        }
        uint32_t stg = sbase + (uint32_t)buf*32768u;
        buf = (buf == 2) ? 0 : buf + 1;

        #pragma unroll
        for (int sub = 0; sub < 2; sub++) {
            uint32_t sA = stg + (uint32_t)sub*16384u;
            uint32_t sB = sA + 8192u;
            #pragma unroll
            for (int ks = 0; ks < 2; ks++) {
                uint32_t kx = ks ? 32u : 0u;
                uint32_t bh[4][2], a[4][4];
                #pragma unroll
                for (int p = 0; p < 2; p++)
                    LDSM_X4(bh[2*p][0], bh[2*p][1], bh[2*p+1][0], bh[2*p+1][1],
                            sB + ((b_base + p*1024u) ^ kx));
                #pragma unroll
                for (int mt = 0; mt < 4; mt++)
                    LDSM_X4(a[mt][0], a[mt][1], a[mt][2], a[mt][3],
                            sA + ((a_base + mt*1024u) ^ kx));
                #pragma unroll
                for (int mt = 0; mt < 4; mt++)
                    #pragma unroll
                    for (int nt = 0; nt < 4; nt++)
                        MMA16816(acc[mt][nt], a[mt][0],a[mt][1],a[mt][2],a[mt][3],
                                 bh[nt][0],bh[nt][1]);
            }
        }
    }
    #undef STAGE_LOAD

    #pragma unroll
    for (int mt = 0; mt < 4; mt++) {
        #pragma unroll
        for (int nt = 0; nt < 4; nt++) {
            int c0 = bn + wn*32 + nt*8 + qp*2;
            if (c0 >= N) continue;
            int rbase = bm + wm*64 + mt*16 + grp;
            float bs0 = 0.f, bs1 = 0.f;
            if (bias) { bs0 = bias[c0]; bs1 = bias[c0 + 1]; }
            #pragma unroll
            for (int half = 0; half < 2; half++) {
                int r = rbase + half*8;
                if (r >= rowlim) continue;
                float v0 = acc[mt][nt][half*2 + 0] + bs0;
                float v1 = acc[mt][nt][half*2 + 1] + bs1;
                if (act == 1) { v0 = tanhf(v0); v1 = tanhf(v1); }
                else if (act == 2) {
                    v0 = 0.5f*v0*(1.f + erff(v0*0.7071067811865476f));
                    v1 = 0.5f*v1*(1.f + erff(v1*0.7071067811865476f));
                }
                if (res) {
                    v0 += res[(size_t)r*N + c0];
                    v1 += res[(size_t)r*N + c0 + 1];
                }
                size_t orow = (size_t)(r + odelta);
                if (Ck) {
                    float* dst; int cc;
                    if (c0 < 512)       { dst = C;  cc = c0; }
                    else if (c0 < 1024) { dst = Ck; cc = c0 - 512; }
                    else                { dst = Cv; cc = c0 - 1024; }
                    float2 o; o.x = v0; o.y = v1;
                    *reinterpret_cast<float2*>(dst + orow*512 + cc) = o;
                } else if (Ch) {
                    *reinterpret_cast<uint32_t*>(Ch + orow*N + c0) = pack2h(v0, v1);
                } else {
                    float2 o; o.x = v0; o.y = v1;
                    *reinterpret_cast<float2*>(C + orow*N + c0) = o;
                }
            }
        }
    }
}

// ---------------- LayerNorm (real rows) -> fp16 ----------------
__global__ void ln_kernel(const float* __restrict__ in, const float* __restrict__ gam,
                          const float* __restrict__ bet) {
    int gw = (blockIdx.x*blockDim.x + threadIdx.x) >> 5;
    int lane = threadIdx.x & 31;
    if (gw >= BSZ*NTOK) return;
    int b = gw / NTOK, t = gw - b*NTOK;
    size_t row = (size_t)(b*SEQ + t);
    const float4* rp = reinterpret_cast<const float4*>(in + row*DM);
    float4 v[4];
    float s=0.f, s2=0.f;
    #pragma unroll
    for (int i=0;i<4;i++) {
        v[i] = rp[lane + 32*i];
        s  += v[i].x+v[i].y+v[i].z+v[i].w;
        s2 += v[i].x*v[i].x + v[i].y*v[i].y + v[i].z*v[i].z + v[i].w*v[i].w;
    }
    #pragma unroll
    for (int o=16;o;o>>=1) { s += __shfl_xor_sync(~0u,s,o); s2 += __shfl_xor_sync(~0u,s2,o); }
    float mu  = s*(1.f/512.f);
    float var = s2*(1.f/512.f) - mu*mu;
    float r = rsqrtf(var + 1e-5f);
    #pragma unroll
    for (int i=0;i<4;i++) {
        int c = (lane + 32*i)*4;
        float4 g4 = *reinterpret_cast<const float4*>(gam + c);
        float4 b4 = *reinterpret_cast<const float4*>(bet + c);
        uint2 hv;
        hv.x = pack2h((v[i].x-mu)*r*g4.x + b4.x, (v[i].y-mu)*r*g4.y + b4.y);
        hv.y = pack2h((v[i].z-mu)*r*g4.z + b4.z, (v[i].w-mu)*r*g4.w + b4.w);
        *reinterpret_cast<uint2*>(g_sh + row*DM + c) = hv;
    }
}

// ---------------- local attention (unchanged from R12) ----------------
__global__ __launch_bounds__(1024) void local_attn_kernel() {
    extern __shared__ float dyn[];
    float* kt = dyn;
    float* vt = dyn + 8192;
    float* qs = dyn + 16384;
    float* sc = dyn + 24576;
    int b   = blockIdx.x / QBPB;
    int blk = blockIdx.x - b*QBPB;
    int qbase = blk*64;
    int win = qbase >> 7;
    int warp = threadIdx.x >> 5, lane = threadIdx.x & 31;
    int qt0 = qbase + warp, qt1 = qbase + warp + 32;
    size_t qoff0 = (size_t)(b*SEQ + qt0)*DM;
    size_t qoff1 = (size_t)(b*SEQ + qt1)*DM;
    {
        *reinterpret_cast<float4*>(qs + warp*128 + lane*4) =
            *reinterpret_cast<const float4*>(g_q + qoff0 + lane*4);
        *reinterpret_cast<float4*>(qs + (warp+32)*128 + lane*4) =
            *reinterpret_cast<const float4*>(g_q + qoff1 + lane*4);
    }
    float m0 = -1e30f, l0 = 0.f, m1 = -1e30f, l1 = 0.f;
    float4 acc0 = make_float4(0.f,0.f,0.f,0.f);
    float4 acc1 = make_float4(0.f,0.f,0.f,0.f);
    int kbase = win*128 - 128;
    for (int ch=0; ch<6; ch++) {
        int t0 = kbase + ch*64;
        __syncthreads();
        #pragma unroll
        for (int it=0; it<4; it++) {
            int idx = (it & 1)*1024 + threadIdx.x;
            int r = idx >> 5, c4 = idx & 31;
            int t = t0 + r;
            float* dst = (it < 2) ? kt : vt;
            const float* src = (it < 2) ? g_k : g_v;
            float4 val = make_float4(0.f,0.f,0.f,0.f);
            if (t >= 0 && t < SEQ)
                val = *reinterpret_cast<const float4*>(src + (size_t)(b*SEQ+t)*DM + c4*4);
            *reinterpret_cast<float4*>(dst + r*128 + c4*4) = val;
        }
        __syncthreads();
        float s00 = 0.f, s01 = 0.f, s10 = 0.f, s11 = 0.f;
        const float* qa = qs + warp*128;
        const float* qb = qs + (warp+32)*128;
        #pragma unroll
        for (int it=0; it<32; it++) {
            int d4 = ((it + lane) & 31)*4;
            float4 q0 = *reinterpret_cast<const float4*>(qa + d4);
            float4 q1 = *reinterpret_cast<const float4*>(qb + d4);
            float4 k0 = *reinterpret_cast<const float4*>(kt + lane*128 + d4);
            float4 k1 = *reinterpret_cast<const float4*>(kt + (lane+32)*128 + d4);
            s00 = fmaf(q0.x,k0.x, fmaf(q0.y,k0.y, fmaf(q0.z,k0.z, fmaf(q0.w,k0.w, s00))));
            s01 = fmaf(q0.x,k1.x, fmaf(q0.y,k1.y, fmaf(q0.z,k1.z, fmaf(q0.w,k1.w, s01))));
            s10 = fmaf(q1.x,k0.x, fmaf(q1.y,k0.y, fmaf(q1.z,k0.z, fmaf(q1.w,k0.w, s10))));
            s11 = fmaf(q1.x,k1.x, fmaf(q1.y,k1.y, fmaf(q1.z,k1.z, fmaf(q1.w,k1.w, s11))));
        }
        {
            int ta = t0 + lane, tb = t0 + lane + 32;
            bool va = (ta >= 0 && ta < SEQ), vb = (tb >= 0 && tb < SEQ);
            s00 = va ? s00*SCALE : -1e38f;
            s01 = vb ? s01*SCALE : -1e38f;
            s10 = va ? s10*SCALE : -1e38f;
            s11 = vb ? s11*SCALE : -1e38f;
        }
        float cm0 = fmaxf(s00, s01), cm1 = fmaxf(s10, s11);
        #pragma unroll
        for (int o=16;o;o>>=1) {
            cm0 = fmaxf(cm0, __shfl_xor_sync(~0u,cm0,o));
            cm1 = fmaxf(cm1, __shfl_xor_sync(~0u,cm1,o));
        }
        float mn0 = fmaxf(m0, cm0), mn1 = fmaxf(m1, cm1);
        float c0 = EXPF(m0 - mn0), c1 = EXPF(m1 - mn1);
        l0 *= c0; acc0.x*=c0; acc0.y*=c0; acc0.z*=c0; acc0.w*=c0;
        l1 *= c1; acc1.x*=c1; acc1.y*=c1; acc1.z*=c1; acc1.w*=c1;
        float p00 = EXPF(s00 - mn0), p01 = EXPF(s01 - mn0);
        float p10 = EXPF(s10 - mn1), p11 = EXPF(s11 - mn1);
        l0 += p00 + p01; l1 += p10 + p11;
        sc[warp*64 + lane]        = p00;
        sc[warp*64 + lane + 32]   = p01;
        sc[(warp+32)*64 + lane]      = p10;
        sc[(warp+32)*64 + lane + 32] = p11;
        __syncwarp();
        for (int j=0; j<64; j++) {
            float p0 = sc[warp*64 + j];
            float p1 = sc[(warp+32)*64 + j];
            float4 vv = *reinterpret_cast<const float4*>(vt + j*128 + lane*4);
            acc0.x = fmaf(p0, vv.x, acc0.x);
            acc0.y = fmaf(p0, vv.y, acc0.y);
            acc0.z = fmaf(p0, vv.z, acc0.z);
            acc0.w = fmaf(p0, vv.w, acc0.w);
            acc1.x = fmaf(p1, vv.x, acc1.x);
            acc1.y = fmaf(p1, vv.y, acc1.y);
            acc1.z = fmaf(p1, vv.z, acc1.z);
            acc1.w = fmaf(p1, vv.w, acc1.w);
        }
        m0 = mn0; m1 = mn1;
    }
    #pragma unroll
    for (int o=16;o;o>>=1) {
        l0 += __shfl_xor_sync(~0u,l0,o);
        l1 += __shfl_xor_sync(~0u,l1,o);
    }
    float i0 = 1.f/l0, i1 = 1.f/l1;
    uint2 hv;
    hv.x = pack2h(acc0.x*i0, acc0.y*i0);
    hv.y = pack2h(acc0.z*i0, acc0.w*i0);
    *reinterpret_cast<uint2*>(g_sh + qoff0 + lane*4) = hv;
    hv.x = pack2h(acc1.x*i1, acc1.y*i1);
    hv.y = pack2h(acc1.z*i1, acc1.w*i1);
    *reinterpret_cast<uint2*>(g_sh + qoff1 + lane*4) = hv;
}

// ---------------- k column max (heads 1..3) ----------------
__global__ void kmax_kernel() {
    int bh = blockIdx.x;
    int b = bh/3, hh = bh%3 + 1;
    int d = blockIdx.y*32 + threadIdx.x;
    int ty = threadIdx.y;
    int col = hh*DH + d;
    float m = -1e30f;
    for (int t = ty; t < SEQ; t += 8)
        m = fmaxf(m, g_k[(size_t)(b*SEQ+t)*DM + col]);
    __shared__ float sm[8][32];
    sm[ty][threadIdx.x] = m;
    __syncthreads();
    if (ty == 0) {
        #pragma unroll
        for (int r=1;r<8;r++) m = fmaxf(m, sm[r][threadIdx.x]);
        g_kmax[bh*DH + d] = m;
    }
}

// ---------------- ctx partial: tensor-core e@v + lse partials ----------------
// ctx[d][e] = sum_t e[t,d]*v[t,e]. A[d][t] via ldmatrix.trans of et[t][d] fp16;
// B[e][t] via ldmatrix.trans of vt[t][e] fp16. C[128 d][128 e] fp32.
__global__ __launch_bounds__(256) void ctx_partial_kernel() {
    __shared__ fp16 et[32][136];
    __shared__ fp16 vt[32][136];
    __shared__ float smax[DH];
    __shared__ float lred[8][DH];
    int bh = blockIdx.x, ks = blockIdx.y;
    int b = bh/3, hh = bh%3 + 1;
    int tid = threadIdx.x;
    if (tid < DH) smax[tid] = g_kmax[bh*DH + tid];
    int lr0 = tid >> 5, lc4 = tid & 31;
    int warp = tid >> 5, lane = tid & 31;
    int mw = warp & 3, nw = warp >> 2;       // warp tile: m = mw*32 (d), n = nw*64 (e)
    int grp = lane >> 2, qp = lane & 3;
    int lg = lane >> 3, lr8 = lane & 7;      // ldmatrix group / row

    float acc[2][8][4];
    #pragma unroll
    for (int i=0;i<2;i++)
        #pragma unroll
        for (int j=0;j<8;j++)
            #pragma unroll
            for (int r=0;r<4;r++) acc[i][j][r] = 0.f;
    float4 lacc = make_float4(0.f,0.f,0.f,0.f);
    __syncthreads();                          // smax visible

    const int TPB = SEQ / KSPL;               // 128 t per block
    for (int c = 0; c < TPB/32; c++) {
        #pragma unroll
        for (int i=0;i<4;i++) {
            int r = lr0 + 8*i;
            int t = ks*TPB + c*32 + r;
            size_t off = (size_t)(b*SEQ+t)*DM + hh*DH + lc4*4;
            float4 kv = *reinterpret_cast<const float4*>(g_k + off);
            float4 vv = *reinterpret_cast<const float4*>(g_v + off);
            int d0 = lc4*4;
            float e0 = EXPF(kv.x - smax[d0+0]);
            float e1 = EXPF(kv.y - smax[d0+1]);
            float e2 = EXPF(kv.z - smax[d0+2]);
            float e3 = EXPF(kv.w - smax[d0+3]);
            lacc.x += e0; lacc.y += e1; lacc.z += e2; lacc.w += e3;
            uint2 ep; ep.x = pack2h(e0, e1); ep.y = pack2h(e2, e3);
            uint2 vp; vp.x = pack2h(vv.x, vv.y); vp.y = pack2h(vv.z, vv.w);
            *reinterpret_cast<uint2*>(&et[r][d0]) = ep;
            *reinterpret_cast<uint2*>(&vt[r][d0]) = vp;
        }
        __syncthreads();
        #pragma unroll
        for (int kk = 0; kk < 2; kk++) {
            // A frags: groups g0:(k0-7,m0) g1:(k0-7,m8) g2:(k8-15,m0) g3:(k8-15,m8)
            uint32_t a[2][4];
            int arow = kk*16 + (lg & 2)*4 + lr8;
            #pragma unroll
            for (int mt = 0; mt < 2; mt++) {
                int acol = mw*32 + mt*16 + (lg & 1)*8;
                LDSM_X4T(a[mt][0], a[mt][1], a[mt][2], a[mt][3],
                         smem_u32(&et[arow][acol]));
            }
            // B frags: groups g0:(k0-7,n0) g1:(k8-15,n0) g2:(k0-7,n8) g3:(k8-15,n8)
            uint32_t bf[8][2];
            int brow = kk*16 + (lg & 1)*8 + lr8;
            #pragma unroll
            for (int p = 0; p < 4; p++) {
                int bcol = nw*64 + p*16 + (lg >> 1)*8;
                uint32_t t0r, t1r, t2r, t3r;
                LDSM_X4T(t0r, t1r, t2r, t3r, smem_u32(&vt[brow][bcol]));
                bf[p*2][0] = t0r; bf[p*2][1] = t1r;
                bf[p*2+1][0] = t2r; bf[p*2+1][1] = t3r;
            }
            #pragma unroll
            for (int mt = 0; mt < 2; mt++)
                #pragma unroll
                for (int nt = 0; nt < 8; nt++)
                    MMA16816(acc[mt][nt], a[mt][0],a[mt][1],a[mt][2],a[mt][3],
                             bf[nt][0], bf[nt][1]);
        }
        __syncthreads();
    }
    // lse partial
    *reinterpret_cast<float4*>(&lred[lr0][lc4*4]) = lacc;
    __syncthreads();
    if (tid < DH) {
        float s = 0.f;
        #pragma unroll
        for (int j=0;j<8;j++) s += lred[j][tid];
        g_lsep[(bh*KSPL + ks)*DH + tid] = s;
    }
    // epilogue: C[d][e]
    float* op = g_ctxp + ((size_t)bh*KSPL + ks)*DH*DH;
    #pragma unroll
    for (int mt = 0; mt < 2; mt++)
        #pragma unroll
        for (int nt = 0; nt < 8; nt++) {
            int drow = mw*32 + mt*16 + grp;
            int e0 = nw*64 + nt*8 + qp*2;
            float2 o;
            o.x = acc[mt][nt][0]; o.y = acc[mt][nt][1];
            *reinterpret_cast<float2*>(op + (size_t)drow*DH + e0) = o;
            o.x = acc[mt][nt][2]; o.y = acc[mt][nt][3];
            *reinterpret_cast<float2*>(op + (size_t)(drow+8)*DH + e0) = o;
        }
}

// ---------------- ctx reduce + normalize by lse ----------------
__global__ void ctx_reduce_kernel() {
    int idx = blockIdx.x*256 + threadIdx.x;
    if (idx >= BSZ*3*DH*DH) return;
    int bh = idx / (DH*DH);
    int de = idx - bh*DH*DH;
    int d = de >> 7;
    float s = 0.f, ls = 0.f;
    #pragma unroll
    for (int ks=0;ks<KSPL;ks++) {
        s  += g_ctxp[((size_t)bh*KSPL+ks)*DH*DH + de];
        ls += g_lsep[(bh*KSPL+ks)*DH + d];
    }
    g_ctx[idx] = s / ls;
}

// ---------------- linear-attn output -> fp16 (grid.y offset) ----------------
__global__ __launch_bounds__(256) void lin_out_kernel(int ybase) {
    __shared__ float sctx[64][DH];
    int bh = blockIdx.x;
    int b = bh/3, hh = bh%3 + 1;
    int warp = threadIdx.x >> 5, lane = threadIdx.x & 31;
    const float* ctxp = g_ctx + (size_t)bh*DH*DH;
    float pr[4][4], o[4][4];
    int tbase = (ybase + blockIdx.y)*32 + warp*4;
    #pragma unroll
    for (int tt=0;tt<4;tt++) {
        int t = tbase + tt;
        const float* qp = g_q + (size_t)(b*SEQ+t)*DM + hh*DH;
        float4 q4 = *reinterpret_cast<const float4*>(qp + lane*4);
        float mx = fmaxf(fmaxf(q4.x,q4.y),fmaxf(q4.z,q4.w));
        #pragma unroll
        for (int s=16;s;s>>=1) mx = fmaxf(mx, __shfl_xor_sync(~0u,mx,s));
        float e0=EXPF(q4.x-mx), e1=EXPF(q4.y-mx), e2=EXPF(q4.z-mx), e3=EXPF(q4.w-mx);
        float sm = e0+e1+e2+e3;
        #pragma unroll
        for (int s=16;s;s>>=1) sm += __shfl_xor_sync(~0u,sm,s);
        float inv = SCALE/sm;
        pr[tt][0]=e0*inv; pr[tt][1]=e1*inv; pr[tt][2]=e2*inv; pr[tt][3]=e3*inv;
        o[tt][0]=0.f; o[tt][1]=0.f; o[tt][2]=0.f; o[tt][3]=0.f;
    }
    for (int ph=0; ph<2; ph++) {
        __syncthreads();
        #pragma unroll
        for (int i=0;i<8;i++) {
            int idx = i*256 + threadIdx.x;
            int r = idx >> 5, c4 = idx & 31;
            *reinterpret_cast<float4*>(&sctx[r][c4*4]) =
                *reinterpret_cast<const float4*>(ctxp + (size_t)(ph*64+r)*DH + c4*4);
        }
        __syncthreads();
        #pragma unroll
        for (int dl=0; dl<16; dl++) {
            int src = ph*16 + dl;
            #pragma unroll
            for (int tt=0;tt<4;tt++) {
                float b0 = __shfl_sync(~0u, pr[tt][0], src);
                float b1 = __shfl_sync(~0u, pr[tt][1], src);
                float b2 = __shfl_sync(~0u, pr[tt][2], src);
                float b3 = __shfl_sync(~0u, pr[tt][3], src);
                float4 c0 = *reinterpret_cast<const float4*>(&sctx[dl*4+0][lane*4]);
                float4 c1 = *reinterpret_cast<const float4*>(&sctx[dl*4+1][lane*4]);
                float4 c2 = *reinterpret_cast<const float4*>(&sctx[dl*4+2][lane*4]);
                float4 c3 = *reinterpret_cast<const float4*>(&sctx[dl*4+3][lane*4]);
                o[tt][0] += b0*c0.x + b1*c1.x + b2*c2.x + b3*c3.x;
                o[tt][1] += b0*c0.y + b1*c1.y + b2*c2.y + b3*c3.y;
                o[tt][2] += b0*c0.z + b1*c1.z + b2*c2.z + b3*c3.z;
                o[tt][3] += b0*c0.w + b1*c1.w + b2*c2.w + b3*c3.w;
            }
        }
    }
    #pragma unroll
    for (int tt=0;tt<4;tt++) {
        int t = tbase + tt;
        uint2 hv;
        hv.x = pack2h(o[tt][0], o[tt][1]);
        hv.y = pack2h(o[tt][2], o[tt][3]);
        *reinterpret_cast<uint2*>(g_sh + (size_t)(b*SEQ+t)*DM + hh*DH + lane*4) = hv;
    }
}

// ---------------- host ----------------
static inline void tc_gemm(cudaStream_t st, const fp16* A, const fp16* B,
                           const float* bias, const float* res,
                           float* C, float* Ck, float* Cv, fp16* Ch,
                           int N, int K, int act, int omul = SEQ) {
    dim3 grid((N + 127) / 128, BSZ*MTPB);
    tc_gemm_kernel<<<grid, 256, GEMM_SMEM, st>>>(A, B, bias, res, C, Ck, Cv, Ch,
                                                 N, K, act, omul);
}

extern "C" void kernel_launch(void* const* d_in, const int* in_sizes, int n_in,
                              void* d_out, int out_size) {
    const float* x    = (const float*)d_in[0];
    const float* W1   = (const float*)d_in[1];
    const float* b1   = (const float*)d_in[2];
    const float* ln1g = (const float*)d_in[3];
    const float* ln1b = (const float*)d_in[4];
    const float* Wq   = (const float*)d_in[5];
    const float* Wk   = (const float*)d_in[6];
    const float* Wv   = (const float*)d_in[7];
    const float* Wo   = (const float*)d_in[8];
    const float* bo   = (const float*)d_in[9];
    const float* ln2g = (const float*)d_in[10];
    const float* ln2b = (const float*)d_in[11];
    const float* Wf1  = (const float*)d_in[12];
    const float* bf1  = (const float*)d_in[13];
    const float* Wf2  = (const float*)d_in[14];
    const float* bf2  = (const float*)d_in[15];
    const float* W2   = (const float*)d_in[16];
    const float* b2   = (const float*)d_in[17];
    float* out = (float*)d_out;

    static int init_done = 0;
    static cudaStream_t st1, st2;
    static cudaEvent_t evStart, evT1, evQKV, evPad, evCtx, evLin;
    if (!init_done) {
        cudaFuncSetAttribute(tc_gemm_kernel, cudaFuncAttributeMaxDynamicSharedMemorySize, GEMM_SMEM);
        cudaFuncSetAttribute(local_attn_kernel, cudaFuncAttributeMaxDynamicSharedMemorySize, LA_SMEM);
        cudaStreamCreateWithFlags(&st1, cudaStreamNonBlocking);
        cudaStreamCreateWithFlags(&st2, cudaStreamNonBlocking);
        cudaEventCreateWithFlags(&evStart, cudaEventDisableTiming);
        cudaEventCreateWithFlags(&evT1,    cudaEventDisableTiming);
        cudaEventCreateWithFlags(&evQKV,   cudaEventDisableTiming);
        cudaEventCreateWithFlags(&evPad,   cudaEventDisableTiming);
        cudaEventCreateWithFlags(&evCtx,   cudaEventDisableTiming);
        cudaEventCreateWithFlags(&evLin,   cudaEventDisableTiming);
        init_done = 1;
    }

    float *h,*q,*k,*v;
    fp16 *sh,*s2h;
    fp16 *w1h,*wqkv,*woh,*wf1h,*wf2h,*w2h;
    cudaGetSymbolAddress((void**)&h,    g_h);
    cudaGetSymbolAddress((void**)&q,    g_q);
    cudaGetSymbolAddress((void**)&k,    g_k);
    cudaGetSymbolAddress((void**)&v,    g_v);
    cudaGetSymbolAddress((void**)&sh,   g_sh);
    cudaGetSymbolAddress((void**)&s2h,  g_s2h);
    cudaGetSymbolAddress((void**)&w1h,  g_w1h);
    cudaGetSymbolAddress((void**)&wqkv, g_wqkv);
    cudaGetSymbolAddress((void**)&woh,  g_woh);
    cudaGetSymbolAddress((void**)&wf1h, g_wf1h);
    cudaGetSymbolAddress((void**)&wf2h, g_wf2h);
    cudaGetSymbolAddress((void**)&w2h,  g_w2h);

    dim3 tb(32, 8);

    cudaEventRecord(evStart, 0);
    cudaStreamWaitEvent(st2, evStart, 0);
    pad_ln_kernel<<<1, 512, 0, st2>>>(b1, ln1g, ln1b);
    pad_kv_kernel<<<4, 256, 0, st2>>>(Wk, Wv);
    padfill_kernel<<<(BSZ*(SEQ-NTOK)*(DM/4) + 255)/256, 256, 0, st2>>>();
    cudaEventRecord(evPad, st2);

    cudaStreamWaitEvent(st1, evStart, 0);
    transpose_h_kernel<<<dim3(DM/32,  DM/32),  tb, 0, st1>>>(Wq,  wqkv,            DM,  DM);
    transpose_h_kernel<<<dim3(DM/32,  DM/32),  tb, 0, st1>>>(Wk,  wqkv + DM*DM,    DM,  DM);
    transpose_h_kernel<<<dim3(DM/32,  DM/32),  tb, 0, st1>>>(Wv,  wqkv + 2*DM*DM,  DM,  DM);
    transpose_h_kernel<<<dim3(DM/32,  DM/32),  tb, 0, st1>>>(Wo,  woh,  DM,  DM);
    transpose_h_kernel<<<dim3(DFF/32, DM/32),  tb, 0, st1>>>(Wf1, wf1h, DM,  DFF);
    transpose_h_kernel<<<dim3(DM/32,  DFF/32), tb, 0, st1>>>(Wf2, wf2h, DFF, DM);
    transpose_h_kernel<<<dim3(DOUT/32,DM/32),  tb, 0, st1>>>(W2,  w2h,  DM,  DOUT);
    cudaEventRecord(evT1, st1);

    transpose_h_kernel<<<dim3(DM/32, DIN/32), tb>>>(W1, w1h, DIN, DM);
    pad_split_kernel<<<(BSZ*NTOK*(DIN/4) + 255)/256, 256>>>(x);
    tc_gemm(0, sh, w1h, b1, nullptr, h, nullptr, nullptr, nullptr, DM, DIN, 1);
    ln_kernel<<<BSZ*NTOK/8, 256>>>(h, ln1g, ln1b);
    cudaStreamWaitEvent(0, evT1, 0);
    tc_gemm(0, sh, wqkv, nullptr, nullptr, q, k, v, nullptr, 3*DM, DM, 0);
    cudaEventRecord(evQKV, 0);

    // lin chain on st1 (through ctx); lin_out weighted split (st1: 74, main: 20)
    cudaStreamWaitEvent(st1, evQKV, 0);
    cudaStreamWaitEvent(st1, evPad, 0);
    kmax_kernel<<<dim3(BSZ*3,4), dim3(32,8), 0, st1>>>();
    ctx_partial_kernel<<<dim3(BSZ*3,KSPL), 256, 0, st1>>>();
    ctx_reduce_kernel<<<(BSZ*3*DH*DH + 255)/256, 256, 0, st1>>>();
    cudaEventRecord(evCtx, st1);
    lin_out_kernel<<<dim3(BSZ*3, 74), 256, 0, st1>>>(0);
    cudaEventRecord(evLin, st1);

    cudaStreamWaitEvent(0, evPad, 0);
    local_attn_kernel<<<BSZ*QBPB, 1024, LA_SMEM>>>();
    cudaStreamWaitEvent(0, evCtx, 0);
    lin_out_kernel<<<dim3(BSZ*3, 20), 256>>>(74);
    cudaStreamWaitEvent(0, evLin, 0);

    // tail
    tc_gemm(0, sh, woh, bo, h, h, nullptr, nullptr, nullptr, DM, DM, 0);
    ln_kernel<<<BSZ*NTOK/8, 256>>>(h, ln2g, ln2b);
    tc_gemm(0, sh, wf1h, bf1, nullptr, nullptr, nullptr, nullptr, s2h, DFF, DM, 2);
    tc_gemm(0, s2h, wf2h, bf2, h, nullptr, nullptr, nullptr, sh, DM, DFF, 0);
    tc_gemm(0, sh, w2h, b2, nullptr, out, nullptr, nullptr, nullptr, DOUT, DM, 0, NTOK);
}

// round 15
// speedup vs baseline: 1.4202x; 1.1873x over previous
#include <cuda_runtime.h>
#include <cuda_fp16.h>
#include <math.h>
#include <stdint.h>

#define BSZ   8
#define SEQ   4096
#define NTOK  3000
#define DIN   128
#define DM    512
#define DFF   2048
#define DOUT  64
#define DH    128
#define MTOT  (BSZ*SEQ)
#define MTPB  24
#define QBPB  47
#define KSPL  32
#define SCALE 0.08838834764831845f
#define GEMM_SMEM (3*32768)
#define LA_SMEM   52224              // 3 x [64][136] fp16 tiles

typedef __half fp16;

// ---------------- scratch ----------------
__device__ float g_h[MTOT*DM];
__device__ float g_q[MTOT*DM];
__device__ float g_k[MTOT*DM];
__device__ float g_v[MTOT*DM];
__device__ float g_kmax[BSZ*3*DH];
__device__ float g_lsep[BSZ*3*KSPL*DH];
__device__ float g_ctxp[(size_t)BSZ*3*KSPL*DH*DH];
__device__ float g_ctx[BSZ*3*DH*DH];
__device__ float g_lnpad[DM];
__device__ float g_kpad[DM];
__device__ float g_vpad[DM];
__device__ fp16 g_sh[MTOT*DM];
__device__ fp16 g_s2h[MTOT*DFF];
__device__ fp16 g_w1h[DM*DIN];
__device__ fp16 g_wqkv[3*DM*DM];
__device__ fp16 g_woh[DM*DM];
__device__ fp16 g_wf1h[DFF*DM];
__device__ fp16 g_wf2h[DM*DFF];
__device__ fp16 g_w2h[DOUT*DM];

// ---------------- helpers ----------------
__device__ __forceinline__ uint32_t smem_u32(const void* p) {
    uint32_t a;
    asm("{ .reg .u64 t; cvta.to.shared.u64 t, %1; cvt.u32.u64 %0, t; }" : "=r"(a) : "l"(p));
    return a;
}
__device__ __forceinline__ uint32_t pack2h(float x, float y) {
    __half2 h = __floats2half2_rn(x, y);
    return *reinterpret_cast<uint32_t*>(&h);
}
__device__ __forceinline__ float fexp(float x) {
    x = fmaxf(x, -87.0f);
    float t = x * 1.4426950408889634f;
    float fn = rintf(t);
    float r = t - fn;
    float p =            1.5403530394e-4f;
    p = fmaf(p, r, 1.3333558146e-3f);
    p = fmaf(p, r, 9.6181291076e-3f);
    p = fmaf(p, r, 5.5504108665e-2f);
    p = fmaf(p, r, 2.4022650696e-1f);
    p = fmaf(p, r, 6.9314718056e-1f);
    p = fmaf(p, r, 1.0f);
    return __int_as_float(__float_as_int(p) + (((int)fn) << 23));
}
#define EXPF(x) fexp(x)

#define LDSM_X4(r0,r1,r2,r3,addr) \
    asm volatile("ldmatrix.sync.aligned.m8n8.x4.shared.b16 {%0,%1,%2,%3}, [%4];" \
        : "=r"(r0),"=r"(r1),"=r"(r2),"=r"(r3) : "r"(addr))
#define LDSM_X4T(r0,r1,r2,r3,addr) \
    asm volatile("ldmatrix.sync.aligned.m8n8.x4.trans.shared.b16 {%0,%1,%2,%3}, [%4];" \
        : "=r"(r0),"=r"(r1),"=r"(r2),"=r"(r3) : "r"(addr))
#define MMA16816(d, a0,a1,a2,a3, b0,b1) \
    asm volatile("mma.sync.aligned.m16n8k16.row.col.f32.f16.f16.f32 " \
        "{%0,%1,%2,%3},{%4,%5,%6,%7},{%8,%9},{%0,%1,%2,%3};" \
        : "+f"((d)[0]),"+f"((d)[1]),"+f"((d)[2]),"+f"((d)[3]) \
        : "r"(a0),"r"(a1),"r"(a2),"r"(a3),"r"(b0),"r"(b1))
#define CP_ASYNC16(dst, src, sz) \
    asm volatile("cp.async.cg.shared.global [%0], [%1], 16, %2;" :: "r"(dst), "l"(src), "r"(sz))
#define CP_COMMIT()  asm volatile("cp.async.commit_group;" ::: "memory")
#define CP_WAIT0()   asm volatile("cp.async.wait_group 0;" ::: "memory")
#define CP_WAIT1()   asm volatile("cp.async.wait_group 1;" ::: "memory")

// ---------------- weight transpose + fp16 ----------------
__global__ void transpose_h_kernel(const float* __restrict__ W,
                                   fp16* __restrict__ Th, int K, int N) {
    __shared__ float t[32][33];
    int bx = blockIdx.x * 32, by = blockIdx.y * 32;
    int x = bx + threadIdx.x;
    #pragma unroll
    for (int i = 0; i < 32; i += 8) {
        int y = by + threadIdx.y + i;
        if (x < N && y < K) t[threadIdx.y + i][threadIdx.x] = W[(size_t)y * N + x];
    }
    __syncthreads();
    int xk = by + threadIdx.x;
    #pragma unroll
    for (int i = 0; i < 32; i += 8) {
        int yn = bx + threadIdx.y + i;
        if (xk < K && yn < N)
            Th[(size_t)yn * K + xk] = __float2half_rn(t[threadIdx.x][threadIdx.y + i]);
    }
}

// ---------------- x (real rows only) -> g_sh fp16 ----------------
__global__ void pad_split_kernel(const float* __restrict__ x) {
    int idx = blockIdx.x*256 + threadIdx.x;
    const int total = BSZ*NTOK*(DIN/4);
    if (idx >= total) return;
    int rr = idx >> 5;
    int c4 = idx & 31;
    int b = rr / NTOK, t = rr - b*NTOK;
    float4 val = reinterpret_cast<const float4*>(x)[(size_t)rr*32 + c4];
    uint2 hv;
    hv.x = pack2h(val.x, val.y);
    hv.y = pack2h(val.z, val.w);
    *reinterpret_cast<uint2*>(g_sh + (size_t)(b*SEQ + t)*DIN + c4*4) = hv;
}

// ---------------- pad-row LN ----------------
__global__ void pad_ln_kernel(const float* __restrict__ b1, const float* __restrict__ gam,
                              const float* __restrict__ bet) {
    __shared__ float ss[16], ss2[16], stat[2];
    int t = threadIdx.x;
    float h = tanhf(b1[t]);
    float s = h, s2 = h*h;
    #pragma unroll
    for (int o=16;o;o>>=1) { s += __shfl_xor_sync(~0u,s,o); s2 += __shfl_xor_sync(~0u,s2,o); }
    if ((t & 31) == 0) { ss[t>>5] = s; ss2[t>>5] = s2; }
    __syncthreads();
    if (t == 0) {
        float S=0.f, S2=0.f;
        #pragma unroll
        for (int i=0;i<16;i++) { S += ss[i]; S2 += ss2[i]; }
        float mu = S*(1.f/512.f);
        float var = S2*(1.f/512.f) - mu*mu;
        stat[0] = mu; stat[1] = rsqrtf(var + 1e-5f);
    }
    __syncthreads();
    g_lnpad[t] = (h - stat[0])*stat[1]*gam[t] + bet[t];
}

// ---------------- pad-row k/v ----------------
__global__ void pad_kv_kernel(const float* __restrict__ Wk, const float* __restrict__ Wv) {
    int d = blockIdx.x*256 + threadIdx.x;
    if (d >= 2*DM) return;
    const float* W = (d < DM) ? Wk : Wv;
    int dd = d & (DM-1);
    float s = 0.f;
    for (int kk = 0; kk < DM; kk++) s += g_lnpad[kk] * W[(size_t)kk*DM + dd];
    if (d < DM) g_kpad[dd] = s; else g_vpad[dd] = s;
}

// ---------------- broadcast pad k/v rows ----------------
__global__ void padfill_kernel() {
    int idx = blockIdx.x*256 + threadIdx.x;
    const int per = (SEQ-NTOK)*(DM/4);
    if (idx >= BSZ*per) return;
    int b = idx / per, r = idx - b*per;
    int t = NTOK + r/(DM/4), c4 = r % (DM/4);
    size_t off = (size_t)(b*SEQ + t)*DM + c4*4;
    *reinterpret_cast<float4*>(g_k + off) = *reinterpret_cast<const float4*>(g_kpad + c4*4);
    *reinterpret_cast<float4*>(g_v + off) = *reinterpret_cast<const float4*>(g_vpad + c4*4);
}

// ---------------- fp16 tensor-core GEMM (unchanged) ----------------
__global__ __launch_bounds__(256, 2) void tc_gemm_kernel(
    const fp16* __restrict__ A, const fp16* __restrict__ B,
    const float* __restrict__ bias, const float* __restrict__ res,
    float* __restrict__ C, float* __restrict__ Ck, float* __restrict__ Cv,
    fp16* __restrict__ Ch,
    int N, int K, int act, int omul)
{
    extern __shared__ __align__(1024) char smc[];
    uint32_t sbase = smem_u32(smc);
    int tid = threadIdx.x;
    int mtile = blockIdx.y;
    int bb = mtile / MTPB, t0 = (mtile - bb*MTPB) << 7;
    int bm = bb*SEQ + t0;
    int alim = NTOK - t0;
    int rowlim = bm + alim;
    int odelta = bb*(omul - SEQ);
    int bn = blockIdx.x << 7;
    int lane = tid & 31, w = tid >> 5;
    int wm = w & 1, wn = w >> 1;
    int grp = lane >> 2, qp = lane & 3;

    uint32_t swz = (lane >> 1) & 3;
    uint32_t a_base = (uint32_t)(wm*64 + (lane & 15))*64 + (((uint32_t)(lane >> 4) ^ swz) << 4);
    uint32_t b_base = (uint32_t)(wn*32 + ((lane >> 4) & 1)*8 + (lane & 7))*64
                    + ((((uint32_t)(lane >> 3) & 1) ^ swz) << 4);

    float acc[4][4][4];
    #pragma unroll
    for (int i=0;i<4;i++)
        #pragma unroll
        for (int j=0;j<4;j++)
            #pragma unroll
            for (int r=0;r<4;r++) acc[i][j][r] = 0.f;

    const int NC = K >> 6;

    #define STAGE_LOAD(c_, buf_) do { \
        uint32_t sb = sbase + (uint32_t)(buf_)*32768u; \
        _Pragma("unroll") \
        for (int i_ = 0; i_ < 8; i_++) { \
            const int sub_ = i_ >> 2; \
            const int arr_ = (i_ >> 1) & 1; \
            int j_ = ((i_ & 1) << 8) + tid; \
            int r_ = j_ >> 2, cc_ = j_ & 3; \
            int k0 = ((c_) << 6) + sub_*32; \
            uint32_t dst_ = sb + (uint32_t)sub_*16384u + (uint32_t)arr_*8192u \
                          + (uint32_t)r_*64u + ((uint32_t)(cc_ ^ ((r_ >> 1) & 3)) << 4); \
            const fp16* g_; int sz_ = 16; \
            if (arr_ == 0) { \
                if (r_ < alim) g_ = A + (size_t)(bm + r_)*K + k0 + cc_*8; \
                else { g_ = A; sz_ = 0; } \
            } else { \
                int rowv_ = bn + r_; \
                if (rowv_ < N) g_ = B + (size_t)rowv_*K + k0 + cc_*8; \
                else { g_ = B; sz_ = 0; } \
            } \
            CP_ASYNC16(dst_, g_, sz_); \
        } \
        CP_COMMIT(); \
    } while (0)

    STAGE_LOAD(0, 0);
    if (NC > 1) STAGE_LOAD(1, 1);

    int buf = 0, bufn = 2;
    for (int c = 0; c < NC; c++) {
        if (c + 1 < NC) CP_WAIT1(); else CP_WAIT0();
        __syncthreads();
        if (c + 2 < NC) {
            STAGE_LOAD(c + 2, bufn);
            bufn = (bufn == 2) ? 0 : bufn + 1;
        }
        uint32_t stg = sbase + (uint32_t)buf*32768u;
        buf = (buf == 2) ? 0 : buf + 1;

        #pragma unroll
        for (int sub = 0; sub < 2; sub++) {
            uint32_t sA = stg + (uint32_t)sub*16384u;
            uint32_t sB = sA + 8192u;
            #pragma unroll
            for (int ks = 0; ks < 2; ks++) {
                uint32_t kx = ks ? 32u : 0u;
                uint32_t bh[4][2], a[4][4];
                #pragma unroll
                for (int p = 0; p < 2; p++)
                    LDSM_X4(bh[2*p][0], bh[2*p][1], bh[2*p+1][0], bh[2*p+1][1],
                            sB + ((b_base + p*1024u) ^ kx));
                #pragma unroll
                for (int mt = 0; mt < 4; mt++)
                    LDSM_X4(a[mt][0], a[mt][1], a[mt][2], a[mt][3],
                            sA + ((a_base + mt*1024u) ^ kx));
                #pragma unroll
                for (int mt = 0; mt < 4; mt++)
                    #pragma unroll
                    for (int nt = 0; nt < 4; nt++)
                        MMA16816(acc[mt][nt], a[mt][0],a[mt][1],a[mt][2],a[mt][3],
                                 bh[nt][0],bh[nt][1]);
            }
        }
    }
    #undef STAGE_LOAD

    #pragma unroll
    for (int mt = 0; mt < 4; mt++) {
        #pragma unroll
        for (int nt = 0; nt < 4; nt++) {
            int c0 = bn + wn*32 + nt*8 + qp*2;
            if (c0 >= N) continue;
            int rbase = bm + wm*64 + mt*16 + grp;
            float bs0 = 0.f, bs1 = 0.f;
            if (bias) { bs0 = bias[c0]; bs1 = bias[c0 + 1]; }
            #pragma unroll
            for (int half = 0; half < 2; half++) {
                int r = rbase + half*8;
                if (r >= rowlim) continue;
                float v0 = acc[mt][nt][half*2 + 0] + bs0;
                float v1 = acc[mt][nt][half*2 + 1] + bs1;
                if (act == 1) { v0 = tanhf(v0); v1 = tanhf(v1); }
                else if (act == 2) {
                    v0 = 0.5f*v0*(1.f + erff(v0*0.7071067811865476f));
                    v1 = 0.5f*v1*(1.f + erff(v1*0.7071067811865476f));
                }
                if (res) {
                    v0 += res[(size_t)r*N + c0];
                    v1 += res[(size_t)r*N + c0 + 1];
                }
                size_t orow = (size_t)(r + odelta);
                if (Ck) {
                    float* dst; int cc;
                    if (c0 < 512)       { dst = C;  cc = c0; }
                    else if (c0 < 1024) { dst = Ck; cc = c0 - 512; }
                    else                { dst = Cv; cc = c0 - 1024; }
                    float2 o; o.x = v0; o.y = v1;
                    *reinterpret_cast<float2*>(dst + orow*512 + cc) = o;
                } else if (Ch) {
                    *reinterpret_cast<uint32_t*>(Ch + orow*N + c0) = pack2h(v0, v1);
                } else {
                    float2 o; o.x = v0; o.y = v1;
                    *reinterpret_cast<float2*>(C + orow*N + c0) = o;
                }
            }
        }
    }
}

// ---------------- LayerNorm (real rows) -> fp16 ----------------
__global__ void ln_kernel(const float* __restrict__ in, const float* __restrict__ gam,
                          const float* __restrict__ bet) {
    int gw = (blockIdx.x*blockDim.x + threadIdx.x) >> 5;
    int lane = threadIdx.x & 31;
    if (gw >= BSZ*NTOK) return;
    int b = gw / NTOK, t = gw - b*NTOK;
    size_t row = (size_t)(b*SEQ + t);
    const float4* rp = reinterpret_cast<const float4*>(in + row*DM);
    float4 v[4];
    float s=0.f, s2=0.f;
    #pragma unroll
    for (int i=0;i<4;i++) {
        v[i] = rp[lane + 32*i];
        s  += v[i].x+v[i].y+v[i].z+v[i].w;
        s2 += v[i].x*v[i].x + v[i].y*v[i].y + v[i].z*v[i].z + v[i].w*v[i].w;
    }
    #pragma unroll
    for (int o=16;o;o>>=1) { s += __shfl_xor_sync(~0u,s,o); s2 += __shfl_xor_sync(~0u,s2,o); }
    float mu  = s*(1.f/512.f);
    float var = s2*(1.f/512.f) - mu*mu;
    float r = rsqrtf(var + 1e-5f);
    #pragma unroll
    for (int i=0;i<4;i++) {
        int c = (lane + 32*i)*4;
        float4 g4 = *reinterpret_cast<const float4*>(gam + c);
        float4 b4 = *reinterpret_cast<const float4*>(bet + c);
        uint2 hv;
        hv.x = pack2h((v[i].x-mu)*r*g4.x + b4.x, (v[i].y-mu)*r*g4.y + b4.y);
        hv.y = pack2h((v[i].z-mu)*r*g4.z + b4.z, (v[i].w-mu)*r*g4.w + b4.w);
        *reinterpret_cast<uint2*>(g_sh + row*DM + c) = hv;
    }
}

// ---------------- local attention, head 0: tensor-core FlashAttention --------
// 64 queries/block, 4 warps (warp w -> q rows w*16..+15). Tiles [64][136] fp16.
__global__ __launch_bounds__(128) void local_attn_kernel() {
    extern __shared__ fp16 sm16[];
    fp16* qt = sm16;            // [64][136]
    fp16* kt = sm16 + 8704;
    fp16* vt = sm16 + 17408;
    int b   = blockIdx.x / QBPB;
    int blk = blockIdx.x - b*QBPB;
    int qbase = blk*64;
    int win = qbase >> 7;
    int tid = threadIdx.x;
    int warp = tid >> 5, lane = tid & 31;
    int grp = lane >> 2, qp = lane & 3;

    // load Q tile (64 x 128) fp32 -> fp16
    #pragma unroll
    for (int i = 0; i < 16; i++) {
        int idx = i*128 + tid;
        int r = idx >> 5, c4 = idx & 31;
        float4 qv = *reinterpret_cast<const float4*>(
            g_q + (size_t)(b*SEQ + qbase + r)*DM + c4*4);
        uint2 hp; hp.x = pack2h(qv.x, qv.y); hp.y = pack2h(qv.z, qv.w);
        *reinterpret_cast<uint2*>(qt + r*136 + c4*4) = hp;
    }

    float m0 = -1e30f, m1 = -1e30f, l0 = 0.f, l1 = 0.f;
    float o[16][4];
    #pragma unroll
    for (int nt=0; nt<16; nt++)
        #pragma unroll
        for (int r=0; r<4; r++) o[nt][r] = 0.f;

    int kbase = win*128 - 128;
    for (int ch=0; ch<6; ch++) {
        int t0k = kbase + ch*64;
        __syncthreads();                    // prior reads done (also covers Q write)
        // load K,V chunk (64 x 128 each) fp32 -> fp16
        #pragma unroll
        for (int i = 0; i < 32; i++) {
            int idx = i*128 + tid;
            int isV = idx >> 11;
            int j = idx & 2047;
            int r = j >> 5, c4 = j & 31;
            int t = t0k + r;
            const float* src = isV ? g_v : g_k;
            fp16* dst = isV ? vt : kt;
            float4 val = make_float4(0.f,0.f,0.f,0.f);
            if (t >= 0 && t < SEQ)
                val = *reinterpret_cast<const float4*>(src + (size_t)(b*SEQ+t)*DM + c4*4);
            uint2 hp; hp.x = pack2h(val.x, val.y); hp.y = pack2h(val.z, val.w);
            *reinterpret_cast<uint2*>(dst + r*136 + c4*4) = hp;
        }
        __syncthreads();
        // S = Q K^T : warp m16 x n64, k = 128 (8 steps)
        float s[8][4];
        #pragma unroll
        for (int nt=0; nt<8; nt++)
            #pragma unroll
            for (int r=0; r<4; r++) s[nt][r] = 0.f;
        #pragma unroll
        for (int kk = 0; kk < 8; kk++) {
            uint32_t a0,a1,a2,a3;
            LDSM_X4(a0,a1,a2,a3,
                smem_u32(qt + (warp*16 + (lane & 15))*136 + kk*16 + ((lane >> 4) & 1)*8));
            #pragma unroll
            for (int p = 0; p < 4; p++) {
                uint32_t b0,b1,b2,b3;
                LDSM_X4(b0,b1,b2,b3,
                    smem_u32(kt + (p*16 + ((lane >> 4) & 1)*8 + (lane & 7))*136
                             + kk*16 + ((lane >> 3) & 1)*8));
                MMA16816(s[2*p],   a0,a1,a2,a3, b0,b1);
                MMA16816(s[2*p+1], a0,a1,a2,a3, b2,b3);
            }
        }
        // mask + row max (rows grp / grp+8; cols nt*8+qp*2,+1)
        float cm0 = -1e38f, cm1 = -1e38f;
        #pragma unroll
        for (int nt=0; nt<8; nt++) {
            int tg0 = t0k + nt*8 + qp*2;
            bool v0 = (tg0 >= 0 && tg0 < SEQ);
            bool v1 = (tg0+1 >= 0 && tg0+1 < SEQ);
            s[nt][0] = v0 ? s[nt][0]*SCALE : -1e38f;
            s[nt][1] = v1 ? s[nt][1]*SCALE : -1e38f;
            s[nt][2] = v0 ? s[nt][2]*SCALE : -1e38f;
            s[nt][3] = v1 ? s[nt][3]*SCALE : -1e38f;
            cm0 = fmaxf(cm0, fmaxf(s[nt][0], s[nt][1]));
            cm1 = fmaxf(cm1, fmaxf(s[nt][2], s[nt][3]));
        }
        cm0 = fmaxf(cm0, __shfl_xor_sync(~0u, cm0, 1));
        cm0 = fmaxf(cm0, __shfl_xor_sync(~0u, cm0, 2));
        cm1 = fmaxf(cm1, __shfl_xor_sync(~0u, cm1, 1));
        cm1 = fmaxf(cm1, __shfl_xor_sync(~0u, cm1, 2));
        float mn0 = fmaxf(m0, cm0), mn1 = fmaxf(m1, cm1);
        float c0 = EXPF(m0 - mn0), c1 = EXPF(m1 - mn1);
        l0 *= c0; l1 *= c1;
        #pragma unroll
        for (int nt=0; nt<16; nt++) {
            o[nt][0]*=c0; o[nt][1]*=c0; o[nt][2]*=c1; o[nt][3]*=c1;
        }
        // P = exp(S - mn), packed to A-frags (FA2 C->A pairing)
        uint32_t pa[4][4];
        #pragma unroll
        for (int kk=0; kk<4; kk++) {
            int n0 = 2*kk, n1 = 2*kk+1;
            float p00 = EXPF(s[n0][0]-mn0), p01 = EXPF(s[n0][1]-mn0);
            float p02 = EXPF(s[n0][2]-mn1), p03 = EXPF(s[n0][3]-mn1);
            float p10 = EXPF(s[n1][0]-mn0), p11 = EXPF(s[n1][1]-mn0);
            float p12 = EXPF(s[n1][2]-mn1), p13 = EXPF(s[n1][3]-mn1);
            l0 += p00 + p01 + p10 + p11;
            l1 += p02 + p03 + p12 + p13;
            pa[kk][0] = pack2h(p00, p01);
            pa[kk][1] = pack2h(p02, p03);
            pa[kk][2] = pack2h(p10, p11);
            pa[kk][3] = pack2h(p12, p13);
        }
        // O += P V : k = t (4 steps of 16), n = d (16 tiles), B = V^T via trans
        #pragma unroll
        for (int kk=0; kk<4; kk++) {
            int brow = kk*16 + ((lane >> 3) & 1)*8 + (lane & 7);
            #pragma unroll
            for (int p = 0; p < 8; p++) {
                uint32_t b0,b1,b2,b3;
                LDSM_X4T(b0,b1,b2,b3,
                    smem_u32(vt + brow*136 + p*16 + ((lane >> 4) & 1)*8));
                MMA16816(o[2*p],   pa[kk][0],pa[kk][1],pa[kk][2],pa[kk][3], b0,b1);
                MMA16816(o[2*p+1], pa[kk][0],pa[kk][1],pa[kk][2],pa[kk][3], b2,b3);
            }
        }
        m0 = mn0; m1 = mn1;
    }
    // row-sum reduce l over qp lanes
    l0 += __shfl_xor_sync(~0u, l0, 1); l0 += __shfl_xor_sync(~0u, l0, 2);
    l1 += __shfl_xor_sync(~0u, l1, 1); l1 += __shfl_xor_sync(~0u, l1, 2);
    float i0 = 1.f/l0, i1 = 1.f/l1;
    size_t row0 = (size_t)(b*SEQ + qbase + warp*16 + grp);
    size_t row1 = row0 + 8;
    #pragma unroll
    for (int nt=0; nt<16; nt++) {
        int col = nt*8 + qp*2;
        *reinterpret_cast<uint32_t*>(g_sh + row0*DM + col) = pack2h(o[nt][0]*i0, o[nt][1]*i0);
        *reinterpret_cast<uint32_t*>(g_sh + row1*DM + col) = pack2h(o[nt][2]*i1, o[nt][3]*i1);
    }
}

// ---------------- k column max (heads 1..3) ----------------
__global__ void kmax_kernel() {
    int bh = blockIdx.x;
    int b = bh/3, hh = bh%3 + 1;
    int d = blockIdx.y*32 + threadIdx.x;
    int ty = threadIdx.y;
    int col = hh*DH + d;
    float m = -1e30f;
    for (int t = ty; t < SEQ; t += 8)
        m = fmaxf(m, g_k[(size_t)(b*SEQ+t)*DM + col]);
    __shared__ float sm[8][32];
    sm[ty][threadIdx.x] = m;
    __syncthreads();
    if (ty == 0) {
        #pragma unroll
        for (int r=1;r<8;r++) m = fmaxf(m, sm[r][threadIdx.x]);
        g_kmax[bh*DH + d] = m;
    }
}

// ---------------- ctx partial: tensor-core e@v + lse partials ----------------
__global__ __launch_bounds__(256) void ctx_partial_kernel() {
    __shared__ fp16 et[32][136];
    __shared__ fp16 vt[32][136];
    __shared__ float smax[DH];
    __shared__ float lred[8][DH];
    int bh = blockIdx.x, ks = blockIdx.y;
    int b = bh/3, hh = bh%3 + 1;
    int tid = threadIdx.x;
    if (tid < DH) smax[tid] = g_kmax[bh*DH + tid];
    int lr0 = tid >> 5, lc4 = tid & 31;
    int warp = tid >> 5, lane = tid & 31;
    int mw = warp & 3, nw = warp >> 2;
    int grp = lane >> 2, qp = lane & 3;
    int lg = lane >> 3, lr8 = lane & 7;

    float acc[2][8][4];
    #pragma unroll
    for (int i=0;i<2;i++)
        #pragma unroll
        for (int j=0;j<8;j++)
            #pragma unroll
            for (int r=0;r<4;r++) acc[i][j][r] = 0.f;
    float4 lacc = make_float4(0.f,0.f,0.f,0.f);
    __syncthreads();

    const int TPB = SEQ / KSPL;
    for (int c = 0; c < TPB/32; c++) {
        #pragma unroll
        for (int i=0;i<4;i++) {
            int r = lr0 + 8*i;
            int t = ks*TPB + c*32 + r;
            size_t off = (size_t)(b*SEQ+t)*DM + hh*DH + lc4*4;
            float4 kv = *reinterpret_cast<const float4*>(g_k + off);
            float4 vv = *reinterpret_cast<const float4*>(g_v + off);
            int d0 = lc4*4;
            float e0 = EXPF(kv.x - smax[d0+0]);
            float e1 = EXPF(kv.y - smax[d0+1]);
            float e2 = EXPF(kv.z - smax[d0+2]);
            float e3 = EXPF(kv.w - smax[d0+3]);
            lacc.x += e0; lacc.y += e1; lacc.z += e2; lacc.w += e3;
            uint2 ep; ep.x = pack2h(e0, e1); ep.y = pack2h(e2, e3);
            uint2 vp; vp.x = pack2h(vv.x, vv.y); vp.y = pack2h(vv.z, vv.w);
            *reinterpret_cast<uint2*>(&et[r][d0]) = ep;
            *reinterpret_cast<uint2*>(&vt[r][d0]) = vp;
        }
        __syncthreads();
        #pragma unroll
        for (int kk = 0; kk < 2; kk++) {
            uint32_t a[2][4];
            int arow = kk*16 + (lg & 2)*4 + lr8;
            #pragma unroll
            for (int mt = 0; mt < 2; mt++) {
                int acol = mw*32 + mt*16 + (lg & 1)*8;
                LDSM_X4T(a[mt][0], a[mt][1], a[mt][2], a[mt][3],
                         smem_u32(&et[arow][acol]));
            }
            uint32_t bf[8][2];
            int brow = kk*16 + (lg & 1)*8 + lr8;
            #pragma unroll
            for (int p = 0; p < 4; p++) {
                int bcol = nw*64 + p*16 + (lg >> 1)*8;
                uint32_t t0r, t1r, t2r, t3r;
                LDSM_X4T(t0r, t1r, t2r, t3r, smem_u32(&vt[brow][bcol]));
                bf[p*2][0] = t0r; bf[p*2][1] = t1r;
                bf[p*2+1][0] = t2r; bf[p*2+1][1] = t3r;
            }
            #pragma unroll
            for (int mt = 0; mt < 2; mt++)
                #pragma unroll
                for (int nt = 0; nt < 8; nt++)
                    MMA16816(acc[mt][nt], a[mt][0],a[mt][1],a[mt][2],a[mt][3],
                             bf[nt][0], bf[nt][1]);
        }
        __syncthreads();
    }
    *reinterpret_cast<float4*>(&lred[lr0][lc4*4]) = lacc;
    __syncthreads();
    if (tid < DH) {
        float s = 0.f;
        #pragma unroll
        for (int j=0;j<8;j++) s += lred[j][tid];
        g_lsep[(bh*KSPL + ks)*DH + tid] = s;
    }
    float* op = g_ctxp + ((size_t)bh*KSPL + ks)*DH*DH;
    #pragma unroll
    for (int mt = 0; mt < 2; mt++)
        #pragma unroll
        for (int nt = 0; nt < 8; nt++) {
            int drow = mw*32 + mt*16 + grp;
            int e0 = nw*64 + nt*8 + qp*2;
            float2 o;
            o.x = acc[mt][nt][0]; o.y = acc[mt][nt][1];
            *reinterpret_cast<float2*>(op + (size_t)drow*DH + e0) = o;
            o.x = acc[mt][nt][2]; o.y = acc[mt][nt][3];
            *reinterpret_cast<float2*>(op + (size_t)(drow+8)*DH + e0) = o;
        }
}

// ---------------- ctx reduce + normalize by lse ----------------
__global__ void ctx_reduce_kernel() {
    int idx = blockIdx.x*256 + threadIdx.x;
    if (idx >= BSZ*3*DH*DH) return;
    int bh = idx / (DH*DH);
    int de = idx - bh*DH*DH;
    int d = de >> 7;
    float s = 0.f, ls = 0.f;
    #pragma unroll
    for (int ks=0;ks<KSPL;ks++) {
        s  += g_ctxp[((size_t)bh*KSPL+ks)*DH*DH + de];
        ls += g_lsep[(bh*KSPL+ks)*DH + d];
    }
    g_ctx[idx] = s / ls;
}

// ---------------- linear-attn output -> fp16 (grid.y offset) ----------------
__global__ __launch_bounds__(256) void lin_out_kernel(int ybase) {
    __shared__ float sctx[64][DH];
    int bh = blockIdx.x;
    int b = bh/3, hh = bh%3 + 1;
    int warp = threadIdx.x >> 5, lane = threadIdx.x & 31;
    const float* ctxp = g_ctx + (size_t)bh*DH*DH;
    float pr[4][4], o[4][4];
    int tbase = (ybase + blockIdx.y)*32 + warp*4;
    #pragma unroll
    for (int tt=0;tt<4;tt++) {
        int t = tbase + tt;
        const float* qp = g_q + (size_t)(b*SEQ+t)*DM + hh*DH;
        float4 q4 = *reinterpret_cast<const float4*>(qp + lane*4);
        float mx = fmaxf(fmaxf(q4.x,q4.y),fmaxf(q4.z,q4.w));
        #pragma unroll
        for (int s=16;s;s>>=1) mx = fmaxf(mx, __shfl_xor_sync(~0u,mx,s));
        float e0=EXPF(q4.x-mx), e1=EXPF(q4.y-mx), e2=EXPF(q4.z-mx), e3=EXPF(q4.w-mx);
        float sm = e0+e1+e2+e3;
        #pragma unroll
        for (int s=16;s;s>>=1) sm += __shfl_xor_sync(~0u,sm,s);
        float inv = SCALE/sm;
        pr[tt][0]=e0*inv; pr[tt][1]=e1*inv; pr[tt][2]=e2*inv; pr[tt][3]=e3*inv;
        o[tt][0]=0.f; o[tt][1]=0.f; o[tt][2]=0.f; o[tt][3]=0.f;
    }
    for (int ph=0; ph<2; ph++) {
        __syncthreads();
        #pragma unroll
        for (int i=0;i<8;i++) {
            int idx = i*256 + threadIdx.x;
            int r = idx >> 5, c4 = idx & 31;
            *reinterpret_cast<float4*>(&sctx[r][c4*4]) =
                *reinterpret_cast<const float4*>(ctxp + (size_t)(ph*64+r)*DH + c4*4);
        }
        __syncthreads();
        #pragma unroll
        for (int dl=0; dl<16; dl++) {
            int src = ph*16 + dl;
            #pragma unroll
            for (int tt=0;tt<4;tt++) {
                float b0 = __shfl_sync(~0u, pr[tt][0], src);
                float b1 = __shfl_sync(~0u, pr[tt][1], src);
                float b2 = __shfl_sync(~0u, pr[tt][2], src);
                float b3 = __shfl_sync(~0u, pr[tt][3], src);
                float4 c0 = *reinterpret_cast<const float4*>(&sctx[dl*4+0][lane*4]);
                float4 c1 = *reinterpret_cast<const float4*>(&sctx[dl*4+1][lane*4]);
                float4 c2 = *reinterpret_cast<const float4*>(&sctx[dl*4+2][lane*4]);
                float4 c3 = *reinterpret_cast<const float4*>(&sctx[dl*4+3][lane*4]);
                o[tt][0] += b0*c0.x + b1*c1.x + b2*c2.x + b3*c3.x;
                o[tt][1] += b0*c0.y + b1*c1.y + b2*c2.y + b3*c3.y;
                o[tt][2] += b0*c0.z + b1*c1.z + b2*c2.z + b3*c3.z;
                o[tt][3] += b0*c0.w + b1*c1.w + b2*c2.w + b3*c3.w;
            }
        }
    }
    #pragma unroll
    for (int tt=0;tt<4;tt++) {
        int t = tbase + tt;
        uint2 hv;
        hv.x = pack2h(o[tt][0], o[tt][1]);
        hv.y = pack2h(o[tt][2], o[tt][3]);
        *reinterpret_cast<uint2*>(g_sh + (size_t)(b*SEQ+t)*DM + hh*DH + lane*4) = hv;
    }
}

// ---------------- host ----------------
static inline void tc_gemm(cudaStream_t st, const fp16* A, const fp16* B,
                           const float* bias, const float* res,
                           float* C, float* Ck, float* Cv, fp16* Ch,
                           int N, int K, int act, int omul = SEQ) {
    dim3 grid((N + 127) / 128, BSZ*MTPB);
    tc_gemm_kernel<<<grid, 256, GEMM_SMEM, st>>>(A, B, bias, res, C, Ck, Cv, Ch,
                                                 N, K, act, omul);
}

extern "C" void kernel_launch(void* const* d_in, const int* in_sizes, int n_in,
                              void* d_out, int out_size) {
    const float* x    = (const float*)d_in[0];
    const float* W1   = (const float*)d_in[1];
    const float* b1   = (const float*)d_in[2];
    const float* ln1g = (const float*)d_in[3];
    const float* ln1b = (const float*)d_in[4];
    const float* Wq   = (const float*)d_in[5];
    const float* Wk   = (const float*)d_in[6];
    const float* Wv   = (const float*)d_in[7];
    const float* Wo   = (const float*)d_in[8];
    const float* bo   = (const float*)d_in[9];
    const float* ln2g = (const float*)d_in[10];
    const float* ln2b = (const float*)d_in[11];
    const float* Wf1  = (const float*)d_in[12];
    const float* bf1  = (const float*)d_in[13];
    const float* Wf2  = (const float*)d_in[14];
    const float* bf2  = (const float*)d_in[15];
    const float* W2   = (const float*)d_in[16];
    const float* b2   = (const float*)d_in[17];
    float* out = (float*)d_out;

    static int init_done = 0;
    static cudaStream_t st1, st2;
    static cudaEvent_t evStart, evT1, evQKV, evPad, evCtx, evLin;
    if (!init_done) {
        cudaFuncSetAttribute(tc_gemm_kernel, cudaFuncAttributeMaxDynamicSharedMemorySize, GEMM_SMEM);
        cudaFuncSetAttribute(local_attn_kernel, cudaFuncAttributeMaxDynamicSharedMemorySize, LA_SMEM);
        cudaStreamCreateWithFlags(&st1, cudaStreamNonBlocking);
        cudaStreamCreateWithFlags(&st2, cudaStreamNonBlocking);
        cudaEventCreateWithFlags(&evStart, cudaEventDisableTiming);
        cudaEventCreateWithFlags(&evT1,    cudaEventDisableTiming);
        cudaEventCreateWithFlags(&evQKV,   cudaEventDisableTiming);
        cudaEventCreateWithFlags(&evPad,   cudaEventDisableTiming);
        cudaEventCreateWithFlags(&evCtx,   cudaEventDisableTiming);
        cudaEventCreateWithFlags(&evLin,   cudaEventDisableTiming);
        init_done = 1;
    }

    float *h,*q,*k,*v;
    fp16 *sh,*s2h;
    fp16 *w1h,*wqkv,*woh,*wf1h,*wf2h,*w2h;
    cudaGetSymbolAddress((void**)&h,    g_h);
    cudaGetSymbolAddress((void**)&q,    g_q);
    cudaGetSymbolAddress((void**)&k,    g_k);
    cudaGetSymbolAddress((void**)&v,    g_v);
    cudaGetSymbolAddress((void**)&sh,   g_sh);
    cudaGetSymbolAddress((void**)&s2h,  g_s2h);
    cudaGetSymbolAddress((void**)&w1h,  g_w1h);
    cudaGetSymbolAddress((void**)&wqkv, g_wqkv);
    cudaGetSymbolAddress((void**)&woh,  g_woh);
    cudaGetSymbolAddress((void**)&wf1h, g_wf1h);
    cudaGetSymbolAddress((void**)&wf2h, g_wf2h);
    cudaGetSymbolAddress((void**)&w2h,  g_w2h);

    dim3 tb(32, 8);

    cudaEventRecord(evStart, 0);
    cudaStreamWaitEvent(st2, evStart, 0);
    pad_ln_kernel<<<1, 512, 0, st2>>>(b1, ln1g, ln1b);
    pad_kv_kernel<<<4, 256, 0, st2>>>(Wk, Wv);
    padfill_kernel<<<(BSZ*(SEQ-NTOK)*(DM/4) + 255)/256, 256, 0, st2>>>();
    cudaEventRecord(evPad, st2);

    cudaStreamWaitEvent(st1, evStart, 0);
    transpose_h_kernel<<<dim3(DM/32,  DM/32),  tb, 0, st1>>>(Wq,  wqkv,            DM,  DM);
    transpose_h_kernel<<<dim3(DM/32,  DM/32),  tb, 0, st1>>>(Wk,  wqkv + DM*DM,    DM,  DM);
    transpose_h_kernel<<<dim3(DM/32,  DM/32),  tb, 0, st1>>>(Wv,  wqkv + 2*DM*DM,  DM,  DM);
    transpose_h_kernel<<<dim3(DM/32,  DM/32),  tb, 0, st1>>>(Wo,  woh,  DM,  DM);
    transpose_h_kernel<<<dim3(DFF/32, DM/32),  tb, 0, st1>>>(Wf1, wf1h, DM,  DFF);
    transpose_h_kernel<<<dim3(DM/32,  DFF/32), tb, 0, st1>>>(Wf2, wf2h, DFF, DM);
    transpose_h_kernel<<<dim3(DOUT/32,DM/32),  tb, 0, st1>>>(W2,  w2h,  DM,  DOUT);
    cudaEventRecord(evT1, st1);

    transpose_h_kernel<<<dim3(DM/32, DIN/32), tb>>>(W1, w1h, DIN, DM);
    pad_split_kernel<<<(BSZ*NTOK*(DIN/4) + 255)/256, 256>>>(x);
    tc_gemm(0, sh, w1h, b1, nullptr, h, nullptr, nullptr, nullptr, DM, DIN, 1);
    ln_kernel<<<BSZ*NTOK/8, 256>>>(h, ln1g, ln1b);
    cudaStreamWaitEvent(0, evT1, 0);
    tc_gemm(0, sh, wqkv, nullptr, nullptr, q, k, v, nullptr, 3*DM, DM, 0);
    cudaEventRecord(evQKV, 0);

    // lin chain on st1; lin_out weighted split (st1: 40, main: 54)
    cudaStreamWaitEvent(st1, evQKV, 0);
    cudaStreamWaitEvent(st1, evPad, 0);
    kmax_kernel<<<dim3(BSZ*3,4), dim3(32,8), 0, st1>>>();
    ctx_partial_kernel<<<dim3(BSZ*3,KSPL), 256, 0, st1>>>();
    ctx_reduce_kernel<<<(BSZ*3*DH*DH + 255)/256, 256, 0, st1>>>();
    cudaEventRecord(evCtx, st1);
    lin_out_kernel<<<dim3(BSZ*3, 40), 256, 0, st1>>>(0);
    cudaEventRecord(evLin, st1);

    cudaStreamWaitEvent(0, evPad, 0);
    local_attn_kernel<<<BSZ*QBPB, 128, LA_SMEM>>>();
    cudaStreamWaitEvent(0, evCtx, 0);
    lin_out_kernel<<<dim3(BSZ*3, 54), 256>>>(40);
    cudaStreamWaitEvent(0, evLin, 0);

    // tail
    tc_gemm(0, sh, woh, bo, h, h, nullptr, nullptr, nullptr, DM, DM, 0);
    ln_kernel<<<BSZ*NTOK/8, 256>>>(h, ln2g, ln2b);
    tc_gemm(0, sh, wf1h, bf1, nullptr, nullptr, nullptr, nullptr, s2h, DFF, DM, 2);
    tc_gemm(0, s2h, wf2h, bf2, h, nullptr, nullptr, nullptr, sh, DM, DFF, 0);
    tc_gemm(0, sh, w2h, b2, nullptr, out, nullptr, nullptr, nullptr, DOUT, DM, 0, NTOK);
}

// round 16
// speedup vs baseline: 1.4577x; 1.0264x over previous
#include <cuda_runtime.h>
#include <cuda_fp16.h>
#include <math.h>
#include <stdint.h>

#define BSZ   8
#define SEQ   4096
#define NTOK  3000
#define DIN   128
#define DM    512
#define DFF   2048
#define DOUT  64
#define DH    128
#define MTOT  (BSZ*SEQ)
#define MTPB  24
#define QBPB  47
#define KSPL  32
#define SCALE 0.08838834764831845f
#define GEMM_SMEM (3*32768)
#define LA_SMEM   52224              // 3 x [64][136] fp16 tiles

typedef __half fp16;

// ---------------- scratch ----------------
__device__ float g_h[MTOT*DM];
__device__ fp16 g_q[MTOT*DM];
__device__ fp16 g_k[MTOT*DM];
__device__ fp16 g_v[MTOT*DM];
__device__ float g_kmax[BSZ*3*DH];
__device__ float g_lsep[BSZ*3*KSPL*DH];
__device__ float g_ctxp[(size_t)BSZ*3*KSPL*DH*DH];
__device__ float g_ctx[BSZ*3*DH*DH];
__device__ float g_lnpad[DM];
__device__ float g_kpad[DM];
__device__ float g_vpad[DM];
__device__ fp16 g_sh[MTOT*DM];
__device__ fp16 g_s2h[MTOT*DFF];
__device__ fp16 g_w1h[DM*DIN];
__device__ fp16 g_wqkv[3*DM*DM];
__device__ fp16 g_woh[DM*DM];
__device__ fp16 g_wf1h[DFF*DM];
__device__ fp16 g_wf2h[DM*DFF];
__device__ fp16 g_w2h[DOUT*DM];

// ---------------- helpers ----------------
__device__ __forceinline__ uint32_t smem_u32(const void* p) {
    uint32_t a;
    asm("{ .reg .u64 t; cvta.to.shared.u64 t, %1; cvt.u32.u64 %0, t; }" : "=r"(a) : "l"(p));
    return a;
}
__device__ __forceinline__ uint32_t pack2h(float x, float y) {
    __half2 h = __floats2half2_rn(x, y);
    return *reinterpret_cast<uint32_t*>(&h);
}
__device__ __forceinline__ float fexp(float x) {
    x = fmaxf(x, -87.0f);
    float t = x * 1.4426950408889634f;
    float fn = rintf(t);
    float r = t - fn;
    float p =            1.5403530394e-4f;
    p = fmaf(p, r, 1.3333558146e-3f);
    p = fmaf(p, r, 9.6181291076e-3f);
    p = fmaf(p, r, 5.5504108665e-2f);
    p = fmaf(p, r, 2.4022650696e-1f);
    p = fmaf(p, r, 6.9314718056e-1f);
    p = fmaf(p, r, 1.0f);
    return __int_as_float(__float_as_int(p) + (((int)fn) << 23));
}
#define EXPF(x) fexp(x)

#define LDSM_X4(r0,r1,r2,r3,addr) \
    asm volatile("ldmatrix.sync.aligned.m8n8.x4.shared.b16 {%0,%1,%2,%3}, [%4];" \
        : "=r"(r0),"=r"(r1),"=r"(r2),"=r"(r3) : "r"(addr))
#define LDSM_X4T(r0,r1,r2,r3,addr) \
    asm volatile("ldmatrix.sync.aligned.m8n8.x4.trans.shared.b16 {%0,%1,%2,%3}, [%4];" \
        : "=r"(r0),"=r"(r1),"=r"(r2),"=r"(r3) : "r"(addr))
#define MMA16816(d, a0,a1,a2,a3, b0,b1) \
    asm volatile("mma.sync.aligned.m16n8k16.row.col.f32.f16.f16.f32 " \
        "{%0,%1,%2,%3},{%4,%5,%6,%7},{%8,%9},{%0,%1,%2,%3};" \
        : "+f"((d)[0]),"+f"((d)[1]),"+f"((d)[2]),"+f"((d)[3]) \
        : "r"(a0),"r"(a1),"r"(a2),"r"(a3),"r"(b0),"r"(b1))
#define CP_ASYNC16(dst, src, sz) \
    asm volatile("cp.async.cg.shared.global [%0], [%1], 16, %2;" :: "r"(dst), "l"(src), "r"(sz))
#define CP_COMMIT()  asm volatile("cp.async.commit_group;" ::: "memory")
#define CP_WAIT0()   asm volatile("cp.async.wait_group 0;" ::: "memory")
#define CP_WAIT1()   asm volatile("cp.async.wait_group 1;" ::: "memory")

// ---------------- weight transpose + fp16 ----------------
__global__ void transpose_h_kernel(const float* __restrict__ W,
                                   fp16* __restrict__ Th, int K, int N) {
    __shared__ float t[32][33];
    int bx = blockIdx.x * 32, by = blockIdx.y * 32;
    int x = bx + threadIdx.x;
    #pragma unroll
    for (int i = 0; i < 32; i += 8) {
        int y = by + threadIdx.y + i;
        if (x < N && y < K) t[threadIdx.y + i][threadIdx.x] = W[(size_t)y * N + x];
    }
    __syncthreads();
    int xk = by + threadIdx.x;
    #pragma unroll
    for (int i = 0; i < 32; i += 8) {
        int yn = bx + threadIdx.y + i;
        if (xk < K && yn < N)
            Th[(size_t)yn * K + xk] = __float2half_rn(t[threadIdx.x][threadIdx.y + i]);
    }
}

// ---------------- x (real rows only) -> g_sh fp16 ----------------
__global__ void pad_split_kernel(const float* __restrict__ x) {
    int idx = blockIdx.x*256 + threadIdx.x;
    const int total = BSZ*NTOK*(DIN/4);
    if (idx >= total) return;
    int rr = idx >> 5;
    int c4 = idx & 31;
    int b = rr / NTOK, t = rr - b*NTOK;
    float4 val = reinterpret_cast<const float4*>(x)[(size_t)rr*32 + c4];
    uint2 hv;
    hv.x = pack2h(val.x, val.y);
    hv.y = pack2h(val.z, val.w);
    *reinterpret_cast<uint2*>(g_sh + (size_t)(b*SEQ + t)*DIN + c4*4) = hv;
}

// ---------------- pad-row LN ----------------
__global__ void pad_ln_kernel(const float* __restrict__ b1, const float* __restrict__ gam,
                              const float* __restrict__ bet) {
    __shared__ float ss[16], ss2[16], stat[2];
    int t = threadIdx.x;
    float h = tanhf(b1[t]);
    float s = h, s2 = h*h;
    #pragma unroll
    for (int o=16;o;o>>=1) { s += __shfl_xor_sync(~0u,s,o); s2 += __shfl_xor_sync(~0u,s2,o); }
    if ((t & 31) == 0) { ss[t>>5] = s; ss2[t>>5] = s2; }
    __syncthreads();
    if (t == 0) {
        float S=0.f, S2=0.f;
        #pragma unroll
        for (int i=0;i<16;i++) { S += ss[i]; S2 += ss2[i]; }
        float mu = S*(1.f/512.f);
        float var = S2*(1.f/512.f) - mu*mu;
        stat[0] = mu; stat[1] = rsqrtf(var + 1e-5f);
    }
    __syncthreads();
    g_lnpad[t] = (h - stat[0])*stat[1]*gam[t] + bet[t];
}

// ---------------- pad-row k/v ----------------
__global__ void pad_kv_kernel(const float* __restrict__ Wk, const float* __restrict__ Wv) {
    int d = blockIdx.x*256 + threadIdx.x;
    if (d >= 2*DM) return;
    const float* W = (d < DM) ? Wk : Wv;
    int dd = d & (DM-1);
    float s = 0.f;
    for (int kk = 0; kk < DM; kk++) s += g_lnpad[kk] * W[(size_t)kk*DM + dd];
    if (d < DM) g_kpad[dd] = s; else g_vpad[dd] = s;
}

// ---------------- broadcast pad k/v rows (fp16) -------------------------------
__global__ void padfill_kernel() {
    int idx = blockIdx.x*256 + threadIdx.x;
    const int per = (SEQ-NTOK)*(DM/8);
    if (idx >= BSZ*per) return;
    int b = idx / per, r = idx - b*per;
    int t = NTOK + r/(DM/8), c8 = r % (DM/8);
    float4 a  = *reinterpret_cast<const float4*>(g_kpad + c8*8);
    float4 a2 = *reinterpret_cast<const float4*>(g_kpad + c8*8 + 4);
    float4 c  = *reinterpret_cast<const float4*>(g_vpad + c8*8);
    float4 c2 = *reinterpret_cast<const float4*>(g_vpad + c8*8 + 4);
    uint4 kp, vp;
    kp.x = pack2h(a.x,a.y);  kp.y = pack2h(a.z,a.w);
    kp.z = pack2h(a2.x,a2.y); kp.w = pack2h(a2.z,a2.w);
    vp.x = pack2h(c.x,c.y);  vp.y = pack2h(c.z,c.w);
    vp.z = pack2h(c2.x,c2.y); vp.w = pack2h(c2.z,c2.w);
    size_t off = (size_t)(b*SEQ + t)*DM + c8*8;
    *reinterpret_cast<uint4*>(g_k + off) = kp;
    *reinterpret_cast<uint4*>(g_v + off) = vp;
}

// ---------------- fp16 tensor-core GEMM ----------------
// Output routing: Cqh!=null -> fused QKV fp16 (cols [0,512)->Cqh etc., stride 512);
// else Ch!=null -> fp16 single; else C fp32.
__global__ __launch_bounds__(256, 2) void tc_gemm_kernel(
    const fp16* __restrict__ A, const fp16* __restrict__ B,
    const float* __restrict__ bias, const float* __restrict__ res,
    float* __restrict__ C, fp16* __restrict__ Ch,
    fp16* __restrict__ Cqh, fp16* __restrict__ Ckh, fp16* __restrict__ Cvh,
    int N, int K, int act, int omul)
{
    extern __shared__ __align__(1024) char smc[];
    uint32_t sbase = smem_u32(smc);
    int tid = threadIdx.x;
    int mtile = blockIdx.y;
    int bb = mtile / MTPB, t0 = (mtile - bb*MTPB) << 7;
    int bm = bb*SEQ + t0;
    int alim = NTOK - t0;
    int rowlim = bm + alim;
    int odelta = bb*(omul - SEQ);
    int bn = blockIdx.x << 7;
    int lane = tid & 31, w = tid >> 5;
    int wm = w & 1, wn = w >> 1;
    int grp = lane >> 2, qp = lane & 3;

    uint32_t swz = (lane >> 1) & 3;
    uint32_t a_base = (uint32_t)(wm*64 + (lane & 15))*64 + (((uint32_t)(lane >> 4) ^ swz) << 4);
    uint32_t b_base = (uint32_t)(wn*32 + ((lane >> 4) & 1)*8 + (lane & 7))*64
                    + ((((uint32_t)(lane >> 3) & 1) ^ swz) << 4);

    float acc[4][4][4];
    #pragma unroll
    for (int i=0;i<4;i++)
        #pragma unroll
        for (int j=0;j<4;j++)
            #pragma unroll
            for (int r=0;r<4;r++) acc[i][j][r] = 0.f;

    const int NC = K >> 6;

    #define STAGE_LOAD(c_, buf_) do { \
        uint32_t sb = sbase + (uint32_t)(buf_)*32768u; \
        _Pragma("unroll") \
        for (int i_ = 0; i_ < 8; i_++) { \
            const int sub_ = i_ >> 2; \
            const int arr_ = (i_ >> 1) & 1; \
            int j_ = ((i_ & 1) << 8) + tid; \
            int r_ = j_ >> 2, cc_ = j_ & 3; \
            int k0 = ((c_) << 6) + sub_*32; \
            uint32_t dst_ = sb + (uint32_t)sub_*16384u + (uint32_t)arr_*8192u \
                          + (uint32_t)r_*64u + ((uint32_t)(cc_ ^ ((r_ >> 1) & 3)) << 4); \
            const fp16* g_; int sz_ = 16; \
            if (arr_ == 0) { \
                if (r_ < alim) g_ = A + (size_t)(bm + r_)*K + k0 + cc_*8; \
                else { g_ = A; sz_ = 0; } \
            } else { \
                int rowv_ = bn + r_; \
                if (rowv_ < N) g_ = B + (size_t)rowv_*K + k0 + cc_*8; \
                else { g_ = B; sz_ = 0; } \
            } \
            CP_ASYNC16(dst_, g_, sz_); \
        } \
        CP_COMMIT(); \
    } while (0)

    STAGE_LOAD(0, 0);
    if (NC > 1) STAGE_LOAD(1, 1);

    int buf = 0, bufn = 2;
    for (int c = 0; c < NC; c++) {
        if (c + 1 < NC) CP_WAIT1(); else CP_WAIT0();
        __syncthreads();
        if (c + 2 < NC) {
            STAGE_LOAD(c + 2, bufn);
            bufn = (bufn == 2) ? 0 : bufn + 1;
        }
        uint32_t stg = sbase + (uint32_t)buf*32768u;
        buf = (buf == 2) ? 0 : buf + 1;

        #pragma unroll
        for (int sub = 0; sub < 2; sub++) {
            uint32_t sA = stg + (uint32_t)sub*16384u;
            uint32_t sB = sA + 8192u;
            #pragma unroll
            for (int ks = 0; ks < 2; ks++) {
                uint32_t kx = ks ? 32u : 0u;
                uint32_t bh[4][2], a[4][4];
                #pragma unroll
                for (int p = 0; p < 2; p++)
                    LDSM_X4(bh[2*p][0], bh[2*p][1], bh[2*p+1][0], bh[2*p+1][1],
                            sB + ((b_base + p*1024u) ^ kx));
                #pragma unroll
                for (int mt = 0; mt < 4; mt++)
                    LDSM_X4(a[mt][0], a[mt][1], a[mt][2], a[mt][3],
                            sA + ((a_base + mt*1024u) ^ kx));
                #pragma unroll
                for (int mt = 0; mt < 4; mt++)
                    #pragma unroll
                    for (int nt = 0; nt < 4; nt++)
                        MMA16816(acc[mt][nt], a[mt][0],a[mt][1],a[mt][2],a[mt][3],
                                 bh[nt][0],bh[nt][1]);
            }
        }
    }
    #undef STAGE_LOAD

    #pragma unroll
    for (int mt = 0; mt < 4; mt++) {
        #pragma unroll
        for (int nt = 0; nt < 4; nt++) {
            int c0 = bn + wn*32 + nt*8 + qp*2;
            if (c0 >= N) continue;
            int rbase = bm + wm*64 + mt*16 + grp;
            float bs0 = 0.f, bs1 = 0.f;
            if (bias) { bs0 = bias[c0]; bs1 = bias[c0 + 1]; }
            #pragma unroll
            for (int half = 0; half < 2; half++) {
                int r = rbase + half*8;
                if (r >= rowlim) continue;
                float v0 = acc[mt][nt][half*2 + 0] + bs0;
                float v1 = acc[mt][nt][half*2 + 1] + bs1;
                if (act == 1) { v0 = tanhf(v0); v1 = tanhf(v1); }
                else if (act == 2) {
                    v0 = 0.5f*v0*(1.f + erff(v0*0.7071067811865476f));
                    v1 = 0.5f*v1*(1.f + erff(v1*0.7071067811865476f));
                }
                if (res) {
                    v0 += res[(size_t)r*N + c0];
                    v1 += res[(size_t)r*N + c0 + 1];
                }
                size_t orow = (size_t)(r + odelta);
                if (Cqh) {
                    fp16* dst; int cc;
                    if (c0 < 512)       { dst = Cqh; cc = c0; }
                    else if (c0 < 1024) { dst = Ckh; cc = c0 - 512; }
                    else                { dst = Cvh; cc = c0 - 1024; }
                    *reinterpret_cast<uint32_t*>(dst + orow*512 + cc) = pack2h(v0, v1);
                } else if (Ch) {
                    *reinterpret_cast<uint32_t*>(Ch + orow*N + c0) = pack2h(v0, v1);
                } else {
                    float2 o; o.x = v0; o.y = v1;
                    *reinterpret_cast<float2*>(C + orow*N + c0) = o;
                }
            }
        }
    }
}

// ---------------- LayerNorm (real rows) -> fp16 ----------------
__global__ void ln_kernel(const float* __restrict__ in, const float* __restrict__ gam,
                          const float* __restrict__ bet) {
    int gw = (blockIdx.x*blockDim.x + threadIdx.x) >> 5;
    int lane = threadIdx.x & 31;
    if (gw >= BSZ*NTOK) return;
    int b = gw / NTOK, t = gw - b*NTOK;
    size_t row = (size_t)(b*SEQ + t);
    const float4* rp = reinterpret_cast<const float4*>(in + row*DM);
    float4 v[4];
    float s=0.f, s2=0.f;
    #pragma unroll
    for (int i=0;i<4;i++) {
        v[i] = rp[lane + 32*i];
        s  += v[i].x+v[i].y+v[i].z+v[i].w;
        s2 += v[i].x*v[i].x + v[i].y*v[i].y + v[i].z*v[i].z + v[i].w*v[i].w;
    }
    #pragma unroll
    for (int o=16;o;o>>=1) { s += __shfl_xor_sync(~0u,s,o); s2 += __shfl_xor_sync(~0u,s2,o); }
    float mu  = s*(1.f/512.f);
    float var = s2*(1.f/512.f) - mu*mu;
    float r = rsqrtf(var + 1e-5f);
    #pragma unroll
    for (int i=0;i<4;i++) {
        int c = (lane + 32*i)*4;
        float4 g4 = *reinterpret_cast<const float4*>(gam + c);
        float4 b4 = *reinterpret_cast<const float4*>(bet + c);
        uint2 hv;
        hv.x = pack2h((v[i].x-mu)*r*g4.x + b4.x, (v[i].y-mu)*r*g4.y + b4.y);
        hv.y = pack2h((v[i].z-mu)*r*g4.z + b4.z, (v[i].w-mu)*r*g4.w + b4.w);
        *reinterpret_cast<uint2*>(g_sh + row*DM + c) = hv;
    }
}

// ---------------- local attention, head 0: tensor-core FA (fp16 qkv) ---------
__global__ __launch_bounds__(128) void local_attn_kernel() {
    extern __shared__ fp16 sm16[];
    fp16* qt = sm16;            // [64][136]
    fp16* kt = sm16 + 8704;
    fp16* vt = sm16 + 17408;
    int b   = blockIdx.x / QBPB;
    int blk = blockIdx.x - b*QBPB;
    int qbase = blk*64;
    int win = qbase >> 7;
    int tid = threadIdx.x;
    int warp = tid >> 5, lane = tid & 31;
    int grp = lane >> 2, qp = lane & 3;

    // load Q tile (64 x 128 fp16) — straight uint4 copies
    #pragma unroll
    for (int i = 0; i < 8; i++) {
        int idx = i*128 + tid;
        int r = idx >> 4, c8 = idx & 15;
        *reinterpret_cast<uint4*>(qt + r*136 + c8*8) =
            *reinterpret_cast<const uint4*>(g_q + (size_t)(b*SEQ + qbase + r)*DM + c8*8);
    }

    float m0 = -1e30f, m1 = -1e30f, l0 = 0.f, l1 = 0.f;
    float o[16][4];
    #pragma unroll
    for (int nt=0; nt<16; nt++)
        #pragma unroll
        for (int r=0; r<4; r++) o[nt][r] = 0.f;

    int kbase = win*128 - 128;
    for (int ch=0; ch<6; ch++) {
        int t0k = kbase + ch*64;
        __syncthreads();
        #pragma unroll
        for (int i = 0; i < 16; i++) {
            int idx = i*128 + tid;
            int isV = idx >> 10;
            int j = idx & 1023;
            int r = j >> 4, c8 = j & 15;
            int t = t0k + r;
            const fp16* src = isV ? g_v : g_k;
            fp16* dst = isV ? vt : kt;
            uint4 val = make_uint4(0,0,0,0);
            if (t >= 0 && t < SEQ)
                val = *reinterpret_cast<const uint4*>(src + (size_t)(b*SEQ+t)*DM + c8*8);
            *reinterpret_cast<uint4*>(dst + r*136 + c8*8) = val;
        }
        __syncthreads();
        // S = Q K^T
        float s[8][4];
        #pragma unroll
        for (int nt=0; nt<8; nt++)
            #pragma unroll
            for (int r=0; r<4; r++) s[nt][r] = 0.f;
        #pragma unroll
        for (int kk = 0; kk < 8; kk++) {
            uint32_t a0,a1,a2,a3;
            LDSM_X4(a0,a1,a2,a3,
                smem_u32(qt + (warp*16 + (lane & 15))*136 + kk*16 + ((lane >> 4) & 1)*8));
            #pragma unroll
            for (int p = 0; p < 4; p++) {
                uint32_t b0,b1,b2,b3;
                LDSM_X4(b0,b1,b2,b3,
                    smem_u32(kt + (p*16 + ((lane >> 4) & 1)*8 + (lane & 7))*136
                             + kk*16 + ((lane >> 3) & 1)*8));
                MMA16816(s[2*p],   a0,a1,a2,a3, b0,b1);
                MMA16816(s[2*p+1], a0,a1,a2,a3, b2,b3);
            }
        }
        float cm0 = -1e38f, cm1 = -1e38f;
        #pragma unroll
        for (int nt=0; nt<8; nt++) {
            int tg0 = t0k + nt*8 + qp*2;
            bool v0 = (tg0 >= 0 && tg0 < SEQ);
            bool v1 = (tg0+1 >= 0 && tg0+1 < SEQ);
            s[nt][0] = v0 ? s[nt][0]*SCALE : -1e38f;
            s[nt][1] = v1 ? s[nt][1]*SCALE : -1e38f;
            s[nt][2] = v0 ? s[nt][2]*SCALE : -1e38f;
            s[nt][3] = v1 ? s[nt][3]*SCALE : -1e38f;
            cm0 = fmaxf(cm0, fmaxf(s[nt][0], s[nt][1]));
            cm1 = fmaxf(cm1, fmaxf(s[nt][2], s[nt][3]));
        }
        cm0 = fmaxf(cm0, __shfl_xor_sync(~0u, cm0, 1));
        cm0 = fmaxf(cm0, __shfl_xor_sync(~0u, cm0, 2));
        cm1 = fmaxf(cm1, __shfl_xor_sync(~0u, cm1, 1));
        cm1 = fmaxf(cm1, __shfl_xor_sync(~0u, cm1, 2));
        float mn0 = fmaxf(m0, cm0), mn1 = fmaxf(m1, cm1);
        float c0 = EXPF(m0 - mn0), c1 = EXPF(m1 - mn1);
        l0 *= c0; l1 *= c1;
        #pragma unroll
        for (int nt=0; nt<16; nt++) {
            o[nt][0]*=c0; o[nt][1]*=c0; o[nt][2]*=c1; o[nt][3]*=c1;
        }
        uint32_t pa[4][4];
        #pragma unroll
        for (int kk=0; kk<4; kk++) {
            int n0 = 2*kk, n1 = 2*kk+1;
            float p00 = EXPF(s[n0][0]-mn0), p01 = EXPF(s[n0][1]-mn0);
            float p02 = EXPF(s[n0][2]-mn1), p03 = EXPF(s[n0][3]-mn1);
            float p10 = EXPF(s[n1][0]-mn0), p11 = EXPF(s[n1][1]-mn0);
            float p12 = EXPF(s[n1][2]-mn1), p13 = EXPF(s[n1][3]-mn1);
            l0 += p00 + p01 + p10 + p11;
            l1 += p02 + p03 + p12 + p13;
            pa[kk][0] = pack2h(p00, p01);
            pa[kk][1] = pack2h(p02, p03);
            pa[kk][2] = pack2h(p10, p11);
            pa[kk][3] = pack2h(p12, p13);
        }
        #pragma unroll
        for (int kk=0; kk<4; kk++) {
            int brow = kk*16 + ((lane >> 3) & 1)*8 + (lane & 7);
            #pragma unroll
            for (int p = 0; p < 8; p++) {
                uint32_t b0,b1,b2,b3;
                LDSM_X4T(b0,b1,b2,b3,
                    smem_u32(vt + brow*136 + p*16 + ((lane >> 4) & 1)*8));
                MMA16816(o[2*p],   pa[kk][0],pa[kk][1],pa[kk][2],pa[kk][3], b0,b1);
                MMA16816(o[2*p+1], pa[kk][0],pa[kk][1],pa[kk][2],pa[kk][3], b2,b3);
            }
        }
        m0 = mn0; m1 = mn1;
    }
    l0 += __shfl_xor_sync(~0u, l0, 1); l0 += __shfl_xor_sync(~0u, l0, 2);
    l1 += __shfl_xor_sync(~0u, l1, 1); l1 += __shfl_xor_sync(~0u, l1, 2);
    float i0 = 1.f/l0, i1 = 1.f/l1;
    size_t row0 = (size_t)(b*SEQ + qbase + warp*16 + grp);
    size_t row1 = row0 + 8;
    #pragma unroll
    for (int nt=0; nt<16; nt++) {
        int col = nt*8 + qp*2;
        *reinterpret_cast<uint32_t*>(g_sh + row0*DM + col) = pack2h(o[nt][0]*i0, o[nt][1]*i0);
        *reinterpret_cast<uint32_t*>(g_sh + row1*DM + col) = pack2h(o[nt][2]*i1, o[nt][3]*i1);
    }
}

// ---------------- k column max (heads 1..3, fp16 k) ----------------
__global__ void kmax_kernel() {
    int bh = blockIdx.x;
    int b = bh/3, hh = bh%3 + 1;
    int d = blockIdx.y*32 + threadIdx.x;
    int ty = threadIdx.y;
    int col = hh*DH + d;
    float m = -1e30f;
    for (int t = ty; t < SEQ; t += 8)
        m = fmaxf(m, __half2float(g_k[(size_t)(b*SEQ+t)*DM + col]));
    __shared__ float sm[8][32];
    sm[ty][threadIdx.x] = m;
    __syncthreads();
    if (ty == 0) {
        #pragma unroll
        for (int r=1;r<8;r++) m = fmaxf(m, sm[r][threadIdx.x]);
        g_kmax[bh*DH + d] = m;
    }
}

// ---------------- ctx partial: tensor-core e@v + lse partials ----------------
__global__ __launch_bounds__(256) void ctx_partial_kernel() {
    __shared__ fp16 et[32][136];
    __shared__ fp16 vt[32][136];
    __shared__ float smax[DH];
    __shared__ float lred[8][DH];
    int bh = blockIdx.x, ks = blockIdx.y;
    int b = bh/3, hh = bh%3 + 1;
    int tid = threadIdx.x;
    if (tid < DH) smax[tid] = g_kmax[bh*DH + tid];
    int lr0 = tid >> 5, lc4 = tid & 31;
    int warp = tid >> 5, lane = tid & 31;
    int mw = warp & 3, nw = warp >> 2;
    int grp = lane >> 2, qp = lane & 3;
    int lg = lane >> 3, lr8 = lane & 7;

    float acc[2][8][4];
    #pragma unroll
    for (int i=0;i<2;i++)
        #pragma unroll
        for (int j=0;j<8;j++)
            #pragma unroll
            for (int r=0;r<4;r++) acc[i][j][r] = 0.f;
    float4 lacc = make_float4(0.f,0.f,0.f,0.f);
    __syncthreads();

    const int TPB = SEQ / KSPL;
    for (int c = 0; c < TPB/32; c++) {
        #pragma unroll
        for (int i=0;i<4;i++) {
            int r = lr0 + 8*i;
            int t = ks*TPB + c*32 + r;
            size_t off = (size_t)(b*SEQ+t)*DM + hh*DH + lc4*4;
            uint2 kp = *reinterpret_cast<const uint2*>(g_k + off);
            uint2 vp = *reinterpret_cast<const uint2*>(g_v + off);
            __half2 ka = *reinterpret_cast<__half2*>(&kp.x);
            __half2 kb = *reinterpret_cast<__half2*>(&kp.y);
            int d0 = lc4*4;
            float e0 = EXPF(__low2float(ka)  - smax[d0+0]);
            float e1 = EXPF(__high2float(ka) - smax[d0+1]);
            float e2 = EXPF(__low2float(kb)  - smax[d0+2]);
            float e3 = EXPF(__high2float(kb) - smax[d0+3]);
            lacc.x += e0; lacc.y += e1; lacc.z += e2; lacc.w += e3;
            uint2 ep; ep.x = pack2h(e0, e1); ep.y = pack2h(e2, e3);
            *reinterpret_cast<uint2*>(&et[r][d0]) = ep;
            *reinterpret_cast<uint2*>(&vt[r][d0]) = vp;
        }
        __syncthreads();
        #pragma unroll
        for (int kk = 0; kk < 2; kk++) {
            uint32_t a[2][4];
            int arow = kk*16 + (lg & 2)*4 + lr8;
            #pragma unroll
            for (int mt = 0; mt < 2; mt++) {
                int acol = mw*32 + mt*16 + (lg & 1)*8;
                LDSM_X4T(a[mt][0], a[mt][1], a[mt][2], a[mt][3],
                         smem_u32(&et[arow][acol]));
            }
            uint32_t bf[8][2];
            int brow = kk*16 + (lg & 1)*8 + lr8;
            #pragma unroll
            for (int p = 0; p < 4; p++) {
                int bcol = nw*64 + p*16 + (lg >> 1)*8;
                uint32_t t0r, t1r, t2r, t3r;
                LDSM_X4T(t0r, t1r, t2r, t3r, smem_u32(&vt[brow][bcol]));
                bf[p*2][0] = t0r; bf[p*2][1] = t1r;
                bf[p*2+1][0] = t2r; bf[p*2+1][1] = t3r;
            }
            #pragma unroll
            for (int mt = 0; mt < 2; mt++)
                #pragma unroll
                for (int nt = 0; nt < 8; nt++)
                    MMA16816(acc[mt][nt], a[mt][0],a[mt][1],a[mt][2],a[mt][3],
                             bf[nt][0], bf[nt][1]);
        }
        __syncthreads();
    }
    *reinterpret_cast<float4*>(&lred[lr0][lc4*4]) = lacc;
    __syncthreads();
    if (tid < DH) {
        float s = 0.f;
        #pragma unroll
        for (int j=0;j<8;j++) s += lred[j][tid];
        g_lsep[(bh*KSPL + ks)*DH + tid] = s;
    }
    float* op = g_ctxp + ((size_t)bh*KSPL + ks)*DH*DH;
    #pragma unroll
    for (int mt = 0; mt < 2; mt++)
        #pragma unroll
        for (int nt = 0; nt < 8; nt++) {
            int drow = mw*32 + mt*16 + grp;
            int e0 = nw*64 + nt*8 + qp*2;
            float2 o;
            o.x = acc[mt][nt][0]; o.y = acc[mt][nt][1];
            *reinterpret_cast<float2*>(op + (size_t)drow*DH + e0) = o;
            o.x = acc[mt][nt][2]; o.y = acc[mt][nt][3];
            *reinterpret_cast<float2*>(op + (size_t)(drow+8)*DH + e0) = o;
        }
}

// ---------------- ctx reduce + normalize by lse ----------------
__global__ void ctx_reduce_kernel() {
    int idx = blockIdx.x*256 + threadIdx.x;
    if (idx >= BSZ*3*DH*DH) return;
    int bh = idx / (DH*DH);
    int de = idx - bh*DH*DH;
    int d = de >> 7;
    float s = 0.f, ls = 0.f;
    #pragma unroll
    for (int ks=0;ks<KSPL;ks++) {
        s  += g_ctxp[((size_t)bh*KSPL+ks)*DH*DH + de];
        ls += g_lsep[(bh*KSPL+ks)*DH + d];
    }
    g_ctx[idx] = s / ls;
}

// ---------------- linear-attn output (fp16 q) -> fp16 ----------------
__global__ __launch_bounds__(256) void lin_out_kernel(int ybase) {
    __shared__ float sctx[64][DH];
    int bh = blockIdx.x;
    int b = bh/3, hh = bh%3 + 1;
    int warp = threadIdx.x >> 5, lane = threadIdx.x & 31;
    const float* ctxp = g_ctx + (size_t)bh*DH*DH;
    float pr[4][4], o[4][4];
    int tbase = (ybase + blockIdx.y)*32 + warp*4;
    #pragma unroll
    for (int tt=0;tt<4;tt++) {
        int t = tbase + tt;
        uint2 qp2 = *reinterpret_cast<const uint2*>(
            g_q + (size_t)(b*SEQ+t)*DM + hh*DH + lane*4);
        __half2 qa = *reinterpret_cast<__half2*>(&qp2.x);
        __half2 qb = *reinterpret_cast<__half2*>(&qp2.y);
        float q0 = __low2float(qa), q1 = __high2float(qa);
        float q2 = __low2float(qb), q3 = __high2float(qb);
        float mx = fmaxf(fmaxf(q0,q1),fmaxf(q2,q3));
        #pragma unroll
        for (int s=16;s;s>>=1) mx = fmaxf(mx, __shfl_xor_sync(~0u,mx,s));
        float e0=EXPF(q0-mx), e1=EXPF(q1-mx), e2=EXPF(q2-mx), e3=EXPF(q3-mx);
        float sm = e0+e1+e2+e3;
        #pragma unroll
        for (int s=16;s;s>>=1) sm += __shfl_xor_sync(~0u,sm,s);
        float inv = SCALE/sm;
        pr[tt][0]=e0*inv; pr[tt][1]=e1*inv; pr[tt][2]=e2*inv; pr[tt][3]=e3*inv;
        o[tt][0]=0.f; o[tt][1]=0.f; o[tt][2]=0.f; o[tt][3]=0.f;
    }
    for (int ph=0; ph<2; ph++) {
        __syncthreads();
        #pragma unroll
        for (int i=0;i<8;i++) {
            int idx = i*256 + threadIdx.x;
            int r = idx >> 5, c4 = idx & 31;
            *reinterpret_cast<float4*>(&sctx[r][c4*4]) =
                *reinterpret_cast<const float4*>(ctxp + (size_t)(ph*64+r)*DH + c4*4);
        }
        __syncthreads();
        #pragma unroll
        for (int dl=0; dl<16; dl++) {
            int src = ph*16 + dl;
            #pragma unroll
            for (int tt=0;tt<4;tt++) {
                float b0 = __shfl_sync(~0u, pr[tt][0], src);
                float b1 = __shfl_sync(~0u, pr[tt][1], src);
                float b2 = __shfl_sync(~0u, pr[tt][2], src);
                float b3 = __shfl_sync(~0u, pr[tt][3], src);
                float4 c0 = *reinterpret_cast<const float4*>(&sctx[dl*4+0][lane*4]);
                float4 c1 = *reinterpret_cast<const float4*>(&sctx[dl*4+1][lane*4]);
                float4 c2 = *reinterpret_cast<const float4*>(&sctx[dl*4+2][lane*4]);
                float4 c3 = *reinterpret_cast<const float4*>(&sctx[dl*4+3][lane*4]);
                o[tt][0] += b0*c0.x + b1*c1.x + b2*c2.x + b3*c3.x;
                o[tt][1] += b0*c0.y + b1*c1.y + b2*c2.y + b3*c3.y;
                o[tt][2] += b0*c0.z + b1*c1.z + b2*c2.z + b3*c3.z;
                o[tt][3] += b0*c0.w + b1*c1.w + b2*c2.w + b3*c3.w;
            }
        }
    }
    #pragma unroll
    for (int tt=0;tt<4;tt++) {
        int t = tbase + tt;
        uint2 hv;
        hv.x = pack2h(o[tt][0], o[tt][1]);
        hv.y = pack2h(o[tt][2], o[tt][3]);
        *reinterpret_cast<uint2*>(g_sh + (size_t)(b*SEQ+t)*DM + hh*DH + lane*4) = hv;
    }
}

// ---------------- host ----------------
static inline void tc_gemm(cudaStream_t st, const fp16* A, const fp16* B,
                           const float* bias, const float* res,
                           float* C, fp16* Ch, fp16* Cqh, fp16* Ckh, fp16* Cvh,
                           int N, int K, int act, int omul = SEQ) {
    dim3 grid((N + 127) / 128, BSZ*MTPB);
    tc_gemm_kernel<<<grid, 256, GEMM_SMEM, st>>>(A, B, bias, res, C, Ch,
                                                 Cqh, Ckh, Cvh, N, K, act, omul);
}

extern "C" void kernel_launch(void* const* d_in, const int* in_sizes, int n_in,
                              void* d_out, int out_size) {
    const float* x    = (const float*)d_in[0];
    const float* W1   = (const float*)d_in[1];
    const float* b1   = (const float*)d_in[2];
    const float* ln1g = (const float*)d_in[3];
    const float* ln1b = (const float*)d_in[4];
    const float* Wq   = (const float*)d_in[5];
    const float* Wk   = (const float*)d_in[6];
    const float* Wv   = (const float*)d_in[7];
    const float* Wo   = (const float*)d_in[8];
    const float* bo   = (const float*)d_in[9];
    const float* ln2g = (const float*)d_in[10];
    const float* ln2b = (const float*)d_in[11];
    const float* Wf1  = (const float*)d_in[12];
    const float* bf1  = (const float*)d_in[13];
    const float* Wf2  = (const float*)d_in[14];
    const float* bf2  = (const float*)d_in[15];
    const float* W2   = (const float*)d_in[16];
    const float* b2   = (const float*)d_in[17];
    float* out = (float*)d_out;

    static int init_done = 0;
    static cudaStream_t st1, st2;
    static cudaEvent_t evStart, evT1, evQKV, evPad, evCtx, evLin;
    if (!init_done) {
        cudaFuncSetAttribute(tc_gemm_kernel, cudaFuncAttributeMaxDynamicSharedMemorySize, GEMM_SMEM);
        cudaFuncSetAttribute(local_attn_kernel, cudaFuncAttributeMaxDynamicSharedMemorySize, LA_SMEM);
        cudaStreamCreateWithFlags(&st1, cudaStreamNonBlocking);
        cudaStreamCreateWithFlags(&st2, cudaStreamNonBlocking);
        cudaEventCreateWithFlags(&evStart, cudaEventDisableTiming);
        cudaEventCreateWithFlags(&evT1,    cudaEventDisableTiming);
        cudaEventCreateWithFlags(&evQKV,   cudaEventDisableTiming);
        cudaEventCreateWithFlags(&evPad,   cudaEventDisableTiming);
        cudaEventCreateWithFlags(&evCtx,   cudaEventDisableTiming);
        cudaEventCreateWithFlags(&evLin,   cudaEventDisableTiming);
        init_done = 1;
    }

    float *h;
    fp16 *q,*k,*v;
    fp16 *sh,*s2h;
    fp16 *w1h,*wqkv,*woh,*wf1h,*wf2h,*w2h;
    cudaGetSymbolAddress((void**)&h,    g_h);
    cudaGetSymbolAddress((void**)&q,    g_q);
    cudaGetSymbolAddress((void**)&k,    g_k);
    cudaGetSymbolAddress((void**)&v,    g_v);
    cudaGetSymbolAddress((void**)&sh,   g_sh);
    cudaGetSymbolAddress((void**)&s2h,  g_s2h);
    cudaGetSymbolAddress((void**)&w1h,  g_w1h);
    cudaGetSymbolAddress((void**)&wqkv, g_wqkv);
    cudaGetSymbolAddress((void**)&woh,  g_woh);
    cudaGetSymbolAddress((void**)&wf1h, g_wf1h);
    cudaGetSymbolAddress((void**)&wf2h, g_wf2h);
    cudaGetSymbolAddress((void**)&w2h,  g_w2h);

    dim3 tb(32, 8);

    cudaEventRecord(evStart, 0);
    cudaStreamWaitEvent(st2, evStart, 0);
    pad_ln_kernel<<<1, 512, 0, st2>>>(b1, ln1g, ln1b);
    pad_kv_kernel<<<4, 256, 0, st2>>>(Wk, Wv);
    padfill_kernel<<<(BSZ*(SEQ-NTOK)*(DM/8) + 255)/256, 256, 0, st2>>>();
    cudaEventRecord(evPad, st2);

    cudaStreamWaitEvent(st1, evStart, 0);
    transpose_h_kernel<<<dim3(DM/32,  DM/32),  tb, 0, st1>>>(Wq,  wqkv,            DM,  DM);
    transpose_h_kernel<<<dim3(DM/32,  DM/32),  tb, 0, st1>>>(Wk,  wqkv + DM*DM,    DM,  DM);
    transpose_h_kernel<<<dim3(DM/32,  DM/32),  tb, 0, st1>>>(Wv,  wqkv + 2*DM*DM,  DM,  DM);
    transpose_h_kernel<<<dim3(DM/32,  DM/32),  tb, 0, st1>>>(Wo,  woh,  DM,  DM);
    transpose_h_kernel<<<dim3(DFF/32, DM/32),  tb, 0, st1>>>(Wf1, wf1h, DM,  DFF);
    transpose_h_kernel<<<dim3(DM/32,  DFF/32), tb, 0, st1>>>(Wf2, wf2h, DFF, DM);
    transpose_h_kernel<<<dim3(DOUT/32,DM/32),  tb, 0, st1>>>(W2,  w2h,  DM,  DOUT);
    cudaEventRecord(evT1, st1);

    transpose_h_kernel<<<dim3(DM/32, DIN/32), tb>>>(W1, w1h, DIN, DM);
    pad_split_kernel<<<(BSZ*NTOK*(DIN/4) + 255)/256, 256>>>(x);
    tc_gemm(0, sh, w1h, b1, nullptr, h, nullptr, nullptr, nullptr, nullptr, DM, DIN, 1);
    ln_kernel<<<BSZ*NTOK/8, 256>>>(h, ln1g, ln1b);
    cudaStreamWaitEvent(0, evT1, 0);
    tc_gemm(0, sh, wqkv, nullptr, nullptr, nullptr, nullptr, q, k, v, 3*DM, DM, 0);
    cudaEventRecord(evQKV, 0);

    // lin chain on st1; lin_out weighted split (st1: 40, main: 54)
    cudaStreamWaitEvent(st1, evQKV, 0);
    cudaStreamWaitEvent(st1, evPad, 0);
    kmax_kernel<<<dim3(BSZ*3,4), dim3(32,8), 0, st1>>>();
    ctx_partial_kernel<<<dim3(BSZ*3,KSPL), 256, 0, st1>>>();
    ctx_reduce_kernel<<<(BSZ*3*DH*DH + 255)/256, 256, 0, st1>>>();
    cudaEventRecord(evCtx, st1);
    lin_out_kernel<<<dim3(BSZ*3, 40), 256, 0, st1>>>(0);
    cudaEventRecord(evLin, st1);

    cudaStreamWaitEvent(0, evPad, 0);
    local_attn_kernel<<<BSZ*QBPB, 128, LA_SMEM>>>();
    cudaStreamWaitEvent(0, evCtx, 0);
    lin_out_kernel<<<dim3(BSZ*3, 54), 256>>>(40);
    cudaStreamWaitEvent(0, evLin, 0);

    // tail
    tc_gemm(0, sh, woh, bo, h, h, nullptr, nullptr, nullptr, nullptr, DM, DM, 0);
    ln_kernel<<<BSZ*NTOK/8, 256>>>(h, ln2g, ln2b);
    tc_gemm(0, sh, wf1h, bf1, nullptr, nullptr, s2h, nullptr, nullptr, nullptr, DFF, DM, 2);
    tc_gemm(0, s2h, wf2h, bf2, h, nullptr, sh, nullptr, nullptr, nullptr, DM, DFF, 0);
    tc_gemm(0, sh, w2h, b2, nullptr, out, nullptr, nullptr, nullptr, nullptr, DOUT, DM, 0, NTOK);
}

// round 17
// speedup vs baseline: 1.5278x; 1.0481x over previous
#include <cuda_runtime.h>
#include <cuda_fp16.h>
#include <math.h>
#include <stdint.h>

#define BSZ   8
#define SEQ   4096
#define NTOK  3000
#define DIN   128
#define DM    512
#define DFF   2048
#define DOUT  64
#define DH    128
#define MTOT  (BSZ*SEQ)
#define MTPB  24
#define QBPB  47
#define KSPL  32
#define SCALE 0.08838834764831845f
#define GEMM_SMEM (3*32768)
#define LA_SMEM   52224              // 3 x [64][136] fp16 tiles

typedef __half fp16;

// ---------------- scratch ----------------
__device__ float g_h[MTOT*DM];
__device__ fp16 g_hh[MTOT*DM];
__device__ fp16 g_q[MTOT*DM];
__device__ fp16 g_k[MTOT*DM];
__device__ fp16 g_v[MTOT*DM];
__device__ float g_kmax[BSZ*3*DH];
__device__ float g_lsep[BSZ*3*KSPL*DH];
__device__ float g_ctxp[(size_t)BSZ*3*KSPL*DH*DH];
__device__ float g_ctx[BSZ*3*DH*DH];
__device__ float g_lnpad[DM];
__device__ float g_kpad[DM];
__device__ float g_vpad[DM];
__device__ float g_b2p[DOUT];
__device__ fp16 g_sh[MTOT*DM];
__device__ fp16 g_s2h[MTOT*DFF];
__device__ fp16 g_w1h[DM*DIN];
__device__ fp16 g_wqkv[3*DM*DM];
__device__ fp16 g_woh[DM*DM];
__device__ fp16 g_wf1h[DFF*DM];
__device__ fp16 g_w2h[DOUT*DM];
__device__ fp16 g_w2ph[DOUT*DFF];    // (Wf2@W2)^T fp16: [n][k]

// ---------------- helpers ----------------
__device__ __forceinline__ uint32_t smem_u32(const void* p) {
    uint32_t a;
    asm("{ .reg .u64 t; cvta.to.shared.u64 t, %1; cvt.u32.u64 %0, t; }" : "=r"(a) : "l"(p));
    return a;
}
__device__ __forceinline__ uint32_t pack2h(float x, float y) {
    __half2 h = __floats2half2_rn(x, y);
    return *reinterpret_cast<uint32_t*>(&h);
}
__device__ __forceinline__ float fexp(float x) {
    x = fmaxf(x, -87.0f);
    float t = x * 1.4426950408889634f;
    float fn = rintf(t);
    float r = t - fn;
    float p =            1.5403530394e-4f;
    p = fmaf(p, r, 1.3333558146e-3f);
    p = fmaf(p, r, 9.6181291076e-3f);
    p = fmaf(p, r, 5.5504108665e-2f);
    p = fmaf(p, r, 2.4022650696e-1f);
    p = fmaf(p, r, 6.9314718056e-1f);
    p = fmaf(p, r, 1.0f);
    return __int_as_float(__float_as_int(p) + (((int)fn) << 23));
}
#define EXPF(x) fexp(x)

#define LDSM_X4(r0,r1,r2,r3,addr) \
    asm volatile("ldmatrix.sync.aligned.m8n8.x4.shared.b16 {%0,%1,%2,%3}, [%4];" \
        : "=r"(r0),"=r"(r1),"=r"(r2),"=r"(r3) : "r"(addr))
#define LDSM_X4T(r0,r1,r2,r3,addr) \
    asm volatile("ldmatrix.sync.aligned.m8n8.x4.trans.shared.b16 {%0,%1,%2,%3}, [%4];" \
        : "=r"(r0),"=r"(r1),"=r"(r2),"=r"(r3) : "r"(addr))
#define MMA16816(d, a0,a1,a2,a3, b0,b1) \
    asm volatile("mma.sync.aligned.m16n8k16.row.col.f32.f16.f16.f32 " \
        "{%0,%1,%2,%3},{%4,%5,%6,%7},{%8,%9},{%0,%1,%2,%3};" \
        : "+f"((d)[0]),"+f"((d)[1]),"+f"((d)[2]),"+f"((d)[3]) \
        : "r"(a0),"r"(a1),"r"(a2),"r"(a3),"r"(b0),"r"(b1))
#define CP_ASYNC16(dst, src, sz) \
    asm volatile("cp.async.cg.shared.global [%0], [%1], 16, %2;" :: "r"(dst), "l"(src), "r"(sz))
#define CP_COMMIT()  asm volatile("cp.async.commit_group;" ::: "memory")
#define CP_WAIT0()   asm volatile("cp.async.wait_group 0;" ::: "memory")
#define CP_WAIT1()   asm volatile("cp.async.wait_group 1;" ::: "memory")

// ---------------- weight transpose + fp16 ----------------
__global__ void transpose_h_kernel(const float* __restrict__ W,
                                   fp16* __restrict__ Th, int K, int N) {
    __shared__ float t[32][33];
    int bx = blockIdx.x * 32, by = blockIdx.y * 32;
    int x = bx + threadIdx.x;
    #pragma unroll
    for (int i = 0; i < 32; i += 8) {
        int y = by + threadIdx.y + i;
        if (x < N && y < K) t[threadIdx.y + i][threadIdx.x] = W[(size_t)y * N + x];
    }
    __syncthreads();
    int xk = by + threadIdx.x;
    #pragma unroll
    for (int i = 0; i < 32; i += 8) {
        int yn = bx + threadIdx.y + i;
        if (xk < K && yn < N)
            Th[(size_t)yn * K + xk] = __float2half_rn(t[threadIdx.x][threadIdx.y + i]);
    }
}

// ---------------- W2p = (Wf2 @ W2)^T -> fp16 [DOUT][DFF] ----------------
__global__ void w2p_kernel(const float* __restrict__ Wf2, const float* __restrict__ W2) {
    int idx = blockIdx.x*256 + threadIdx.x;
    if (idx >= DOUT*DFF) return;
    int n = idx & (DOUT-1);
    int k = idx >> 6;
    float s = 0.f;
    const float* wr = Wf2 + (size_t)k*DM;
    for (int i = 0; i < DM; i++)
        s = fmaf(wr[i], W2[(size_t)i*DOUT + n], s);
    g_w2ph[(size_t)n*DFF + k] = __float2half_rn(s);
}

// ---------------- b2p = b2 + bf2 @ W2 ----------------
__global__ void b2p_kernel(const float* __restrict__ bf2, const float* __restrict__ W2,
                           const float* __restrict__ b2) {
    int n = threadIdx.x;
    if (n >= DOUT) return;
    float s = b2[n];
    for (int i = 0; i < DM; i++)
        s = fmaf(bf2[i], W2[(size_t)i*DOUT + n], s);
    g_b2p[n] = s;
}

// ---------------- x (real rows only) -> g_sh fp16 ----------------
__global__ void pad_split_kernel(const float* __restrict__ x) {
    int idx = blockIdx.x*256 + threadIdx.x;
    const int total = BSZ*NTOK*(DIN/4);
    if (idx >= total) return;
    int rr = idx >> 5;
    int c4 = idx & 31;
    int b = rr / NTOK, t = rr - b*NTOK;
    float4 val = reinterpret_cast<const float4*>(x)[(size_t)rr*32 + c4];
    uint2 hv;
    hv.x = pack2h(val.x, val.y);
    hv.y = pack2h(val.z, val.w);
    *reinterpret_cast<uint2*>(g_sh + (size_t)(b*SEQ + t)*DIN + c4*4) = hv;
}

// ---------------- pad-row LN ----------------
__global__ void pad_ln_kernel(const float* __restrict__ b1, const float* __restrict__ gam,
                              const float* __restrict__ bet) {
    __shared__ float ss[16], ss2[16], stat[2];
    int t = threadIdx.x;
    float h = tanhf(b1[t]);
    float s = h, s2 = h*h;
    #pragma unroll
    for (int o=16;o;o>>=1) { s += __shfl_xor_sync(~0u,s,o); s2 += __shfl_xor_sync(~0u,s2,o); }
    if ((t & 31) == 0) { ss[t>>5] = s; ss2[t>>5] = s2; }
    __syncthreads();
    if (t == 0) {
        float S=0.f, S2=0.f;
        #pragma unroll
        for (int i=0;i<16;i++) { S += ss[i]; S2 += ss2[i]; }
        float mu = S*(1.f/512.f);
        float var = S2*(1.f/512.f) - mu*mu;
        stat[0] = mu; stat[1] = rsqrtf(var + 1e-5f);
    }
    __syncthreads();
    g_lnpad[t] = (h - stat[0])*stat[1]*gam[t] + bet[t];
}

// ---------------- pad-row k/v ----------------
__global__ void pad_kv_kernel(const float* __restrict__ Wk, const float* __restrict__ Wv) {
    int d = blockIdx.x*256 + threadIdx.x;
    if (d >= 2*DM) return;
    const float* W = (d < DM) ? Wk : Wv;
    int dd = d & (DM-1);
    float s = 0.f;
    for (int kk = 0; kk < DM; kk++) s += g_lnpad[kk] * W[(size_t)kk*DM + dd];
    if (d < DM) g_kpad[dd] = s; else g_vpad[dd] = s;
}

// ---------------- broadcast pad k/v rows (fp16) -------------------------------
__global__ void padfill_kernel() {
    int idx = blockIdx.x*256 + threadIdx.x;
    const int per = (SEQ-NTOK)*(DM/8);
    if (idx >= BSZ*per) return;
    int b = idx / per, r = idx - b*per;
    int t = NTOK + r/(DM/8), c8 = r % (DM/8);
    float4 a  = *reinterpret_cast<const float4*>(g_kpad + c8*8);
    float4 a2 = *reinterpret_cast<const float4*>(g_kpad + c8*8 + 4);
    float4 c  = *reinterpret_cast<const float4*>(g_vpad + c8*8);
    float4 c2 = *reinterpret_cast<const float4*>(g_vpad + c8*8 + 4);
    uint4 kp, vp;
    kp.x = pack2h(a.x,a.y);  kp.y = pack2h(a.z,a.w);
    kp.z = pack2h(a2.x,a2.y); kp.w = pack2h(a2.z,a2.w);
    vp.x = pack2h(c.x,c.y);  vp.y = pack2h(c.z,c.w);
    vp.z = pack2h(c2.x,c2.y); vp.w = pack2h(c2.z,c2.w);
    size_t off = (size_t)(b*SEQ + t)*DM + c8*8;
    *reinterpret_cast<uint4*>(g_k + off) = kp;
    *reinterpret_cast<uint4*>(g_v + off) = vp;
}

// ---------------- fp16 tensor-core GEMM ----------------
// Routing: Cqh!=null -> fused QKV fp16; else store fp32 to C (if C) and/or
// fp16 to Ch (if Ch). Residual res is read in OUTPUT row space (orow).
__global__ __launch_bounds__(256, 2) void tc_gemm_kernel(
    const fp16* __restrict__ A, const fp16* __restrict__ B,
    const float* __restrict__ bias, const float* __restrict__ res,
    float* __restrict__ C, fp16* __restrict__ Ch,
    fp16* __restrict__ Cqh, fp16* __restrict__ Ckh, fp16* __restrict__ Cvh,
    int N, int K, int act, int omul)
{
    extern __shared__ __align__(1024) char smc[];
    uint32_t sbase = smem_u32(smc);
    int tid = threadIdx.x;
    int mtile = blockIdx.y;
    int bb = mtile / MTPB, t0 = (mtile - bb*MTPB) << 7;
    int bm = bb*SEQ + t0;
    int alim = NTOK - t0;
    int rowlim = bm + alim;
    int odelta = bb*(omul - SEQ);
    int bn = blockIdx.x << 7;
    int lane = tid & 31, w = tid >> 5;
    int wm = w & 1, wn = w >> 1;
    int grp = lane >> 2, qp = lane & 3;

    uint32_t swz = (lane >> 1) & 3;
    uint32_t a_base = (uint32_t)(wm*64 + (lane & 15))*64 + (((uint32_t)(lane >> 4) ^ swz) << 4);
    uint32_t b_base = (uint32_t)(wn*32 + ((lane >> 4) & 1)*8 + (lane & 7))*64
                    + ((((uint32_t)(lane >> 3) & 1) ^ swz) << 4);

    float acc[4][4][4];
    #pragma unroll
    for (int i=0;i<4;i++)
        #pragma unroll
        for (int j=0;j<4;j++)
            #pragma unroll
            for (int r=0;r<4;r++) acc[i][j][r] = 0.f;

    const int NC = K >> 6;

    #define STAGE_LOAD(c_, buf_) do { \
        uint32_t sb = sbase + (uint32_t)(buf_)*32768u; \
        _Pragma("unroll") \
        for (int i_ = 0; i_ < 8; i_++) { \
            const int sub_ = i_ >> 2; \
            const int arr_ = (i_ >> 1) & 1; \
            int j_ = ((i_ & 1) << 8) + tid; \
            int r_ = j_ >> 2, cc_ = j_ & 3; \
            int k0 = ((c_) << 6) + sub_*32; \
            uint32_t dst_ = sb + (uint32_t)sub_*16384u + (uint32_t)arr_*8192u \
                          + (uint32_t)r_*64u + ((uint32_t)(cc_ ^ ((r_ >> 1) & 3)) << 4); \
            const fp16* g_; int sz_ = 16; \
            if (arr_ == 0) { \
                if (r_ < alim) g_ = A + (size_t)(bm + r_)*K + k0 + cc_*8; \
                else { g_ = A; sz_ = 0; } \
            } else { \
                int rowv_ = bn + r_; \
                if (rowv_ < N) g_ = B + (size_t)rowv_*K + k0 + cc_*8; \
                else { g_ = B; sz_ = 0; } \
            } \
            CP_ASYNC16(dst_, g_, sz_); \
        } \
        CP_COMMIT(); \
    } while (0)

    STAGE_LOAD(0, 0);
    if (NC > 1) STAGE_LOAD(1, 1);

    int buf = 0, bufn = 2;
    for (int c = 0; c < NC; c++) {
        if (c + 1 < NC) CP_WAIT1(); else CP_WAIT0();
        __syncthreads();
        if (c + 2 < NC) {
            STAGE_LOAD(c + 2, bufn);
            bufn = (bufn == 2) ? 0 : bufn + 1;
        }
        uint32_t stg = sbase + (uint32_t)buf*32768u;
        buf = (buf == 2) ? 0 : buf + 1;

        #pragma unroll
        for (int sub = 0; sub < 2; sub++) {
            uint32_t sA = stg + (uint32_t)sub*16384u;
            uint32_t sB = sA + 8192u;
            #pragma unroll
            for (int ks = 0; ks < 2; ks++) {
                uint32_t kx = ks ? 32u : 0u;
                uint32_t bh[4][2], a[4][4];
                #pragma unroll
                for (int p = 0; p < 2; p++)
                    LDSM_X4(bh[2*p][0], bh[2*p][1], bh[2*p+1][0], bh[2*p+1][1],
                            sB + ((b_base + p*1024u) ^ kx));
                #pragma unroll
                for (int mt = 0; mt < 4; mt++)
                    LDSM_X4(a[mt][0], a[mt][1], a[mt][2], a[mt][3],
                            sA + ((a_base + mt*1024u) ^ kx));
                #pragma unroll
                for (int mt = 0; mt < 4; mt++)
                    #pragma unroll
                    for (int nt = 0; nt < 4; nt++)
                        MMA16816(acc[mt][nt], a[mt][0],a[mt][1],a[mt][2],a[mt][3],
                                 bh[nt][0],bh[nt][1]);
            }
        }
    }
    #undef STAGE_LOAD

    #pragma unroll
    for (int mt = 0; mt < 4; mt++) {
        #pragma unroll
        for (int nt = 0; nt < 4; nt++) {
            int c0 = bn + wn*32 + nt*8 + qp*2;
            if (c0 >= N) continue;
            int rbase = bm + wm*64 + mt*16 + grp;
            float bs0 = 0.f, bs1 = 0.f;
            if (bias) { bs0 = bias[c0]; bs1 = bias[c0 + 1]; }
            #pragma unroll
            for (int half = 0; half < 2; half++) {
                int r = rbase + half*8;
                if (r >= rowlim) continue;
                float v0 = acc[mt][nt][half*2 + 0] + bs0;
                float v1 = acc[mt][nt][half*2 + 1] + bs1;
                if (act == 1) { v0 = tanhf(v0); v1 = tanhf(v1); }
                else if (act == 2) {
                    v0 = 0.5f*v0*(1.f + erff(v0*0.7071067811865476f));
                    v1 = 0.5f*v1*(1.f + erff(v1*0.7071067811865476f));
                }
                size_t orow = (size_t)(r + odelta);
                if (res) {
                    v0 += res[orow*N + c0];
                    v1 += res[orow*N + c0 + 1];
                }
                if (Cqh) {
                    fp16* dst; int cc;
                    if (c0 < 512)       { dst = Cqh; cc = c0; }
                    else if (c0 < 1024) { dst = Ckh; cc = c0 - 512; }
                    else                { dst = Cvh; cc = c0 - 1024; }
                    *reinterpret_cast<uint32_t*>(dst + orow*512 + cc) = pack2h(v0, v1);
                } else {
                    if (C) {
                        float2 o; o.x = v0; o.y = v1;
                        *reinterpret_cast<float2*>(C + orow*N + c0) = o;
                    }
                    if (Ch) {
                        *reinterpret_cast<uint32_t*>(Ch + orow*N + c0) = pack2h(v0, v1);
                    }
                }
            }
        }
    }
}

// ---------------- LayerNorm (real rows) -> fp16 ----------------
__global__ void ln_kernel(const float* __restrict__ in, const float* __restrict__ gam,
                          const float* __restrict__ bet) {
    int gw = (blockIdx.x*blockDim.x + threadIdx.x) >> 5;
    int lane = threadIdx.x & 31;
    if (gw >= BSZ*NTOK) return;
    int b = gw / NTOK, t = gw - b*NTOK;
    size_t row = (size_t)(b*SEQ + t);
    const float4* rp = reinterpret_cast<const float4*>(in + row*DM);
    float4 v[4];
    float s=0.f, s2=0.f;
    #pragma unroll
    for (int i=0;i<4;i++) {
        v[i] = rp[lane + 32*i];
        s  += v[i].x+v[i].y+v[i].z+v[i].w;
        s2 += v[i].x*v[i].x + v[i].y*v[i].y + v[i].z*v[i].z + v[i].w*v[i].w;
    }
    #pragma unroll
    for (int o=16;o;o>>=1) { s += __shfl_xor_sync(~0u,s,o); s2 += __shfl_xor_sync(~0u,s2,o); }
    float mu  = s*(1.f/512.f);
    float var = s2*(1.f/512.f) - mu*mu;
    float r = rsqrtf(var + 1e-5f);
    #pragma unroll
    for (int i=0;i<4;i++) {
        int c = (lane + 32*i)*4;
        float4 g4 = *reinterpret_cast<const float4*>(gam + c);
        float4 b4 = *reinterpret_cast<const float4*>(bet + c);
        uint2 hv;
        hv.x = pack2h((v[i].x-mu)*r*g4.x + b4.x, (v[i].y-mu)*r*g4.y + b4.y);
        hv.y = pack2h((v[i].z-mu)*r*g4.z + b4.z, (v[i].w-mu)*r*g4.w + b4.w);
        *reinterpret_cast<uint2*>(g_sh + row*DM + c) = hv;
    }
}

// ---------------- local attention, head 0: tensor-core FA (fp16 qkv) ---------
__global__ __launch_bounds__(128) void local_attn_kernel() {
    extern __shared__ fp16 sm16[];
    fp16* qt = sm16;            // [64][136]
    fp16* kt = sm16 + 8704;
    fp16* vt = sm16 + 17408;
    int b   = blockIdx.x / QBPB;
    int blk = blockIdx.x - b*QBPB;
    int qbase = blk*64;
    int win = qbase >> 7;
    int tid = threadIdx.x;
    int warp = tid >> 5, lane = tid & 31;
    int grp = lane >> 2, qp = lane & 3;

    #pragma unroll
    for (int i = 0; i < 8; i++) {
        int idx = i*128 + tid;
        int r = idx >> 4, c8 = idx & 15;
        *reinterpret_cast<uint4*>(qt + r*136 + c8*8) =
            *reinterpret_cast<const uint4*>(g_q + (size_t)(b*SEQ + qbase + r)*DM + c8*8);
    }

    float m0 = -1e30f, m1 = -1e30f, l0 = 0.f, l1 = 0.f;
    float o[16][4];
    #pragma unroll
    for (int nt=0; nt<16; nt++)
        #pragma unroll
        for (int r=0; r<4; r++) o[nt][r] = 0.f;

    int kbase = win*128 - 128;
    for (int ch=0; ch<6; ch++) {
        int t0k = kbase + ch*64;
        __syncthreads();
        #pragma unroll
        for (int i = 0; i < 16; i++) {
            int idx = i*128 + tid;
            int isV = idx >> 10;
            int j = idx & 1023;
            int r = j >> 4, c8 = j & 15;
            int t = t0k + r;
            const fp16* src = isV ? g_v : g_k;
            fp16* dst = isV ? vt : kt;
            uint4 val = make_uint4(0,0,0,0);
            if (t >= 0 && t < SEQ)
                val = *reinterpret_cast<const uint4*>(src + (size_t)(b*SEQ+t)*DM + c8*8);
            *reinterpret_cast<uint4*>(dst + r*136 + c8*8) = val;
        }
        __syncthreads();
        float s[8][4];
        #pragma unroll
        for (int nt=0; nt<8; nt++)
            #pragma unroll
            for (int r=0; r<4; r++) s[nt][r] = 0.f;
        #pragma unroll
        for (int kk = 0; kk < 8; kk++) {
            uint32_t a0,a1,a2,a3;
            LDSM_X4(a0,a1,a2,a3,
                smem_u32(qt + (warp*16 + (lane & 15))*136 + kk*16 + ((lane >> 4) & 1)*8));
            #pragma unroll
            for (int p = 0; p < 4; p++) {
                uint32_t b0,b1,b2,b3;
                LDSM_X4(b0,b1,b2,b3,
                    smem_u32(kt + (p*16 + ((lane >> 4) & 1)*8 + (lane & 7))*136
                             + kk*16 + ((lane >> 3) & 1)*8));
                MMA16816(s[2*p],   a0,a1,a2,a3, b0,b1);
                MMA16816(s[2*p+1], a0,a1,a2,a3, b2,b3);
            }
        }
        float cm0 = -1e38f, cm1 = -1e38f;
        #pragma unroll
        for (int nt=0; nt<8; nt++) {
            int tg0 = t0k + nt*8 + qp*2;
            bool v0 = (tg0 >= 0 && tg0 < SEQ);
            bool v1 = (tg0+1 >= 0 && tg0+1 < SEQ);
            s[nt][0] = v0 ? s[nt][0]*SCALE : -1e38f;
            s[nt][1] = v1 ? s[nt][1]*SCALE : -1e38f;
            s[nt][2] = v0 ? s[nt][2]*SCALE : -1e38f;
            s[nt][3] = v1 ? s[nt][3]*SCALE : -1e38f;
            cm0 = fmaxf(cm0, fmaxf(s[nt][0], s[nt][1]));
            cm1 = fmaxf(cm1, fmaxf(s[nt][2], s[nt][3]));
        }
        cm0 = fmaxf(cm0, __shfl_xor_sync(~0u, cm0, 1));
        cm0 = fmaxf(cm0, __shfl_xor_sync(~0u, cm0, 2));
        cm1 = fmaxf(cm1, __shfl_xor_sync(~0u, cm1, 1));
        cm1 = fmaxf(cm1, __shfl_xor_sync(~0u, cm1, 2));
        float mn0 = fmaxf(m0, cm0), mn1 = fmaxf(m1, cm1);
        float c0 = EXPF(m0 - mn0), c1 = EXPF(m1 - mn1);
        l0 *= c0; l1 *= c1;
        #pragma unroll
        for (int nt=0; nt<16; nt++) {
            o[nt][0]*=c0; o[nt][1]*=c0; o[nt][2]*=c1; o[nt][3]*=c1;
        }
        uint32_t pa[4][4];
        #pragma unroll
        for (int kk=0; kk<4; kk++) {
            int n0 = 2*kk, n1 = 2*kk+1;
            float p00 = EXPF(s[n0][0]-mn0), p01 = EXPF(s[n0][1]-mn0);
            float p02 = EXPF(s[n0][2]-mn1), p03 = EXPF(s[n0][3]-mn1);
            float p10 = EXPF(s[n1][0]-mn0), p11 = EXPF(s[n1][1]-mn0);
            float p12 = EXPF(s[n1][2]-mn1), p13 = EXPF(s[n1][3]-mn1);
            l0 += p00 + p01 + p10 + p11;
            l1 += p02 + p03 + p12 + p13;
            pa[kk][0] = pack2h(p00, p01);
            pa[kk][1] = pack2h(p02, p03);
            pa[kk][2] = pack2h(p10, p11);
            pa[kk][3] = pack2h(p12, p13);
        }
        #pragma unroll
        for (int kk=0; kk<4; kk++) {
            int brow = kk*16 + ((lane >> 3) & 1)*8 + (lane & 7);
            #pragma unroll
            for (int p = 0; p < 8; p++) {
                uint32_t b0,b1,b2,b3;
                LDSM_X4T(b0,b1,b2,b3,
                    smem_u32(vt + brow*136 + p*16 + ((lane >> 4) & 1)*8));
                MMA16816(o[2*p],   pa[kk][0],pa[kk][1],pa[kk][2],pa[kk][3], b0,b1);
                MMA16816(o[2*p+1], pa[kk][0],pa[kk][1],pa[kk][2],pa[kk][3], b2,b3);
            }
        }
        m0 = mn0; m1 = mn1;
    }
    l0 += __shfl_xor_sync(~0u, l0, 1); l0 += __shfl_xor_sync(~0u, l0, 2);
    l1 += __shfl_xor_sync(~0u, l1, 1); l1 += __shfl_xor_sync(~0u, l1, 2);
    float i0 = 1.f/l0, i1 = 1.f/l1;
    size_t row0 = (size_t)(b*SEQ + qbase + warp*16 + grp);
    size_t row1 = row0 + 8;
    #pragma unroll
    for (int nt=0; nt<16; nt++) {
        int col = nt*8 + qp*2;
        *reinterpret_cast<uint32_t*>(g_sh + row0*DM + col) = pack2h(o[nt][0]*i0, o[nt][1]*i0);
        *reinterpret_cast<uint32_t*>(g_sh + row1*DM + col) = pack2h(o[nt][2]*i1, o[nt][3]*i1);
    }
}

// ---------------- k column max (heads 1..3, fp16 k) ----------------
__global__ void kmax_kernel() {
    int bh = blockIdx.x;
    int b = bh/3, hh = bh%3 + 1;
    int d = blockIdx.y*32 + threadIdx.x;
    int ty = threadIdx.y;
    int col = hh*DH + d;
    float m = -1e30f;
    for (int t = ty; t < SEQ; t += 8)
        m = fmaxf(m, __half2float(g_k[(size_t)(b*SEQ+t)*DM + col]));
    __shared__ float sm[8][32];
    sm[ty][threadIdx.x] = m;
    __syncthreads();
    if (ty == 0) {
        #pragma unroll
        for (int r=1;r<8;r++) m = fmaxf(m, sm[r][threadIdx.x]);
        g_kmax[bh*DH + d] = m;
    }
}

// ---------------- ctx partial: tensor-core e@v + lse partials ----------------
__global__ __launch_bounds__(256) void ctx_partial_kernel() {
    __shared__ fp16 et[32][136];
    __shared__ fp16 vt[32][136];
    __shared__ float smax[DH];
    __shared__ float lred[8][DH];
    int bh = blockIdx.x, ks = blockIdx.y;
    int b = bh/3, hh = bh%3 + 1;
    int tid = threadIdx.x;
    if (tid < DH) smax[tid] = g_kmax[bh*DH + tid];
    int lr0 = tid >> 5, lc4 = tid & 31;
    int warp = tid >> 5, lane = tid & 31;
    int mw = warp & 3, nw = warp >> 2;
    int grp = lane >> 2, qp = lane & 3;
    int lg = lane >> 3, lr8 = lane & 7;

    float acc[2][8][4];
    #pragma unroll
    for (int i=0;i<2;i++)
        #pragma unroll
        for (int j=0;j<8;j++)
            #pragma unroll
            for (int r=0;r<4;r++) acc[i][j][r] = 0.f;
    float4 lacc = make_float4(0.f,0.f,0.f,0.f);
    __syncthreads();

    const int TPB = SEQ / KSPL;
    for (int c = 0; c < TPB/32; c++) {
        #pragma unroll
        for (int i=0;i<4;i++) {
            int r = lr0 + 8*i;
            int t = ks*TPB + c*32 + r;
            size_t off = (size_t)(b*SEQ+t)*DM + hh*DH + lc4*4;
            uint2 kp = *reinterpret_cast<const uint2*>(g_k + off);
            uint2 vp = *reinterpret_cast<const uint2*>(g_v + off);
            __half2 ka = *reinterpret_cast<__half2*>(&kp.x);
            __half2 kb = *reinterpret_cast<__half2*>(&kp.y);
            int d0 = lc4*4;
            float e0 = EXPF(__low2float(ka)  - smax[d0+0]);
            float e1 = EXPF(__high2float(ka) - smax[d0+1]);
            float e2 = EXPF(__low2float(kb)  - smax[d0+2]);
            float e3 = EXPF(__high2float(kb) - smax[d0+3]);
            lacc.x += e0; lacc.y += e1; lacc.z += e2; lacc.w += e3;
            uint2 ep; ep.x = pack2h(e0, e1); ep.y = pack2h(e2, e3);
            *reinterpret_cast<uint2*>(&et[r][d0]) = ep;
            *reinterpret_cast<uint2*>(&vt[r][d0]) = vp;
        }
        __syncthreads();
        #pragma unroll
        for (int kk = 0; kk < 2; kk++) {
            uint32_t a[2][4];
            int arow = kk*16 + (lg & 2)*4 + lr8;
            #pragma unroll
            for (int mt = 0; mt < 2; mt++) {
                int acol = mw*32 + mt*16 + (lg & 1)*8;
                LDSM_X4T(a[mt][0], a[mt][1], a[mt][2], a[mt][3],
                         smem_u32(&et[arow][acol]));
            }
            uint32_t bf[8][2];
            int brow = kk*16 + (lg & 1)*8 + lr8;
            #pragma unroll
            for (int p = 0; p < 4; p++) {
                int bcol = nw*64 + p*16 + (lg >> 1)*8;
                uint32_t t0r, t1r, t2r, t3r;
                LDSM_X4T(t0r, t1r, t2r, t3r, smem_u32(&vt[brow][bcol]));
                bf[p*2][0] = t0r; bf[p*2][1] = t1r;
                bf[p*2+1][0] = t2r; bf[p*2+1][1] = t3r;
            }
            #pragma unroll
            for (int mt = 0; mt < 2; mt++)
                #pragma unroll
                for (int nt = 0; nt < 8; nt++)
                    MMA16816(acc[mt][nt], a[mt][0],a[mt][1],a[mt][2],a[mt][3],
                             bf[nt][0], bf[nt][1]);
        }
        __syncthreads();
    }
    *reinterpret_cast<float4*>(&lred[lr0][lc4*4]) = lacc;
    __syncthreads();
    if (tid < DH) {
        float s = 0.f;
        #pragma unroll
        for (int j=0;j<8;j++) s += lred[j][tid];
        g_lsep[(bh*KSPL + ks)*DH + tid] = s;
    }
    float* op = g_ctxp + ((size_t)bh*KSPL + ks)*DH*DH;
    #pragma unroll
    for (int mt = 0; mt < 2; mt++)
        #pragma unroll
        for (int nt = 0; nt < 8; nt++) {
            int drow = mw*32 + mt*16 + grp;
            int e0 = nw*64 + nt*8 + qp*2;
            float2 o;
            o.x = acc[mt][nt][0]; o.y = acc[mt][nt][1];
            *reinterpret_cast<float2*>(op + (size_t)drow*DH + e0) = o;
            o.x = acc[mt][nt][2]; o.y = acc[mt][nt][3];
            *reinterpret_cast<float2*>(op + (size_t)(drow+8)*DH + e0) = o;
        }
}

// ---------------- ctx reduce + normalize by lse ----------------
__global__ void ctx_reduce_kernel() {
    int idx = blockIdx.x*256 + threadIdx.x;
    if (idx >= BSZ*3*DH*DH) return;
    int bh = idx / (DH*DH);
    int de = idx - bh*DH*DH;
    int d = de >> 7;
    float s = 0.f, ls = 0.f;
    #pragma unroll
    for (int ks=0;ks<KSPL;ks++) {
        s  += g_ctxp[((size_t)bh*KSPL+ks)*DH*DH + de];
        ls += g_lsep[(bh*KSPL+ks)*DH + d];
    }
    g_ctx[idx] = s / ls;
}

// ---------------- linear-attn output (fp16 q) -> fp16 ----------------
__global__ __launch_bounds__(256) void lin_out_kernel(int ybase) {
    __shared__ float sctx[64][DH];
    int bh = blockIdx.x;
    int b = bh/3, hh = bh%3 + 1;
    int warp = threadIdx.x >> 5, lane = threadIdx.x & 31;
    const float* ctxp = g_ctx + (size_t)bh*DH*DH;
    float pr[4][4], o[4][4];
    int tbase = (ybase + blockIdx.y)*32 + warp*4;
    #pragma unroll
    for (int tt=0;tt<4;tt++) {
        int t = tbase + tt;
        uint2 qp2 = *reinterpret_cast<const uint2*>(
            g_q + (size_t)(b*SEQ+t)*DM + hh*DH + lane*4);
        __half2 qa = *reinterpret_cast<__half2*>(&qp2.x);
        __half2 qb = *reinterpret_cast<__half2*>(&qp2.y);
        float q0 = __low2float(qa), q1 = __high2float(qa);
        float q2 = __low2float(qb), q3 = __high2float(qb);
        float mx = fmaxf(fmaxf(q0,q1),fmaxf(q2,q3));
        #pragma unroll
        for (int s=16;s;s>>=1) mx = fmaxf(mx, __shfl_xor_sync(~0u,mx,s));
        float e0=EXPF(q0-mx), e1=EXPF(q1-mx), e2=EXPF(q2-mx), e3=EXPF(q3-mx);
        float sm = e0+e1+e2+e3;
        #pragma unroll
        for (int s=16;s;s>>=1) sm += __shfl_xor_sync(~0u,sm,s);
        float inv = SCALE/sm;
        pr[tt][0]=e0*inv; pr[tt][1]=e1*inv; pr[tt][2]=e2*inv; pr[tt][3]=e3*inv;
        o[tt][0]=0.f; o[tt][1]=0.f; o[tt][2]=0.f; o[tt][3]=0.f;
    }
    for (int ph=0; ph<2; ph++) {
        __syncthreads();
        #pragma unroll
        for (int i=0;i<8;i++) {
            int idx = i*256 + threadIdx.x;
            int r = idx >> 5, c4 = idx & 31;
            *reinterpret_cast<float4*>(&sctx[r][c4*4]) =
                *reinterpret_cast<const float4*>(ctxp + (size_t)(ph*64+r)*DH + c4*4);
        }
        __syncthreads();
        #pragma unroll
        for (int dl=0; dl<16; dl++) {
            int src = ph*16 + dl;
            #pragma unroll
            for (int tt=0;tt<4;tt++) {
                float b0 = __shfl_sync(~0u, pr[tt][0], src);
                float b1 = __shfl_sync(~0u, pr[tt][1], src);
                float b2 = __shfl_sync(~0u, pr[tt][2], src);
                float b3 = __shfl_sync(~0u, pr[tt][3], src);
                float4 c0 = *reinterpret_cast<const float4*>(&sctx[dl*4+0][lane*4]);
                float4 c1 = *reinterpret_cast<const float4*>(&sctx[dl*4+1][lane*4]);
                float4 c2 = *reinterpret_cast<const float4*>(&sctx[dl*4+2][lane*4]);
                float4 c3 = *reinterpret_cast<const float4*>(&sctx[dl*4+3][lane*4]);
                o[tt][0] += b0*c0.x + b1*c1.x + b2*c2.x + b3*c3.x;
                o[tt][1] += b0*c0.y + b1*c1.y + b2*c2.y + b3*c3.y;
                o[tt][2] += b0*c0.z + b1*c1.z + b2*c2.z + b3*c3.z;
                o[tt][3] += b0*c0.w + b1*c1.w + b2*c2.w + b3*c3.w;
            }
        }
    }
    #pragma unroll
    for (int tt=0;tt<4;tt++) {
        int t = tbase + tt;
        uint2 hv;
        hv.x = pack2h(o[tt][0], o[tt][1]);
        hv.y = pack2h(o[tt][2], o[tt][3]);
        *reinterpret_cast<uint2*>(g_sh + (size_t)(b*SEQ+t)*DM + hh*DH + lane*4) = hv;
    }
}

// ---------------- host ----------------
static inline void tc_gemm(cudaStream_t st, const fp16* A, const fp16* B,
                           const float* bias, const float* res,
                           float* C, fp16* Ch, fp16* Cqh, fp16* Ckh, fp16* Cvh,
                           int N, int K, int act, int omul = SEQ) {
    dim3 grid((N + 127) / 128, BSZ*MTPB);
    tc_gemm_kernel<<<grid, 256, GEMM_SMEM, st>>>(A, B, bias, res, C, Ch,
                                                 Cqh, Ckh, Cvh, N, K, act, omul);
}

extern "C" void kernel_launch(void* const* d_in, const int* in_sizes, int n_in,
                              void* d_out, int out_size) {
    const float* x    = (const float*)d_in[0];
    const float* W1   = (const float*)d_in[1];
    const float* b1   = (const float*)d_in[2];
    const float* ln1g = (const float*)d_in[3];
    const float* ln1b = (const float*)d_in[4];
    const float* Wq   = (const float*)d_in[5];
    const float* Wk   = (const float*)d_in[6];
    const float* Wv   = (const float*)d_in[7];
    const float* Wo   = (const float*)d_in[8];
    const float* bo   = (const float*)d_in[9];
    const float* ln2g = (const float*)d_in[10];
    const float* ln2b = (const float*)d_in[11];
    const float* Wf1  = (const float*)d_in[12];
    const float* bf1  = (const float*)d_in[13];
    const float* Wf2  = (const float*)d_in[14];
    const float* bf2  = (const float*)d_in[15];
    const float* W2   = (const float*)d_in[16];
    const float* b2   = (const float*)d_in[17];
    float* out = (float*)d_out;

    static int init_done = 0;
    static cudaStream_t st1, st2;
    static cudaEvent_t evStart, evT1, evQKV, evPad, evCtx, evLin;
    if (!init_done) {
        cudaFuncSetAttribute(tc_gemm_kernel, cudaFuncAttributeMaxDynamicSharedMemorySize, GEMM_SMEM);
        cudaFuncSetAttribute(local_attn_kernel, cudaFuncAttributeMaxDynamicSharedMemorySize, LA_SMEM);
        cudaStreamCreateWithFlags(&st1, cudaStreamNonBlocking);
        cudaStreamCreateWithFlags(&st2, cudaStreamNonBlocking);
        cudaEventCreateWithFlags(&evStart, cudaEventDisableTiming);
        cudaEventCreateWithFlags(&evT1,    cudaEventDisableTiming);
        cudaEventCreateWithFlags(&evQKV,   cudaEventDisableTiming);
        cudaEventCreateWithFlags(&evPad,   cudaEventDisableTiming);
        cudaEventCreateWithFlags(&evCtx,   cudaEventDisableTiming);
        cudaEventCreateWithFlags(&evLin,   cudaEventDisableTiming);
        init_done = 1;
    }

    float *h, *b2p;
    fp16 *hh,*q,*k,*v;
    fp16 *sh,*s2h;
    fp16 *w1h,*wqkv,*woh,*wf1h,*w2h,*w2ph;
    cudaGetSymbolAddress((void**)&h,    g_h);
    cudaGetSymbolAddress((void**)&hh,   g_hh);
    cudaGetSymbolAddress((void**)&b2p,  g_b2p);
    cudaGetSymbolAddress((void**)&q,    g_q);
    cudaGetSymbolAddress((void**)&k,    g_k);
    cudaGetSymbolAddress((void**)&v,    g_v);
    cudaGetSymbolAddress((void**)&sh,   g_sh);
    cudaGetSymbolAddress((void**)&s2h,  g_s2h);
    cudaGetSymbolAddress((void**)&w1h,  g_w1h);
    cudaGetSymbolAddress((void**)&wqkv, g_wqkv);
    cudaGetSymbolAddress((void**)&woh,  g_woh);
    cudaGetSymbolAddress((void**)&wf1h, g_wf1h);
    cudaGetSymbolAddress((void**)&w2h,  g_w2h);
    cudaGetSymbolAddress((void**)&w2ph, g_w2ph);

    dim3 tb(32, 8);

    cudaEventRecord(evStart, 0);
    cudaStreamWaitEvent(st2, evStart, 0);
    pad_ln_kernel<<<1, 512, 0, st2>>>(b1, ln1g, ln1b);
    pad_kv_kernel<<<4, 256, 0, st2>>>(Wk, Wv);
    padfill_kernel<<<(BSZ*(SEQ-NTOK)*(DM/8) + 255)/256, 256, 0, st2>>>();
    cudaEventRecord(evPad, st2);

    cudaStreamWaitEvent(st1, evStart, 0);
    transpose_h_kernel<<<dim3(DM/32,  DM/32),  tb, 0, st1>>>(Wq,  wqkv,            DM,  DM);
    transpose_h_kernel<<<dim3(DM/32,  DM/32),  tb, 0, st1>>>(Wk,  wqkv + DM*DM,    DM,  DM);
    transpose_h_kernel<<<dim3(DM/32,  DM/32),  tb, 0, st1>>>(Wv,  wqkv + 2*DM*DM,  DM,  DM);
    transpose_h_kernel<<<dim3(DM/32,  DM/32),  tb, 0, st1>>>(Wo,  woh,  DM,  DM);
    transpose_h_kernel<<<dim3(DFF/32, DM/32),  tb, 0, st1>>>(Wf1, wf1h, DM,  DFF);
    transpose_h_kernel<<<dim3(DOUT/32,DM/32),  tb, 0, st1>>>(W2,  w2h,  DM,  DOUT);
    w2p_kernel<<<(DOUT*DFF + 255)/256, 256, 0, st1>>>(Wf2, W2);
    b2p_kernel<<<1, 64, 0, st1>>>(bf2, W2, b2);
    cudaEventRecord(evT1, st1);

    transpose_h_kernel<<<dim3(DM/32, DIN/32), tb>>>(W1, w1h, DIN, DM);
    pad_split_kernel<<<(BSZ*NTOK*(DIN/4) + 255)/256, 256>>>(x);
    tc_gemm(0, sh, w1h, b1, nullptr, h, nullptr, nullptr, nullptr, nullptr, DM, DIN, 1);
    ln_kernel<<<BSZ*NTOK/8, 256>>>(h, ln1g, ln1b);
    cudaStreamWaitEvent(0, evT1, 0);
    tc_gemm(0, sh, wqkv, nullptr, nullptr, nullptr, nullptr, q, k, v, 3*DM, DM, 0);
    cudaEventRecord(evQKV, 0);

    // lin chain on st1; lin_out weighted split (st1: 40, main: 54)
    cudaStreamWaitEvent(st1, evQKV, 0);
    cudaStreamWaitEvent(st1, evPad, 0);
    kmax_kernel<<<dim3(BSZ*3,4), dim3(32,8), 0, st1>>>();
    ctx_partial_kernel<<<dim3(BSZ*3,KSPL), 256, 0, st1>>>();
    ctx_reduce_kernel<<<(BSZ*3*DH*DH + 255)/256, 256, 0, st1>>>();
    cudaEventRecord(evCtx, st1);
    lin_out_kernel<<<dim3(BSZ*3, 40), 256, 0, st1>>>(0);
    cudaEventRecord(evLin, st1);

    cudaStreamWaitEvent(0, evPad, 0);
    local_attn_kernel<<<BSZ*QBPB, 128, LA_SMEM>>>();
    cudaStreamWaitEvent(0, evCtx, 0);
    lin_out_kernel<<<dim3(BSZ*3, 54), 256>>>(40);
    cudaStreamWaitEvent(0, evLin, 0);

    // tail: Wo (dual-store fp32 h + fp16 hh), ln2, FF1,
    //       out = hh@W2 + b2p, then out += gelu(ff)@(Wf2@W2)
    tc_gemm(0, sh, woh, bo, h, h, hh, nullptr, nullptr, nullptr, DM, DM, 0);
    ln_kernel<<<BSZ*NTOK/8, 256>>>(h, ln2g, ln2b);
    tc_gemm(0, sh, wf1h, bf1, nullptr, nullptr, s2h, nullptr, nullptr, nullptr, DFF, DM, 2);
    tc_gemm(0, hh, w2h, b2p, nullptr, out, nullptr, nullptr, nullptr, nullptr, DOUT, DM, 0, NTOK);
    tc_gemm(0, s2h, w2ph, nullptr, out, out, nullptr, nullptr, nullptr, nullptr, DOUT, DFF, 0, NTOK);
}